// round 1
// baseline (speedup 1.0000x reference)
#include <cuda_runtime.h>
#include <cuda_bf16.h>
#include <math.h>

#define BB 2
#define CC 8
#define FF 256
#define WW 512
#define HH 8
#define HD 32
#define EE 4
#define BC (BB*CC)
#define NTOT ((size_t)BB*CC*FF*WW)

// ---------------- scratch (static device globals; no allocation) ----------------
__device__ float g_h[BB*CC*FF*WW];
__device__ float g_z[BB*CC*FF*WW];
__device__ float g_q[BB*CC*FF*WW];
__device__ float g_k[BB*CC*FF*WW];
__device__ float g_v[BB*CC*FF*WW];
__device__ float g_t[BB*CC*FF*WW];
__device__ float g_u[BB*CC*EE*WW];

// ---------------- simple copy ----------------
__global__ void copy_kernel(float* __restrict__ dst, const float* __restrict__ src, size_t n) {
    size_t i = (size_t)blockIdx.x * blockDim.x + threadIdx.x;
    size_t stride = (size_t)gridDim.x * blockDim.x;
    for (; i < n; i += stride) dst[i] = src[i];
}

// ---------------- LayerNorm over features (axis f), per (b,c,w) column ----------------
__global__ void ln_kernel(const float* __restrict__ src, const float* __restrict__ g,
                          const float* __restrict__ bet, float* __restrict__ dst) {
    int bc = blockIdx.y;
    int w = blockIdx.x * blockDim.x + threadIdx.x;
    int c = bc & (CC - 1);
    const float* p = src + (size_t)bc * FF * WW + w;
    float s = 0.f, s2 = 0.f;
#pragma unroll 8
    for (int f = 0; f < FF; f++) {
        float v = p[(size_t)f * WW];
        s += v; s2 += v * v;
    }
    float m = s * (1.0f / FF);
    float var = s2 * (1.0f / FF) - m * m;
    float rs = rsqrtf(var + 1e-5f);
    const float* gc = g + c * FF;
    const float* bb = bet + c * FF;
    float* q = dst + (size_t)bc * FF * WW + w;
#pragma unroll 8
    for (int f = 0; f < FF; f++) {
        q[(size_t)f * WW] = (p[(size_t)f * WW] - m) * rs * gc[f] + bb[f];
    }
}

// ---------------- batched SGEMM: Out[bc][g][w] (+=) sum_f Wm[c][g][f] * X[bc][f][w] ----------------
// grid: (W/128, F/128, BC), block 256. BM=BN=128, BK=8, 8x8 microtile.
template<int ACC>
__global__ __launch_bounds__(256) void gemm128(const float* __restrict__ X,
                                               const float* __restrict__ Wm,
                                               float* __restrict__ Out) {
    __shared__ float As[8 * 132];
    __shared__ float Bs[8 * 132];
    int bc = blockIdx.z;
    int c = bc & (CC - 1);
    const float* A  = Wm + (size_t)c * FF * FF;
    const float* Bx = X  + (size_t)bc * FF * WW;
    float*       Cp = Out + (size_t)bc * FF * WW;
    int m0 = blockIdx.y * 128, n0 = blockIdx.x * 128;
    int t = threadIdx.x;
    int tx = t & 15, ty = t >> 4;
    int am = t >> 1;            // 0..127 (row of A tile)
    int ak = (t & 1) * 4;       // 0 or 4
    int bk = t >> 5;            // 0..7   (row of B tile)
    int bn = (t & 31) * 4;      // 0..124

    float acc[8][8];
#pragma unroll
    for (int i = 0; i < 8; i++)
#pragma unroll
        for (int j = 0; j < 8; j++) acc[i][j] = 0.f;

    for (int k0 = 0; k0 < FF; k0 += 8) {
        float4 av = *(const float4*)(A + (size_t)(m0 + am) * FF + k0 + ak);
        float4 bv = *(const float4*)(Bx + (size_t)(k0 + bk) * WW + n0 + bn);
        As[(ak + 0) * 132 + am] = av.x;
        As[(ak + 1) * 132 + am] = av.y;
        As[(ak + 2) * 132 + am] = av.z;
        As[(ak + 3) * 132 + am] = av.w;
        *(float4*)(Bs + bk * 132 + bn) = bv;
        __syncthreads();
#pragma unroll
        for (int k = 0; k < 8; k++) {
            float4 a0 = *(const float4*)(As + k * 132 + ty * 8);
            float4 a1 = *(const float4*)(As + k * 132 + ty * 8 + 4);
            float4 b0 = *(const float4*)(Bs + k * 132 + tx * 4);
            float4 b1 = *(const float4*)(Bs + k * 132 + 64 + tx * 4);
            float a[8] = {a0.x, a0.y, a0.z, a0.w, a1.x, a1.y, a1.z, a1.w};
            float b[8] = {b0.x, b0.y, b0.z, b0.w, b1.x, b1.y, b1.z, b1.w};
#pragma unroll
            for (int i = 0; i < 8; i++)
#pragma unroll
                for (int j = 0; j < 8; j++)
                    acc[i][j] = fmaf(a[i], b[j], acc[i][j]);
        }
        __syncthreads();
    }
#pragma unroll
    for (int i = 0; i < 8; i++) {
        float* crow = Cp + (size_t)(m0 + ty * 8 + i) * WW + n0;
        if (ACC) {
            float4 c0 = *(float4*)(crow + tx * 4);
            float4 c1 = *(float4*)(crow + 64 + tx * 4);
            c0.x += acc[i][0]; c0.y += acc[i][1]; c0.z += acc[i][2]; c0.w += acc[i][3];
            c1.x += acc[i][4]; c1.y += acc[i][5]; c1.z += acc[i][6]; c1.w += acc[i][7];
            *(float4*)(crow + tx * 4) = c0;
            *(float4*)(crow + 64 + tx * 4) = c1;
        } else {
            float4 c0 = make_float4(acc[i][0], acc[i][1], acc[i][2], acc[i][3]);
            float4 c1 = make_float4(acc[i][4], acc[i][5], acc[i][6], acc[i][7]);
            *(float4*)(crow + tx * 4) = c0;
            *(float4*)(crow + 64 + tx * 4) = c1;
        }
    }
}

// ---------------- 1x3 channel-mix conv (+bias) fused with interleaved RoPE ----------------
// grid: (W/128, F/2, BC), block 128. Each thread computes rows f0=2p and f0+1 at one w.
__global__ void convrope_kernel(const float* __restrict__ src, const float* __restrict__ Kw,
                                const float* __restrict__ bias, float* __restrict__ dst,
                                int do_rope) {
    int w = blockIdx.x * 128 + threadIdx.x;
    int f0 = blockIdx.y * 2;
    int bc = blockIdx.z;
    int b = bc >> 3;
    int co = bc & 7;
    const float* Kc = Kw + co * CC * 3;
    float y0 = bias[co], y1 = y0;
    const float* base = src + ((size_t)b * CC * FF + f0) * WW + w;
#pragma unroll
    for (int ci = 0; ci < CC; ci++) {
        const float* xp = base + (size_t)ci * FF * WW;
        float k0 = Kc[ci * 3 + 0], k1 = Kc[ci * 3 + 1], k2 = Kc[ci * 3 + 2];
        float xl = (w > 0) ? xp[-1] : 0.f;
        float xc = xp[0];
        float xr = (w < WW - 1) ? xp[1] : 0.f;
        y0 += k0 * xl + k1 * xc + k2 * xr;
        xl = (w > 0) ? xp[WW - 1] : 0.f;
        xc = xp[WW];
        xr = (w < WW - 1) ? xp[WW + 1] : 0.f;
        y1 += k0 * xl + k1 * xc + k2 * xr;
    }
    float* op = dst + ((size_t)bc * FF + f0) * WW + w;
    if (do_rope) {
        int d = f0 & (HD - 1);                       // even d within head
        float theta = expf(-(float)d * (9.210340371976184f / (float)HD)); // 10000^{-d/HD}
        float ang = (float)w * theta;
        float sn, cs;
        sincosf(ang, &sn, &cs);
        op[0]  = y0 * cs - y1 * sn;
        op[WW] = y1 * cs + y0 * sn;
    } else {
        op[0] = y0;
        op[WW] = y1;
    }
}

// ---------------- attention: one CTA per (b,c,h), K/V in smem, online softmax ----------------
#define ATTN_SMEM (2 * WW * 36 * 4)
__global__ __launch_bounds__(512) void attn_kernel(const float* __restrict__ Q,
                                                   const float* __restrict__ Kb,
                                                   const float* __restrict__ Vb,
                                                   float* __restrict__ Ob) {
    extern __shared__ float sm[];
    float* sk = sm;
    float* sv = sm + WW * 36;
    int bch = blockIdx.x;
    int h = bch & (HH - 1);
    int bc = bch >> 3;
    size_t base = ((size_t)bc * FF + h * HD) * WW;
    const float* gq = Q + base;
    const float* gk = Kb + base;
    const float* gv = Vb + base;
    int n = threadIdx.x;
#pragma unroll
    for (int d = 0; d < HD; d++) {
        sk[n * 36 + d] = gk[(size_t)d * WW + n];
        sv[n * 36 + d] = gv[(size_t)d * WW + n];
    }
    float4 q4[8];
#pragma unroll
    for (int j = 0; j < 8; j++) {
        q4[j].x = gq[(size_t)(4 * j + 0) * WW + n] * 0.0625f;  // 1/sqrt(F)=1/16 folded into q
        q4[j].y = gq[(size_t)(4 * j + 1) * WW + n] * 0.0625f;
        q4[j].z = gq[(size_t)(4 * j + 2) * WW + n] * 0.0625f;
        q4[j].w = gq[(size_t)(4 * j + 3) * WW + n] * 0.0625f;
    }
    __syncthreads();

    float mrun = -INFINITY, lrun = 0.f;
    float4 a4[8];
#pragma unroll
    for (int j = 0; j < 8; j++) a4[j] = make_float4(0.f, 0.f, 0.f, 0.f);

    for (int m = 0; m < WW; m++) {
        const float4* kp = (const float4*)(sk + m * 36);
        float s = 0.f;
#pragma unroll
        for (int j = 0; j < 8; j++) {
            float4 kv = kp[j];
            s += q4[j].x * kv.x + q4[j].y * kv.y + q4[j].z * kv.z + q4[j].w * kv.w;
        }
        const float4* vp = (const float4*)(sv + m * 36);
        if (s > mrun) {
            float corr = __expf(mrun - s);
            mrun = s;
            lrun = lrun * corr + 1.f;
#pragma unroll
            for (int j = 0; j < 8; j++) {
                float4 vv = vp[j];
                a4[j].x = a4[j].x * corr + vv.x;
                a4[j].y = a4[j].y * corr + vv.y;
                a4[j].z = a4[j].z * corr + vv.z;
                a4[j].w = a4[j].w * corr + vv.w;
            }
        } else {
            float p = __expf(s - mrun);
            lrun += p;
#pragma unroll
            for (int j = 0; j < 8; j++) {
                float4 vv = vp[j];
                a4[j].x += p * vv.x;
                a4[j].y += p * vv.y;
                a4[j].z += p * vv.z;
                a4[j].w += p * vv.w;
            }
        }
    }
    float inv = 1.f / lrun;
    float* op = Ob + base;
#pragma unroll
    for (int j = 0; j < 8; j++) {
        op[(size_t)(4 * j + 0) * WW + n] = a4[j].x * inv;
        op[(size_t)(4 * j + 1) * WW + n] = a4[j].y * inv;
        op[(size_t)(4 * j + 2) * WW + n] = a4[j].z * inv;
        op[(size_t)(4 * j + 3) * WW + n] = a4[j].w * inv;
    }
}

// ---------------- fused depthwise: out = sqrelu(conv11(z)+b11) + (conv7(z)+b7) ----------------
__global__ void dwfused_kernel(const float* __restrict__ z, const float* __restrict__ w11,
                               const float* __restrict__ b11, const float* __restrict__ w7,
                               const float* __restrict__ b7, float* __restrict__ out) {
    int w = blockIdx.x * 128 + threadIdx.x;
    int f = blockIdx.y;
    int bc = blockIdx.z;
    int c = bc & 7;
    const float* zp = z + (size_t)bc * FF * WW + w;
    float a = b11[c], b2 = b7[c];
#pragma unroll
    for (int k = 0; k < 11; k++) {
        int fv = f + k - 5;
        if (fv >= 0 && fv < FF) {
            float v = zp[(size_t)fv * WW];
            a += w11[c * 11 + k] * v;
            if (k >= 2 && k <= 8) b2 += w7[c * 7 + (k - 2)] * v;
        }
    }
    float r = fmaxf(a, 0.f);
    out[((size_t)bc * FF + f) * WW + w] = r * r + b2;
}

// ---------------- depthwise 7-tap conv, accumulated into h ----------------
__global__ void dwc2_acc_kernel(const float* __restrict__ z, const float* __restrict__ w7,
                                const float* __restrict__ b7, float* __restrict__ h) {
    int w = blockIdx.x * 128 + threadIdx.x;
    int f = blockIdx.y;
    int bc = blockIdx.z;
    int c = bc & 7;
    const float* zp = z + (size_t)bc * FF * WW + w;
    float s = b7[c];
#pragma unroll
    for (int k = 0; k < 7; k++) {
        int fv = f + k - 3;
        if (fv >= 0 && fv < FF) s += w7[c * 7 + k] * zp[(size_t)fv * WW];
    }
    h[((size_t)bc * FF + f) * WW + w] += s;
}

// ---------------- FFN ----------------
__global__ void ffn1_kernel(const float* __restrict__ z, const float* __restrict__ w3,
                            float* __restrict__ u) {
    int w = blockIdx.x * 128 + threadIdx.x;
    int e = blockIdx.y;
    int bc = blockIdx.z;
    int c = bc & 7;
    const float* zp = z + (size_t)bc * FF * WW + w;
    const float* wp = w3 + (c * EE + e) * FF;
    float s = 0.f;
#pragma unroll 8
    for (int f = 0; f < FF; f++) s += wp[f] * zp[(size_t)f * WW];
    float r = fmaxf(s, 0.f);
    u[((size_t)bc * EE + e) * WW + w] = r * r;
}

__global__ void ffn2_kernel(const float* __restrict__ u, const float* __restrict__ w4,
                            float* __restrict__ h) {
    int w = blockIdx.x * 128 + threadIdx.x;
    int f = blockIdx.y;
    int bc = blockIdx.z;
    int c = bc & 7;
    const float* up = u + (size_t)bc * EE * WW + w;
    const float* wp = w4 + ((size_t)c * FF + f) * EE;
    float s = wp[0] * up[0] + wp[1] * up[WW] + wp[2] * up[2 * WW] + wp[3] * up[3 * WW];
    h[((size_t)bc * FF + f) * WW + w] += s;
}

// ---------------- output: concat(x, h) on channel axis ----------------
__global__ void out_kernel(const float* __restrict__ x, const float* __restrict__ h,
                           float* __restrict__ out) {
    size_t i = (size_t)blockIdx.x * blockDim.x + threadIdx.x;
    size_t total = (size_t)BB * 2 * CC * FF * WW;
    if (i >= total) return;
    size_t chunk = (size_t)CC * FF * WW;
    size_t grp = i / chunk;      // 0: b0.x, 1: b0.h, 2: b1.x, 3: b1.h
    size_t inner = i % chunk;
    size_t b = grp >> 1;
    const float* src = (grp & 1) ? h : x;
    out[i] = src[b * chunk + inner];
}

// ================================================================================
extern "C" void kernel_launch(void* const* d_in, const int* in_sizes, int n_in,
                              void* d_out, int out_size) {
    const float* x    = (const float*)d_in[0];
    const float* skip = (const float*)d_in[1];
    const float* Wq   = (const float*)d_in[2];
    const float* Kq   = (const float*)d_in[3];
    const float* bq   = (const float*)d_in[4];
    const float* Wk   = (const float*)d_in[5];
    const float* Kk   = (const float*)d_in[6];
    const float* bk   = (const float*)d_in[7];
    const float* Wv   = (const float*)d_in[8];
    const float* Kv   = (const float*)d_in[9];
    const float* bv   = (const float*)d_in[10];
    const float* Wo   = (const float*)d_in[11];
    const float* ng   = (const float*)d_in[12];
    const float* nb   = (const float*)d_in[13];
    const float* c1aw = (const float*)d_in[14];
    const float* c1ab = (const float*)d_in[15];
    const float* c1bw = (const float*)d_in[16];
    const float* c1bb = (const float*)d_in[17];
    const float* c2w  = (const float*)d_in[18];
    const float* c2b  = (const float*)d_in[19];
    const float* w3   = (const float*)d_in[20];
    const float* w4   = (const float*)d_in[21];
    float* out = (float*)d_out;

    float *ph, *pz, *pq, *pk, *pv, *pt, *pu;
    cudaGetSymbolAddress((void**)&ph, g_h);
    cudaGetSymbolAddress((void**)&pz, g_z);
    cudaGetSymbolAddress((void**)&pq, g_q);
    cudaGetSymbolAddress((void**)&pk, g_k);
    cudaGetSymbolAddress((void**)&pv, g_v);
    cudaGetSymbolAddress((void**)&pt, g_t);
    cudaGetSymbolAddress((void**)&pu, g_u);

    cudaFuncSetAttribute(attn_kernel, cudaFuncAttributeMaxDynamicSharedMemorySize, ATTN_SMEM);

    const dim3 gemm_grid(4, 2, BC);     // W/128, F/128, bc
    const dim3 conv_grid(4, FF / 2, BC);
    const dim3 ln_grid(2, BC);
    const dim3 elw_grid(4, FF, BC);

    const size_t WFF = (size_t)CC * FF * FF;    // per-layer Wq stride
    const size_t KFF = (size_t)CC * CC * 3;     // per-layer Kq stride

    auto attn_block = [&](int i, const float* qsrc, const float* msrc) {
        gemm128<0><<<gemm_grid, 256>>>(qsrc, Wq + (size_t)i * WFF, pt);
        convrope_kernel<<<conv_grid, 128>>>(pt, Kq + (size_t)i * KFF, bq + i * CC, pq, 1);
        gemm128<0><<<gemm_grid, 256>>>(msrc, Wk + (size_t)i * WFF, pt);
        convrope_kernel<<<conv_grid, 128>>>(pt, Kk + (size_t)i * KFF, bk + i * CC, pk, 1);
        gemm128<0><<<gemm_grid, 256>>>(msrc, Wv + (size_t)i * WFF, pt);
        convrope_kernel<<<conv_grid, 128>>>(pt, Kv + (size_t)i * KFF, bv + i * CC, pv, 0);
        attn_kernel<<<BC * HH, 512, ATTN_SMEM>>>(pq, pk, pv, pt);
        gemm128<1><<<gemm_grid, 256>>>(pt, Wo + (size_t)i * WFF, ph);
    };

    // h = x
    copy_kernel<<<2048, 512>>>(ph, x, NTOT);

    // z = LN0(h); h += attn0(z,z); h += attn1(z, skip)
    ln_kernel<<<ln_grid, 256>>>(ph, ng + 0 * CC * FF, nb + 0 * CC * FF, pz);
    attn_block(0, pz, pz);
    attn_block(1, pz, skip);

    // conv block
    ln_kernel<<<ln_grid, 256>>>(ph, ng + 1 * CC * FF, nb + 1 * CC * FF, pz);
    dwfused_kernel<<<elw_grid, 128>>>(pz, c1aw, c1ab, c1bw, c1bb, pq);
    ln_kernel<<<ln_grid, 256>>>(pq, ng + 2 * CC * FF, nb + 2 * CC * FF, pz);
    dwc2_acc_kernel<<<elw_grid, 128>>>(pz, c2w, c2b, ph);

    // attn2 (self) and attn3 (skip)
    ln_kernel<<<ln_grid, 256>>>(ph, ng + 3 * CC * FF, nb + 3 * CC * FF, pz);
    attn_block(2, pz, pz);
    ln_kernel<<<ln_grid, 256>>>(ph, ng + 4 * CC * FF, nb + 4 * CC * FF, pz);
    attn_block(3, pz, skip);

    // FFN
    ln_kernel<<<ln_grid, 256>>>(ph, ng + 5 * CC * FF, nb + 5 * CC * FF, pz);
    ffn1_kernel<<<dim3(4, EE, BC), 128>>>(pz, w3, pu);
    ffn2_kernel<<<elw_grid, 128>>>(pu, w4, ph);

    // out = concat(x, h)
    size_t total = (size_t)BB * 2 * CC * FF * WW;
    out_kernel<<<(unsigned)((total + 255) / 256), 256>>>(x, ph, out);
    (void)in_sizes; (void)n_in; (void)out_size;
}

// round 2
// speedup vs baseline: 1.1113x; 1.1113x over previous
#include <cuda_runtime.h>
#include <cuda_bf16.h>
#include <math.h>

#define BB 2
#define CC 8
#define FF 256
#define WW 512
#define HH 8
#define HD 32
#define EE 4
#define BC (BB*CC)
#define NTOT ((size_t)BB*CC*FF*WW)

// ---------------- scratch (static device globals; no allocation) ----------------
__device__ float g_h[BB*CC*FF*WW];
__device__ float g_z[BB*CC*FF*WW];
__device__ float g_q[BB*CC*FF*WW];
__device__ float g_k[BB*CC*FF*WW];
__device__ float g_v[BB*CC*FF*WW];
__device__ float g_t[BB*CC*FF*WW];
__device__ float g_t2[BB*CC*FF*WW];
__device__ float g_t3[BB*CC*FF*WW];
__device__ float g_u[BB*CC*EE*WW];

// ---------------- packed f32x2 helpers (sm_100a) ----------------
__device__ __forceinline__ unsigned long long pk2(float lo, float hi) {
    unsigned long long r;
    asm("mov.b64 %0, {%1, %2};" : "=l"(r) : "f"(lo), "f"(hi));
    return r;
}
// d = a*b + d
__device__ __forceinline__ void fma2(unsigned long long& d, unsigned long long a, unsigned long long b) {
    asm("fma.rn.f32x2 %0, %1, %2, %0;" : "+l"(d) : "l"(a), "l"(b));
}
// d = d*b + c
__device__ __forceinline__ void fma2o(unsigned long long& d, unsigned long long b, unsigned long long c) {
    asm("fma.rn.f32x2 %0, %0, %1, %2;" : "+l"(d) : "l"(b), "l"(c));
}
__device__ __forceinline__ float2 up2(unsigned long long v) {
    float2 r;
    asm("mov.b64 {%0, %1}, %2;" : "=f"(r.x), "=f"(r.y) : "l"(v));
    return r;
}

// ---------------- simple copy ----------------
__global__ void copy_kernel(float* __restrict__ dst, const float* __restrict__ src, size_t n) {
    size_t i = (size_t)blockIdx.x * blockDim.x + threadIdx.x;
    size_t stride = (size_t)gridDim.x * blockDim.x;
    for (; i < n; i += stride) dst[i] = src[i];
}

// ---------------- LayerNorm over features (axis f), per (b,c,w) column ----------------
__global__ void ln_kernel(const float* __restrict__ src, const float* __restrict__ g,
                          const float* __restrict__ bet, float* __restrict__ dst) {
    int bc = blockIdx.y;
    int w = blockIdx.x * blockDim.x + threadIdx.x;
    int c = bc & (CC - 1);
    const float* p = src + (size_t)bc * FF * WW + w;
    float s = 0.f, s2 = 0.f;
#pragma unroll 8
    for (int f = 0; f < FF; f++) {
        float v = p[(size_t)f * WW];
        s += v; s2 += v * v;
    }
    float m = s * (1.0f / FF);
    float var = s2 * (1.0f / FF) - m * m;
    float rs = rsqrtf(var + 1e-5f);
    const float* gc = g + c * FF;
    const float* bb = bet + c * FF;
    float* q = dst + (size_t)bc * FF * WW + w;
#pragma unroll 8
    for (int f = 0; f < FF; f++) {
        q[(size_t)f * WW] = (p[(size_t)f * WW] - m) * rs * gc[f] + bb[f];
    }
}

// ---------------- SGEMM tile body: C[128m x 128n] = A[128m x 256k] * B[256k x 128n] ----------------
// 256 threads, 8x8 microtile via packed f32x2, double-buffered smem.
__device__ __forceinline__ void gemm_tile(const float* __restrict__ A, const float* __restrict__ Bx,
                                          float* __restrict__ Cp, int m0, int n0, bool accum) {
    __shared__ alignas(16) float As[2][8 * 132];
    __shared__ alignas(16) float Bs[2][8 * 132];
    int t = threadIdx.x;
    int tx = t & 15, ty = t >> 4;
    int am = t >> 1;            // 0..127 (row of A tile)
    int ak = (t & 1) * 4;       // 0 or 4
    int bk = t >> 5;            // 0..7
    int bn = (t & 31) * 4;      // 0..124

    unsigned long long acc2[8][4];
#pragma unroll
    for (int i = 0; i < 8; i++)
#pragma unroll
        for (int j = 0; j < 4; j++) acc2[i][j] = 0ull;

    float4 av = *(const float4*)(A + (size_t)(m0 + am) * FF + ak);
    float4 bv = *(const float4*)(Bx + (size_t)bk * WW + n0 + bn);
    As[0][(ak + 0) * 132 + am] = av.x;
    As[0][(ak + 1) * 132 + am] = av.y;
    As[0][(ak + 2) * 132 + am] = av.z;
    As[0][(ak + 3) * 132 + am] = av.w;
    *(float4*)(&Bs[0][bk * 132 + bn]) = bv;
    __syncthreads();

    for (int k0 = 0; k0 < FF; k0 += 8) {
        int cur = (k0 >> 3) & 1;
        bool has = (k0 + 8) < FF;
        float4 av2, bv2;
        if (has) {
            av2 = *(const float4*)(A + (size_t)(m0 + am) * FF + k0 + 8 + ak);
            bv2 = *(const float4*)(Bx + (size_t)(k0 + 8 + bk) * WW + n0 + bn);
        }
        const float* Asc = As[cur];
        const float* Bsc = Bs[cur];
#pragma unroll
        for (int k = 0; k < 8; k++) {
            float4 a0 = *(const float4*)(Asc + k * 132 + ty * 8);
            float4 a1 = *(const float4*)(Asc + k * 132 + ty * 8 + 4);
            ulonglong2 b01 = *(const ulonglong2*)(Bsc + k * 132 + tx * 4);
            ulonglong2 b23 = *(const ulonglong2*)(Bsc + k * 132 + 64 + tx * 4);
            unsigned long long a2[8];
            a2[0] = pk2(a0.x, a0.x); a2[1] = pk2(a0.y, a0.y);
            a2[2] = pk2(a0.z, a0.z); a2[3] = pk2(a0.w, a0.w);
            a2[4] = pk2(a1.x, a1.x); a2[5] = pk2(a1.y, a1.y);
            a2[6] = pk2(a1.z, a1.z); a2[7] = pk2(a1.w, a1.w);
#pragma unroll
            for (int i = 0; i < 8; i++) {
                fma2(acc2[i][0], a2[i], b01.x);
                fma2(acc2[i][1], a2[i], b01.y);
                fma2(acc2[i][2], a2[i], b23.x);
                fma2(acc2[i][3], a2[i], b23.y);
            }
        }
        if (has) {
            As[cur ^ 1][(ak + 0) * 132 + am] = av2.x;
            As[cur ^ 1][(ak + 1) * 132 + am] = av2.y;
            As[cur ^ 1][(ak + 2) * 132 + am] = av2.z;
            As[cur ^ 1][(ak + 3) * 132 + am] = av2.w;
            *(float4*)(&Bs[cur ^ 1][bk * 132 + bn]) = bv2;
        }
        __syncthreads();
    }

#pragma unroll
    for (int i = 0; i < 8; i++) {
        float* crow = Cp + (size_t)(m0 + ty * 8 + i) * WW + n0;
        float2 p0 = up2(acc2[i][0]);
        float2 p1 = up2(acc2[i][1]);
        float2 p2 = up2(acc2[i][2]);
        float2 p3 = up2(acc2[i][3]);
        if (accum) {
            float4 c0 = *(float4*)(crow + tx * 4);
            float4 c1 = *(float4*)(crow + 64 + tx * 4);
            c0.x += p0.x; c0.y += p0.y; c0.z += p1.x; c0.w += p1.y;
            c1.x += p2.x; c1.y += p2.y; c1.z += p3.x; c1.w += p3.y;
            *(float4*)(crow + tx * 4) = c0;
            *(float4*)(crow + 64 + tx * 4) = c1;
        } else {
            *(float4*)(crow + tx * 4) = make_float4(p0.x, p0.y, p1.x, p1.y);
            *(float4*)(crow + 64 + tx * 4) = make_float4(p2.x, p2.y, p3.x, p3.y);
        }
    }
}

// QKV fused GEMM: grid (4, 2, 3*BC)
__global__ __launch_bounds__(256) void gemm_qkv(const float* __restrict__ qsrc, const float* __restrict__ msrc,
                                                const float* __restrict__ Wq, const float* __restrict__ Wk,
                                                const float* __restrict__ Wv,
                                                float* __restrict__ oq, float* __restrict__ ok_,
                                                float* __restrict__ ov) {
    int z = blockIdx.z;
    int which = z >> 4;        // /BC
    int bc = z & 15;
    int c = bc & (CC - 1);
    const float* X = (which == 0) ? qsrc : msrc;
    const float* Wm = (which == 0) ? Wq : (which == 1) ? Wk : Wv;
    float* Out = (which == 0) ? oq : (which == 1) ? ok_ : ov;
    gemm_tile(Wm + (size_t)c * FF * FF, X + (size_t)bc * FF * WW,
              Out + (size_t)bc * FF * WW, blockIdx.y * 128, blockIdx.x * 128, false);
}

// single GEMM (O projection): grid (4, 2, BC)
__global__ __launch_bounds__(256) void gemm_one(const float* __restrict__ X, const float* __restrict__ Wm,
                                                float* __restrict__ Out, int accum) {
    int bc = blockIdx.z;
    int c = bc & (CC - 1);
    gemm_tile(Wm + (size_t)c * FF * FF, X + (size_t)bc * FF * WW,
              Out + (size_t)bc * FF * WW, blockIdx.y * 128, blockIdx.x * 128, accum != 0);
}

// ---------------- fused QKV 1x3 channel-mix conv + RoPE ----------------
// grid (4, FF/2, 3*BB), block 128. One block produces ALL 8 output channels.
__global__ void convrope3_kernel(const float* __restrict__ tq, const float* __restrict__ tk,
                                 const float* __restrict__ tv,
                                 const float* __restrict__ Kq, const float* __restrict__ Kk,
                                 const float* __restrict__ Kv,
                                 const float* __restrict__ bq, const float* __restrict__ bk,
                                 const float* __restrict__ bv,
                                 float* __restrict__ oq, float* __restrict__ ok_,
                                 float* __restrict__ ov) {
    int which = blockIdx.z / BB;
    int b = blockIdx.z % BB;
    const float* src = (which == 0) ? tq : (which == 1) ? tk : tv;
    const float* Kw  = (which == 0) ? Kq : (which == 1) ? Kk : Kv;
    const float* bias = (which == 0) ? bq : (which == 1) ? bk : bv;
    float* dst = (which == 0) ? oq : (which == 1) ? ok_ : ov;
    int w0 = blockIdx.x * 128;
    int f0 = blockIdx.y * 2;
    int t = threadIdx.x;
    __shared__ float s[CC * 2 * 132];
    __shared__ float sK[CC * CC * 3];
    __shared__ float sB[CC];
    for (int idx = t; idx < CC * CC * 3; idx += 128) sK[idx] = Kw[idx];
    if (t < CC) sB[t] = bias[t];
    for (int idx = t; idx < CC * 2 * 130; idx += 128) {
        int col = idx % 130;
        int rr = (idx / 130) & 1;
        int ci = idx / 260;
        int wg = w0 - 1 + col;
        float v = 0.f;
        if (wg >= 0 && wg < WW)
            v = src[((size_t)(b * CC + ci) * FF + f0 + rr) * WW + wg];
        s[(ci * 2 + rr) * 132 + col] = v;
    }
    __syncthreads();
    int w = w0 + t;
    float sn, cs;
    int d = f0 & (HD - 1);
    float theta = expf(-(float)d * (9.210340371976184f / (float)HD));  // 10000^{-d/HD}
    sincosf((float)w * theta, &sn, &cs);
    bool dorope = (which < 2);
#pragma unroll
    for (int co = 0; co < CC; co++) {
        float y0 = sB[co], y1 = y0;
#pragma unroll
        for (int ci = 0; ci < CC; ci++) {
            float k0 = sK[(co * CC + ci) * 3 + 0];
            float k1 = sK[(co * CC + ci) * 3 + 1];
            float k2 = sK[(co * CC + ci) * 3 + 2];
            const float* r0p = s + (ci * 2 + 0) * 132 + t;
            const float* r1p = s + (ci * 2 + 1) * 132 + t;
            y0 += k0 * r0p[0] + k1 * r0p[1] + k2 * r0p[2];
            y1 += k0 * r1p[0] + k1 * r1p[1] + k2 * r1p[2];
        }
        float* op = dst + ((size_t)(b * CC + co) * FF + f0) * WW + w;
        if (dorope) {
            op[0]  = y0 * cs - y1 * sn;
            op[WW] = y1 * cs + y0 * sn;
        } else {
            op[0] = y0;
            op[WW] = y1;
        }
    }
}

// ---------------- attention: one CTA per (b,c,h), K/V in smem, f32x2 online softmax ----------------
#define ATTN_SMEM (2 * WW * 36 * 4)
__global__ __launch_bounds__(512) void attn_kernel(const float* __restrict__ Q,
                                                   const float* __restrict__ Kb,
                                                   const float* __restrict__ Vb,
                                                   float* __restrict__ Ob) {
    extern __shared__ float smB[];
    float* sk = smB;
    float* sv = smB + WW * 36;
    int bch = blockIdx.x;
    int h = bch & (HH - 1);
    int bc = bch >> 3;
    size_t base = ((size_t)bc * FF + h * HD) * WW;
    const float* gq = Q + base;
    const float* gk = Kb + base;
    const float* gv = Vb + base;
    int n = threadIdx.x;
#pragma unroll
    for (int d = 0; d < HD; d++) {
        sk[n * 36 + d] = gk[(size_t)d * WW + n];
        sv[n * 36 + d] = gv[(size_t)d * WW + n];
    }
    unsigned long long q2[16];
#pragma unroll
    for (int u = 0; u < 16; u++) {
        float lo = gq[(size_t)(2 * u) * WW + n] * 0.0625f;      // fold 1/sqrt(F)
        float hi = gq[(size_t)(2 * u + 1) * WW + n] * 0.0625f;
        q2[u] = pk2(lo, hi);
    }
    __syncthreads();

    float mrun = -INFINITY, lrun = 0.f;
    unsigned long long a2[16];
#pragma unroll
    for (int u = 0; u < 16; u++) a2[u] = 0ull;

    for (int m = 0; m < WW; m++) {
        const ulonglong2* kp = (const ulonglong2*)(sk + m * 36);
        unsigned long long s0 = 0ull, s1 = 0ull, s2 = 0ull, s3 = 0ull;
#pragma unroll
        for (int i = 0; i < 8; i += 2) {
            ulonglong2 ka = kp[i];
            ulonglong2 kb2 = kp[i + 1];
            fma2(s0, q2[2 * i + 0], ka.x);
            fma2(s1, q2[2 * i + 1], ka.y);
            fma2(s2, q2[2 * i + 2], kb2.x);
            fma2(s3, q2[2 * i + 3], kb2.y);
        }
        float2 r0 = up2(s0), r1 = up2(s1), r2 = up2(s2), r3 = up2(s3);
        float s = ((r0.x + r0.y) + (r1.x + r1.y)) + ((r2.x + r2.y) + (r3.x + r3.y));
        const ulonglong2* vp = (const ulonglong2*)(sv + m * 36);
        if (s > mrun) {
            float corr = __expf(mrun - s);
            mrun = s;
            lrun = lrun * corr + 1.f;
            unsigned long long c2 = pk2(corr, corr);
#pragma unroll
            for (int i = 0; i < 8; i++) {
                ulonglong2 vv = vp[i];
                fma2o(a2[2 * i + 0], c2, vv.x);
                fma2o(a2[2 * i + 1], c2, vv.y);
            }
        } else {
            float p = __expf(s - mrun);
            lrun += p;
            unsigned long long p2 = pk2(p, p);
#pragma unroll
            for (int i = 0; i < 8; i++) {
                ulonglong2 vv = vp[i];
                fma2(a2[2 * i + 0], p2, vv.x);
                fma2(a2[2 * i + 1], p2, vv.y);
            }
        }
    }
    float inv = 1.f / lrun;
    float* op = Ob + base;
#pragma unroll
    for (int u = 0; u < 16; u++) {
        float2 r = up2(a2[u]);
        op[(size_t)(2 * u) * WW + n]     = r.x * inv;
        op[(size_t)(2 * u + 1) * WW + n] = r.y * inv;
    }
}

// ---------------- fused depthwise: out = sqrelu(conv11(z)) + conv7(z), column-walking ----------------
// grid (4, BC), block 128
__global__ void dwfused_kernel(const float* __restrict__ z, const float* __restrict__ w11,
                               const float* __restrict__ b11, const float* __restrict__ w7,
                               const float* __restrict__ b7, float* __restrict__ out) {
    int w = blockIdx.x * 128 + threadIdx.x;
    int bc = blockIdx.y;
    int c = bc & 7;
    const float* zp = z + (size_t)bc * FF * WW + w;
    float* op = out + (size_t)bc * FF * WW + w;
    float k11[11], k7[7];
#pragma unroll
    for (int j = 0; j < 11; j++) k11[j] = w11[c * 11 + j];
#pragma unroll
    for (int j = 0; j < 7; j++) k7[j] = w7[c * 7 + j];
    float bb11 = b11[c], bb7 = b7[c];
    float win[11];
#pragma unroll
    for (int j = 0; j < 5; j++) win[j] = 0.f;
#pragma unroll
    for (int j = 5; j < 11; j++) win[j] = zp[(size_t)(j - 5) * WW];
    for (int f = 0; f < FF; f++) {
        float a = bb11, b2v = bb7;
#pragma unroll
        for (int j = 0; j < 11; j++) a += k11[j] * win[j];
#pragma unroll
        for (int j = 0; j < 7; j++) b2v += k7[j] * win[j + 2];
        float r = fmaxf(a, 0.f);
        op[(size_t)f * WW] = r * r + b2v;
#pragma unroll
        for (int j = 0; j < 10; j++) win[j] = win[j + 1];
        int fn = f + 6;
        win[10] = (fn < FF) ? zp[(size_t)fn * WW] : 0.f;
    }
}

// ---------------- depthwise 7-tap conv accumulated into h, column-walking ----------------
// grid (4, BC), block 128
__global__ void dwc2_acc_kernel(const float* __restrict__ z, const float* __restrict__ w7,
                                const float* __restrict__ b7, float* __restrict__ h) {
    int w = blockIdx.x * 128 + threadIdx.x;
    int bc = blockIdx.y;
    int c = bc & 7;
    const float* zp = z + (size_t)bc * FF * WW + w;
    float* op = h + (size_t)bc * FF * WW + w;
    float k7[7];
#pragma unroll
    for (int j = 0; j < 7; j++) k7[j] = w7[c * 7 + j];
    float bb = b7[c];
    float win[7];
#pragma unroll
    for (int j = 0; j < 3; j++) win[j] = 0.f;
#pragma unroll
    for (int j = 3; j < 7; j++) win[j] = zp[(size_t)(j - 3) * WW];
    for (int f = 0; f < FF; f++) {
        float a = bb;
#pragma unroll
        for (int j = 0; j < 7; j++) a += k7[j] * win[j];
        op[(size_t)f * WW] += a;
#pragma unroll
        for (int j = 0; j < 6; j++) win[j] = win[j + 1];
        int fn = f + 4;
        win[6] = (fn < FF) ? zp[(size_t)fn * WW] : 0.f;
    }
}

// ---------------- FFN ----------------
// grid (4, BC), block 128: all 4 e-outputs in one pass over f
__global__ void ffn1_kernel(const float* __restrict__ z, const float* __restrict__ w3,
                            float* __restrict__ u) {
    int w = blockIdx.x * 128 + threadIdx.x;
    int bc = blockIdx.y;
    int c = bc & 7;
    const float* zp = z + (size_t)bc * FF * WW + w;
    const float* wp = w3 + (size_t)c * EE * FF;
    float s0 = 0.f, s1 = 0.f, s2 = 0.f, s3 = 0.f;
#pragma unroll 4
    for (int f = 0; f < FF; f++) {
        float zv = zp[(size_t)f * WW];
        s0 += wp[f] * zv;
        s1 += wp[FF + f] * zv;
        s2 += wp[2 * FF + f] * zv;
        s3 += wp[3 * FF + f] * zv;
    }
    float* up = u + (size_t)bc * EE * WW + w;
    float r;
    r = fmaxf(s0, 0.f); up[0]      = r * r;
    r = fmaxf(s1, 0.f); up[WW]     = r * r;
    r = fmaxf(s2, 0.f); up[2 * WW] = r * r;
    r = fmaxf(s3, 0.f); up[3 * WW] = r * r;
}

__global__ void ffn2_kernel(const float* __restrict__ u, const float* __restrict__ w4,
                            float* __restrict__ h) {
    int w = blockIdx.x * 128 + threadIdx.x;
    int f = blockIdx.y;
    int bc = blockIdx.z;
    int c = bc & 7;
    const float* up = u + (size_t)bc * EE * WW + w;
    const float* wp = w4 + ((size_t)c * FF + f) * EE;
    float s = wp[0] * up[0] + wp[1] * up[WW] + wp[2] * up[2 * WW] + wp[3] * up[3 * WW];
    h[((size_t)bc * FF + f) * WW + w] += s;
}

// ---------------- output: concat(x, h) on channel axis ----------------
__global__ void out_kernel(const float* __restrict__ x, const float* __restrict__ h,
                           float* __restrict__ out) {
    size_t i = (size_t)blockIdx.x * blockDim.x + threadIdx.x;
    size_t total = (size_t)BB * 2 * CC * FF * WW;
    if (i >= total) return;
    size_t chunk = (size_t)CC * FF * WW;
    size_t grp = i / chunk;
    size_t inner = i % chunk;
    size_t b = grp >> 1;
    const float* src = (grp & 1) ? h : x;
    out[i] = src[b * chunk + inner];
}

// ================================================================================
extern "C" void kernel_launch(void* const* d_in, const int* in_sizes, int n_in,
                              void* d_out, int out_size) {
    const float* x    = (const float*)d_in[0];
    const float* skip = (const float*)d_in[1];
    const float* Wq   = (const float*)d_in[2];
    const float* Kq   = (const float*)d_in[3];
    const float* bq   = (const float*)d_in[4];
    const float* Wk   = (const float*)d_in[5];
    const float* Kk   = (const float*)d_in[6];
    const float* bk   = (const float*)d_in[7];
    const float* Wv   = (const float*)d_in[8];
    const float* Kv   = (const float*)d_in[9];
    const float* bv   = (const float*)d_in[10];
    const float* Wo   = (const float*)d_in[11];
    const float* ng   = (const float*)d_in[12];
    const float* nb   = (const float*)d_in[13];
    const float* c1aw = (const float*)d_in[14];
    const float* c1ab = (const float*)d_in[15];
    const float* c1bw = (const float*)d_in[16];
    const float* c1bb = (const float*)d_in[17];
    const float* c2w  = (const float*)d_in[18];
    const float* c2b  = (const float*)d_in[19];
    const float* w3   = (const float*)d_in[20];
    const float* w4   = (const float*)d_in[21];
    float* out = (float*)d_out;

    float *ph, *pz, *pq, *pk, *pv, *ptq, *ptk, *ptv, *pu;
    cudaGetSymbolAddress((void**)&ph, g_h);
    cudaGetSymbolAddress((void**)&pz, g_z);
    cudaGetSymbolAddress((void**)&pq, g_q);
    cudaGetSymbolAddress((void**)&pk, g_k);
    cudaGetSymbolAddress((void**)&pv, g_v);
    cudaGetSymbolAddress((void**)&ptq, g_t);
    cudaGetSymbolAddress((void**)&ptk, g_t2);
    cudaGetSymbolAddress((void**)&ptv, g_t3);
    cudaGetSymbolAddress((void**)&pu, g_u);

    cudaFuncSetAttribute(attn_kernel, cudaFuncAttributeMaxDynamicSharedMemorySize, ATTN_SMEM);

    const dim3 gemm_grid(4, 2, BC);
    const dim3 gemm3_grid(4, 2, 3 * BC);
    const dim3 conv3_grid(4, FF / 2, 3 * BB);
    const dim3 ln_grid(2, BC);
    const dim3 col_grid(4, BC);

    const size_t WFF = (size_t)CC * FF * FF;
    const size_t KFF = (size_t)CC * CC * 3;

    auto attn_block = [&](int i, const float* qsrc, const float* msrc) {
        gemm_qkv<<<gemm3_grid, 256>>>(qsrc, msrc, Wq + (size_t)i * WFF, Wk + (size_t)i * WFF,
                                      Wv + (size_t)i * WFF, ptq, ptk, ptv);
        convrope3_kernel<<<conv3_grid, 128>>>(ptq, ptk, ptv,
                                              Kq + (size_t)i * KFF, Kk + (size_t)i * KFF, Kv + (size_t)i * KFF,
                                              bq + i * CC, bk + i * CC, bv + i * CC,
                                              pq, pk, pv);
        attn_kernel<<<BC * HH, 512, ATTN_SMEM>>>(pq, pk, pv, ptq);
        gemm_one<<<gemm_grid, 256>>>(ptq, Wo + (size_t)i * WFF, ph, 1);
    };

    // h = x
    copy_kernel<<<2048, 512>>>(ph, x, NTOT);

    // z = LN0(h); h += attn0(z,z); h += attn1(z, skip)
    ln_kernel<<<ln_grid, 256>>>(ph, ng + 0 * CC * FF, nb + 0 * CC * FF, pz);
    attn_block(0, pz, pz);
    attn_block(1, pz, skip);

    // conv block
    ln_kernel<<<ln_grid, 256>>>(ph, ng + 1 * CC * FF, nb + 1 * CC * FF, pz);
    dwfused_kernel<<<col_grid, 128>>>(pz, c1aw, c1ab, c1bw, c1bb, pq);
    ln_kernel<<<ln_grid, 256>>>(pq, ng + 2 * CC * FF, nb + 2 * CC * FF, pz);
    dwc2_acc_kernel<<<col_grid, 128>>>(pz, c2w, c2b, ph);

    // attn2 (self) and attn3 (skip)
    ln_kernel<<<ln_grid, 256>>>(ph, ng + 3 * CC * FF, nb + 3 * CC * FF, pz);
    attn_block(2, pz, pz);
    ln_kernel<<<ln_grid, 256>>>(ph, ng + 4 * CC * FF, nb + 4 * CC * FF, pz);
    attn_block(3, pz, skip);

    // FFN
    ln_kernel<<<ln_grid, 256>>>(ph, ng + 5 * CC * FF, nb + 5 * CC * FF, pz);
    ffn1_kernel<<<col_grid, 128>>>(pz, w3, pu);
    ffn2_kernel<<<dim3(4, FF, BC), 128>>>(pu, w4, ph);

    // out = concat(x, h)
    size_t total = (size_t)BB * 2 * CC * FF * WW;
    out_kernel<<<(unsigned)((total + 255) / 256), 256>>>(x, ph, out);
    (void)in_sizes; (void)n_in; (void)out_size;
}

// round 3
// speedup vs baseline: 1.3034x; 1.1729x over previous
#include <cuda_runtime.h>
#include <cuda_bf16.h>
#include <math.h>

#define BB 2
#define CC 8
#define FF 256
#define WW 512
#define HH 8
#define HD 32
#define EE 4
#define BC (BB*CC)
#define NTOT ((size_t)BB*CC*FF*WW)

// ---------------- scratch (static device globals; no allocation) ----------------
__device__ float g_h[BB*CC*FF*WW];
__device__ float g_z[BB*CC*FF*WW];
__device__ float g_q[BB*CC*FF*WW];
__device__ float g_k[BB*CC*FF*WW];
__device__ float g_v[BB*CC*FF*WW];
__device__ float g_t[BB*CC*FF*WW];
__device__ float g_t2[BB*CC*FF*WW];
__device__ float g_t3[BB*CC*FF*WW];
__device__ float g_u[BB*CC*EE*WW];

// ---------------- packed f32x2 helpers (sm_100a) ----------------
__device__ __forceinline__ unsigned long long pk2(float lo, float hi) {
    unsigned long long r;
    asm("mov.b64 %0, {%1, %2};" : "=l"(r) : "f"(lo), "f"(hi));
    return r;
}
__device__ __forceinline__ void fma2(unsigned long long& d, unsigned long long a, unsigned long long b) {
    asm("fma.rn.f32x2 %0, %1, %2, %0;" : "+l"(d) : "l"(a), "l"(b));
}
__device__ __forceinline__ void fma2o(unsigned long long& d, unsigned long long b, unsigned long long c) {
    asm("fma.rn.f32x2 %0, %0, %1, %2;" : "+l"(d) : "l"(b), "l"(c));
}
__device__ __forceinline__ float2 up2(unsigned long long v) {
    float2 r;
    asm("mov.b64 {%0, %1}, %2;" : "=f"(r.x), "=f"(r.y) : "l"(v));
    return r;
}

// ---------------- simple copy ----------------
__global__ void copy_kernel(float* __restrict__ dst, const float* __restrict__ src, size_t n) {
    size_t i = (size_t)blockIdx.x * blockDim.x + threadIdx.x;
    size_t stride = (size_t)gridDim.x * blockDim.x;
    for (; i < n; i += stride) dst[i] = src[i];
}

// ---------------- LayerNorm over features, f-partitioned reduce ----------------
// grid (8, BC), block (64, 8)
__global__ void ln_kernel(const float* __restrict__ src, const float* __restrict__ g,
                          const float* __restrict__ bet, float* __restrict__ dst) {
    int bc = blockIdx.y;
    int c = bc & (CC - 1);
    int tx = threadIdx.x;
    int fy = threadIdx.y;
    int w = blockIdx.x * 64 + tx;
    const float* p = src + (size_t)bc * FF * WW + w;
    float s = 0.f, s2 = 0.f;
#pragma unroll 8
    for (int f = fy * 32; f < fy * 32 + 32; f++) {
        float v = p[(size_t)f * WW];
        s += v; s2 += v * v;
    }
    __shared__ float red[2][8][64];
    red[0][fy][tx] = s;
    red[1][fy][tx] = s2;
    __syncthreads();
    float S = 0.f, S2 = 0.f;
#pragma unroll
    for (int j = 0; j < 8; j++) { S += red[0][j][tx]; S2 += red[1][j][tx]; }
    float m = S * (1.0f / FF);
    float rs = rsqrtf(S2 * (1.0f / FF) - m * m + 1e-5f);
    const float* gc = g + c * FF;
    const float* bb = bet + c * FF;
    float* q = dst + (size_t)bc * FF * WW + w;
#pragma unroll 8
    for (int f = fy * 32; f < fy * 32 + 32; f++) {
        q[(size_t)f * WW] = (p[(size_t)f * WW] - m) * rs * gc[f] + bb[f];
    }
}

// ---------------- SGEMM tile: C[128m x 128n] = A[128m x 256k] * B[256k x 128n] ----------------
// 256 threads, 8x8 microtile, f32x2, double-buffered smem, A stored DUPLICATED.
#define APAD 268
__device__ __forceinline__ void gemm_tile(const float* __restrict__ A, const float* __restrict__ Bx,
                                          float* __restrict__ Cp, int m0, int n0, bool accum) {
    __shared__ alignas(16) float As[2][8 * APAD];
    __shared__ alignas(16) float Bs[2][8 * 132];
    int t = threadIdx.x;
    int tx = t & 15, ty = t >> 4;
    int am = t >> 1;            // 0..127
    int ak = (t & 1) * 4;       // 0 or 4
    int bk = t >> 5;            // 0..7
    int bn = (t & 31) * 4;      // 0..124

    unsigned long long acc2[8][4];
#pragma unroll
    for (int i = 0; i < 8; i++)
#pragma unroll
        for (int j = 0; j < 4; j++) acc2[i][j] = 0ull;

    {
        float4 av = *(const float4*)(A + (size_t)(m0 + am) * FF + ak);
        float4 bv = *(const float4*)(Bx + (size_t)bk * WW + n0 + bn);
        *(float2*)(&As[0][(ak + 0) * APAD + 2 * am]) = make_float2(av.x, av.x);
        *(float2*)(&As[0][(ak + 1) * APAD + 2 * am]) = make_float2(av.y, av.y);
        *(float2*)(&As[0][(ak + 2) * APAD + 2 * am]) = make_float2(av.z, av.z);
        *(float2*)(&As[0][(ak + 3) * APAD + 2 * am]) = make_float2(av.w, av.w);
        *(float4*)(&Bs[0][bk * 132 + bn]) = bv;
    }
    __syncthreads();

    for (int k0 = 0; k0 < FF; k0 += 8) {
        int cur = (k0 >> 3) & 1;
        bool has = (k0 + 8) < FF;
        float4 av2, bv2;
        if (has) {
            av2 = *(const float4*)(A + (size_t)(m0 + am) * FF + k0 + 8 + ak);
            bv2 = *(const float4*)(Bx + (size_t)(k0 + 8 + bk) * WW + n0 + bn);
        }
        const float* Asc = As[cur];
        const float* Bsc = Bs[cur];
#pragma unroll
        for (int k = 0; k < 8; k++) {
            const ulonglong2* ap = (const ulonglong2*)(Asc + k * APAD + ty * 16);
            ulonglong2 a01 = ap[0];
            ulonglong2 a23 = ap[1];
            ulonglong2 a45 = ap[2];
            ulonglong2 a67 = ap[3];
            ulonglong2 b01 = *(const ulonglong2*)(Bsc + k * 132 + tx * 4);
            ulonglong2 b23 = *(const ulonglong2*)(Bsc + k * 132 + 64 + tx * 4);
            unsigned long long a2[8] = {a01.x, a01.y, a23.x, a23.y, a45.x, a45.y, a67.x, a67.y};
#pragma unroll
            for (int i = 0; i < 8; i++) {
                fma2(acc2[i][0], a2[i], b01.x);
                fma2(acc2[i][1], a2[i], b01.y);
                fma2(acc2[i][2], a2[i], b23.x);
                fma2(acc2[i][3], a2[i], b23.y);
            }
        }
        if (has) {
            *(float2*)(&As[cur ^ 1][(ak + 0) * APAD + 2 * am]) = make_float2(av2.x, av2.x);
            *(float2*)(&As[cur ^ 1][(ak + 1) * APAD + 2 * am]) = make_float2(av2.y, av2.y);
            *(float2*)(&As[cur ^ 1][(ak + 2) * APAD + 2 * am]) = make_float2(av2.z, av2.z);
            *(float2*)(&As[cur ^ 1][(ak + 3) * APAD + 2 * am]) = make_float2(av2.w, av2.w);
            *(float4*)(&Bs[cur ^ 1][bk * 132 + bn]) = bv2;
        }
        __syncthreads();
    }

#pragma unroll
    for (int i = 0; i < 8; i++) {
        float* crow = Cp + (size_t)(m0 + ty * 8 + i) * WW + n0;
        float2 p0 = up2(acc2[i][0]);
        float2 p1 = up2(acc2[i][1]);
        float2 p2 = up2(acc2[i][2]);
        float2 p3 = up2(acc2[i][3]);
        if (accum) {
            float4 c0 = *(float4*)(crow + tx * 4);
            float4 c1 = *(float4*)(crow + 64 + tx * 4);
            c0.x += p0.x; c0.y += p0.y; c0.z += p1.x; c0.w += p1.y;
            c1.x += p2.x; c1.y += p2.y; c1.z += p3.x; c1.w += p3.y;
            *(float4*)(crow + tx * 4) = c0;
            *(float4*)(crow + 64 + tx * 4) = c1;
        } else {
            *(float4*)(crow + tx * 4) = make_float4(p0.x, p0.y, p1.x, p1.y);
            *(float4*)(crow + 64 + tx * 4) = make_float4(p2.x, p2.y, p3.x, p3.y);
        }
    }
}

// QKV fused GEMM: grid (4, 2, 3*BC)
__global__ __launch_bounds__(256) void gemm_qkv(const float* __restrict__ qsrc, const float* __restrict__ msrc,
                                                const float* __restrict__ Wq, const float* __restrict__ Wk,
                                                const float* __restrict__ Wv,
                                                float* __restrict__ oq, float* __restrict__ ok_,
                                                float* __restrict__ ov) {
    int z = blockIdx.z;
    int which = z >> 4;
    int bc = z & 15;
    int c = bc & (CC - 1);
    const float* X = (which == 0) ? qsrc : msrc;
    const float* Wm = (which == 0) ? Wq : (which == 1) ? Wk : Wv;
    float* Out = (which == 0) ? oq : (which == 1) ? ok_ : ov;
    gemm_tile(Wm + (size_t)c * FF * FF, X + (size_t)bc * FF * WW,
              Out + (size_t)bc * FF * WW, blockIdx.y * 128, blockIdx.x * 128, false);
}

// single GEMM (O projection): grid (4, 2, BC)
__global__ __launch_bounds__(256) void gemm_one(const float* __restrict__ X, const float* __restrict__ Wm,
                                                float* __restrict__ Out, int accum) {
    int bc = blockIdx.z;
    int c = bc & (CC - 1);
    gemm_tile(Wm + (size_t)c * FF * FF, X + (size_t)bc * FF * WW,
              Out + (size_t)bc * FF * WW, blockIdx.y * 128, blockIdx.x * 128, accum != 0);
}

// ---------------- fused QKV 1x3 channel-mix conv + RoPE (direct loads, all 8 co/thread) ----------------
// grid (4, FF/2, 3*BB), block 128
__global__ __launch_bounds__(128) void convrope3_kernel(
    const float* __restrict__ tq, const float* __restrict__ tk, const float* __restrict__ tv,
    const float* __restrict__ Kq, const float* __restrict__ Kk, const float* __restrict__ Kv,
    const float* __restrict__ bq, const float* __restrict__ bk, const float* __restrict__ bv,
    float* __restrict__ oq, float* __restrict__ ok_, float* __restrict__ ov) {
    int which = blockIdx.z >> 1;       // /BB (BB=2)
    int b = blockIdx.z & 1;
    const float* src = (which == 0) ? tq : (which == 1) ? tk : tv;
    const float* Kw  = (which == 0) ? Kq : (which == 1) ? Kk : Kv;
    const float* bias = (which == 0) ? bq : (which == 1) ? bk : bv;
    float* dst = (which == 0) ? oq : (which == 1) ? ok_ : ov;

    __shared__ float4 sK4[64];
    __shared__ float sB2[CC];
    int t = threadIdx.x;
    if (t < 64) sK4[t] = make_float4(Kw[t * 3], Kw[t * 3 + 1], Kw[t * 3 + 2], 0.f);
    if (t < CC) sB2[t] = bias[t];
    __syncthreads();

    int w = blockIdx.x * 128 + t;
    int f0 = blockIdx.y * 2;
    float y0[8], y1[8];
#pragma unroll
    for (int co = 0; co < 8; co++) { y0[co] = sB2[co]; y1[co] = sB2[co]; }
#pragma unroll
    for (int ci = 0; ci < 8; ci++) {
        const float* xp = src + ((size_t)(b * CC + ci) * FF + f0) * WW + w;
        float l0 = (w > 0) ? xp[-1] : 0.f;
        float c0 = xp[0];
        float r0 = (w < WW - 1) ? xp[1] : 0.f;
        float l1 = (w > 0) ? xp[WW - 1] : 0.f;
        float c1 = xp[WW];
        float r1 = (w < WW - 1) ? xp[WW + 1] : 0.f;
#pragma unroll
        for (int co = 0; co < 8; co++) {
            float4 kk = sK4[co * 8 + ci];
            y0[co] += kk.x * l0 + kk.y * c0 + kk.z * r0;
            y1[co] += kk.x * l1 + kk.y * c1 + kk.z * r1;
        }
    }
    int d = f0 & (HD - 1);
    float theta = expf(-(float)d * (9.210340371976184f / (float)HD));
    float sn, cs;
    sincosf((float)w * theta, &sn, &cs);
    bool dorope = (which < 2);
#pragma unroll
    for (int co = 0; co < 8; co++) {
        float* op = dst + ((size_t)(b * CC + co) * FF + f0) * WW + w;
        if (dorope) {
            op[0]  = y0[co] * cs - y1[co] * sn;
            op[WW] = y1[co] * cs + y0[co] * sn;
        } else {
            op[0] = y0[co];
            op[WW] = y1[co];
        }
    }
}

// ---------------- attention: one CTA per (b,c,h), K/V in smem, f32x2 online softmax ----------------
#define ATTN_SMEM (2 * WW * 36 * 4)
__global__ __launch_bounds__(512) void attn_kernel(const float* __restrict__ Q,
                                                   const float* __restrict__ Kb,
                                                   const float* __restrict__ Vb,
                                                   float* __restrict__ Ob) {
    extern __shared__ float smB[];
    float* sk = smB;
    float* sv = smB + WW * 36;
    int bch = blockIdx.x;
    int h = bch & (HH - 1);
    int bc = bch >> 3;
    size_t base = ((size_t)bc * FF + h * HD) * WW;
    const float* gq = Q + base;
    const float* gk = Kb + base;
    const float* gv = Vb + base;
    int n = threadIdx.x;
#pragma unroll
    for (int d = 0; d < HD; d++) {
        sk[n * 36 + d] = gk[(size_t)d * WW + n];
        sv[n * 36 + d] = gv[(size_t)d * WW + n];
    }
    unsigned long long q2[16];
#pragma unroll
    for (int u = 0; u < 16; u++) {
        float lo = gq[(size_t)(2 * u) * WW + n] * 0.0625f;
        float hi = gq[(size_t)(2 * u + 1) * WW + n] * 0.0625f;
        q2[u] = pk2(lo, hi);
    }
    __syncthreads();

    float mrun = -INFINITY, lrun = 0.f;
    unsigned long long a2[16];
#pragma unroll
    for (int u = 0; u < 16; u++) a2[u] = 0ull;

    for (int m = 0; m < WW; m++) {
        const ulonglong2* kp = (const ulonglong2*)(sk + m * 36);
        unsigned long long s0 = 0ull, s1 = 0ull, s2 = 0ull, s3 = 0ull;
#pragma unroll
        for (int i = 0; i < 8; i += 2) {
            ulonglong2 ka = kp[i];
            ulonglong2 kb2 = kp[i + 1];
            fma2(s0, q2[2 * i + 0], ka.x);
            fma2(s1, q2[2 * i + 1], ka.y);
            fma2(s2, q2[2 * i + 2], kb2.x);
            fma2(s3, q2[2 * i + 3], kb2.y);
        }
        float2 r0 = up2(s0), r1 = up2(s1), r2 = up2(s2), r3 = up2(s3);
        float s = ((r0.x + r0.y) + (r1.x + r1.y)) + ((r2.x + r2.y) + (r3.x + r3.y));
        const ulonglong2* vp = (const ulonglong2*)(sv + m * 36);
        if (s > mrun) {
            float corr = __expf(mrun - s);
            mrun = s;
            lrun = lrun * corr + 1.f;
            unsigned long long c2 = pk2(corr, corr);
#pragma unroll
            for (int i = 0; i < 8; i++) {
                ulonglong2 vv = vp[i];
                fma2o(a2[2 * i + 0], c2, vv.x);
                fma2o(a2[2 * i + 1], c2, vv.y);
            }
        } else {
            float p = __expf(s - mrun);
            lrun += p;
            unsigned long long p2 = pk2(p, p);
#pragma unroll
            for (int i = 0; i < 8; i++) {
                ulonglong2 vv = vp[i];
                fma2(a2[2 * i + 0], p2, vv.x);
                fma2(a2[2 * i + 1], p2, vv.y);
            }
        }
    }
    float inv = 1.f / lrun;
    float* op = Ob + base;
#pragma unroll
    for (int u = 0; u < 16; u++) {
        float2 r = up2(a2[u]);
        op[(size_t)(2 * u) * WW + n]     = r.x * inv;
        op[(size_t)(2 * u + 1) * WW + n] = r.y * inv;
    }
}

// ---------------- fused depthwise: out = sqrelu(conv11(z)) + conv7(z) ----------------
// grid (4, FF, BC), block 128
__global__ void dwfused_kernel(const float* __restrict__ z, const float* __restrict__ w11,
                               const float* __restrict__ b11, const float* __restrict__ w7,
                               const float* __restrict__ b7, float* __restrict__ out) {
    int w = blockIdx.x * 128 + threadIdx.x;
    int f = blockIdx.y;
    int bc = blockIdx.z;
    int c = bc & 7;
    const float* zp = z + (size_t)bc * FF * WW + w;
    float a = b11[c], b2 = b7[c];
#pragma unroll
    for (int k = 0; k < 11; k++) {
        int fv = f + k - 5;
        if (fv >= 0 && fv < FF) {
            float v = zp[(size_t)fv * WW];
            a += w11[c * 11 + k] * v;
            if (k >= 2 && k <= 8) b2 += w7[c * 7 + (k - 2)] * v;
        }
    }
    float r = fmaxf(a, 0.f);
    out[((size_t)bc * FF + f) * WW + w] = r * r + b2;
}

// ---------------- depthwise 7-tap conv accumulated into h ----------------
// grid (4, FF, BC), block 128
__global__ void dwc2_acc_kernel(const float* __restrict__ z, const float* __restrict__ w7,
                                const float* __restrict__ b7, float* __restrict__ h) {
    int w = blockIdx.x * 128 + threadIdx.x;
    int f = blockIdx.y;
    int bc = blockIdx.z;
    int c = bc & 7;
    const float* zp = z + (size_t)bc * FF * WW + w;
    float s = b7[c];
#pragma unroll
    for (int k = 0; k < 7; k++) {
        int fv = f + k - 3;
        if (fv >= 0 && fv < FF) s += w7[c * 7 + k] * zp[(size_t)fv * WW];
    }
    h[((size_t)bc * FF + f) * WW + w] += s;
}

// ---------------- FFN ----------------
// grid (4, BC), block (128, 2): f-split reduction for 4 e-outputs
__global__ void ffn1_kernel(const float* __restrict__ z, const float* __restrict__ w3,
                            float* __restrict__ u) {
    int tx = threadIdx.x;
    int fy = threadIdx.y;
    int w = blockIdx.x * 128 + tx;
    int bc = blockIdx.y;
    int c = bc & 7;
    const float* zp = z + (size_t)bc * FF * WW + w;
    const float* wp = w3 + (size_t)c * EE * FF;
    float s0 = 0.f, s1 = 0.f, s2 = 0.f, s3 = 0.f;
#pragma unroll 4
    for (int f = fy * 128; f < fy * 128 + 128; f++) {
        float zv = zp[(size_t)f * WW];
        s0 += wp[f] * zv;
        s1 += wp[FF + f] * zv;
        s2 += wp[2 * FF + f] * zv;
        s3 += wp[3 * FF + f] * zv;
    }
    __shared__ float red[4][2][128];
    red[0][fy][tx] = s0; red[1][fy][tx] = s1;
    red[2][fy][tx] = s2; red[3][fy][tx] = s3;
    __syncthreads();
    if (fy == 0) {
        s0 = red[0][0][tx] + red[0][1][tx];
        s1 = red[1][0][tx] + red[1][1][tx];
        s2 = red[2][0][tx] + red[2][1][tx];
        s3 = red[3][0][tx] + red[3][1][tx];
        float* up = u + (size_t)bc * EE * WW + w;
        float r;
        r = fmaxf(s0, 0.f); up[0]      = r * r;
        r = fmaxf(s1, 0.f); up[WW]     = r * r;
        r = fmaxf(s2, 0.f); up[2 * WW] = r * r;
        r = fmaxf(s3, 0.f); up[3 * WW] = r * r;
    }
}

// ffn2 fused with output concat (h-half): out_h = h + w4·u
// grid (4, FF, BC), block 128
__global__ void ffn2_out_kernel(const float* __restrict__ u, const float* __restrict__ w4,
                                const float* __restrict__ h, float* __restrict__ out) {
    int w = blockIdx.x * 128 + threadIdx.x;
    int f = blockIdx.y;
    int bc = blockIdx.z;
    int c = bc & 7;
    int b = bc >> 3;
    const float* up = u + (size_t)bc * EE * WW + w;
    const float* wp = w4 + ((size_t)c * FF + f) * EE;
    float s = wp[0] * up[0] + wp[1] * up[WW] + wp[2] * up[2 * WW] + wp[3] * up[3 * WW];
    out[(((size_t)b * 2 * CC + CC + c) * FF + f) * WW + w] =
        h[((size_t)bc * FF + f) * WW + w] + s;
}

// copy x into out's x-half
__global__ void xcopy_kernel(const float* __restrict__ x, float* __restrict__ out) {
    size_t i = (size_t)blockIdx.x * blockDim.x + threadIdx.x;
    if (i >= NTOT) return;
    size_t chunk = (size_t)CC * FF * WW;
    size_t b = i / chunk;
    size_t inner = i % chunk;
    out[b * 2 * chunk + inner] = x[i];
}

// ================================================================================
extern "C" void kernel_launch(void* const* d_in, const int* in_sizes, int n_in,
                              void* d_out, int out_size) {
    const float* x    = (const float*)d_in[0];
    const float* skip = (const float*)d_in[1];
    const float* Wq   = (const float*)d_in[2];
    const float* Kq   = (const float*)d_in[3];
    const float* bq   = (const float*)d_in[4];
    const float* Wk   = (const float*)d_in[5];
    const float* Kk   = (const float*)d_in[6];
    const float* bk   = (const float*)d_in[7];
    const float* Wv   = (const float*)d_in[8];
    const float* Kv   = (const float*)d_in[9];
    const float* bv   = (const float*)d_in[10];
    const float* Wo   = (const float*)d_in[11];
    const float* ng   = (const float*)d_in[12];
    const float* nb   = (const float*)d_in[13];
    const float* c1aw = (const float*)d_in[14];
    const float* c1ab = (const float*)d_in[15];
    const float* c1bw = (const float*)d_in[16];
    const float* c1bb = (const float*)d_in[17];
    const float* c2w  = (const float*)d_in[18];
    const float* c2b  = (const float*)d_in[19];
    const float* w3   = (const float*)d_in[20];
    const float* w4   = (const float*)d_in[21];
    float* out = (float*)d_out;

    float *ph, *pz, *pq, *pk, *pv, *ptq, *ptk, *ptv, *pu;
    cudaGetSymbolAddress((void**)&ph, g_h);
    cudaGetSymbolAddress((void**)&pz, g_z);
    cudaGetSymbolAddress((void**)&pq, g_q);
    cudaGetSymbolAddress((void**)&pk, g_k);
    cudaGetSymbolAddress((void**)&pv, g_v);
    cudaGetSymbolAddress((void**)&ptq, g_t);
    cudaGetSymbolAddress((void**)&ptk, g_t2);
    cudaGetSymbolAddress((void**)&ptv, g_t3);
    cudaGetSymbolAddress((void**)&pu, g_u);

    cudaFuncSetAttribute(attn_kernel, cudaFuncAttributeMaxDynamicSharedMemorySize, ATTN_SMEM);

    const dim3 gemm_grid(4, 2, BC);
    const dim3 gemm3_grid(4, 2, 3 * BC);
    const dim3 conv3_grid(4, FF / 2, 3 * BB);
    const dim3 ln_grid(8, BC);
    const dim3 ln_block(64, 8);
    const dim3 elw_grid(4, FF, BC);

    const size_t WFF = (size_t)CC * FF * FF;
    const size_t KFF = (size_t)CC * CC * 3;

    auto attn_block = [&](int i, const float* qsrc, const float* msrc) {
        gemm_qkv<<<gemm3_grid, 256>>>(qsrc, msrc, Wq + (size_t)i * WFF, Wk + (size_t)i * WFF,
                                      Wv + (size_t)i * WFF, ptq, ptk, ptv);
        convrope3_kernel<<<conv3_grid, 128>>>(ptq, ptk, ptv,
                                              Kq + (size_t)i * KFF, Kk + (size_t)i * KFF, Kv + (size_t)i * KFF,
                                              bq + i * CC, bk + i * CC, bv + i * CC,
                                              pq, pk, pv);
        attn_kernel<<<BC * HH, 512, ATTN_SMEM>>>(pq, pk, pv, ptq);
        gemm_one<<<gemm_grid, 256>>>(ptq, Wo + (size_t)i * WFF, ph, 1);
    };

    // h = x
    copy_kernel<<<2048, 512>>>(ph, x, NTOT);

    // z = LN0(h); h += attn0(z,z); h += attn1(z, skip)
    ln_kernel<<<ln_grid, ln_block>>>(ph, ng + 0 * CC * FF, nb + 0 * CC * FF, pz);
    attn_block(0, pz, pz);
    attn_block(1, pz, skip);

    // conv block
    ln_kernel<<<ln_grid, ln_block>>>(ph, ng + 1 * CC * FF, nb + 1 * CC * FF, pz);
    dwfused_kernel<<<elw_grid, 128>>>(pz, c1aw, c1ab, c1bw, c1bb, pq);
    ln_kernel<<<ln_grid, ln_block>>>(pq, ng + 2 * CC * FF, nb + 2 * CC * FF, pz);
    dwc2_acc_kernel<<<elw_grid, 128>>>(pz, c2w, c2b, ph);

    // attn2 (self) and attn3 (skip)
    ln_kernel<<<ln_grid, ln_block>>>(ph, ng + 3 * CC * FF, nb + 3 * CC * FF, pz);
    attn_block(2, pz, pz);
    ln_kernel<<<ln_grid, ln_block>>>(ph, ng + 4 * CC * FF, nb + 4 * CC * FF, pz);
    attn_block(3, pz, skip);

    // FFN (+ fused concat)
    ln_kernel<<<ln_grid, ln_block>>>(ph, ng + 5 * CC * FF, nb + 5 * CC * FF, pz);
    ffn1_kernel<<<dim3(4, BC), dim3(128, 2)>>>(pz, w3, pu);
    ffn2_out_kernel<<<elw_grid, 128>>>(pu, w4, ph, out);
    xcopy_kernel<<<(unsigned)((NTOT + 255) / 256), 256>>>(x, out);
    (void)in_sizes; (void)n_in; (void)out_size;
}

// round 6
// speedup vs baseline: 1.3766x; 1.0561x over previous
#include <cuda_runtime.h>
#include <cuda_bf16.h>
#include <math.h>
#include <stdint.h>

#define BB 2
#define CC 8
#define FF 256
#define WW 512
#define HH 8
#define HD 32
#define EE 4
#define BC (BB*CC)
#define NTOT ((size_t)BB*CC*FF*WW)

// ---------------- scratch (static device globals; no allocation) ----------------
__device__ float g_h[BB*CC*FF*WW];
__device__ float g_z[BB*CC*FF*WW];
__device__ float g_q[BB*CC*FF*WW];
__device__ float g_k[BB*CC*FF*WW];
__device__ float g_v[BB*CC*FF*WW];
__device__ float g_t[BB*CC*FF*WW];
__device__ float g_t2[BB*CC*FF*WW];
__device__ float g_t3[BB*CC*FF*WW];
__device__ float g_u[BB*CC*EE*WW];

// ---------------- packed f32x2 helpers (sm_100a) ----------------
__device__ __forceinline__ unsigned long long pk2(float lo, float hi) {
    unsigned long long r;
    asm("mov.b64 %0, {%1, %2};" : "=l"(r) : "f"(lo), "f"(hi));
    return r;
}
__device__ __forceinline__ void fma2(unsigned long long& d, unsigned long long a, unsigned long long b) {
    asm("fma.rn.f32x2 %0, %1, %2, %0;" : "+l"(d) : "l"(a), "l"(b));
}
__device__ __forceinline__ void fma2o(unsigned long long& d, unsigned long long b, unsigned long long c) {
    asm("fma.rn.f32x2 %0, %0, %1, %2;" : "+l"(d) : "l"(b), "l"(c));
}
__device__ __forceinline__ float2 up2(unsigned long long v) {
    float2 r;
    asm("mov.b64 {%0, %1}, %2;" : "=f"(r.x), "=f"(r.y) : "l"(v));
    return r;
}

// ---------------- bf16 pack helpers ----------------
__device__ __forceinline__ uint32_t bfpack(float a, float b) {
    uint32_t lo = (uint32_t)__bfloat16_as_ushort(__float2bfloat16(a));
    uint32_t hi = (uint32_t)__bfloat16_as_ushort(__float2bfloat16(b));
    return lo | (hi << 16);
}
__device__ __forceinline__ float bfres(float x) {   // x - bf16(x), exact by Sterbenz
    return x - __bfloat162float(__float2bfloat16(x));
}

// ---------------- warp mma.sync bf16 (sm_80+, valid on plain sm_100) ----------------
__device__ __forceinline__ void mma_bf16(float* d, uint32_t a0, uint32_t a1, uint32_t a2, uint32_t a3,
                                         uint32_t b0, uint32_t b1) {
    asm volatile(
        "mma.sync.aligned.m16n8k16.row.col.f32.bf16.bf16.f32 "
        "{%0,%1,%2,%3}, {%4,%5,%6,%7}, {%8,%9}, {%0,%1,%2,%3};"
        : "+f"(d[0]), "+f"(d[1]), "+f"(d[2]), "+f"(d[3])
        : "r"(a0), "r"(a1), "r"(a2), "r"(a3), "r"(b0), "r"(b1));
}

// ---------------- tensor-core GEMM tile: Out[128g x 128w] = W[128g x 256f] * X[f][w] ----------------
// 3x-bf16 split (hi*hi + hi*lo + lo*hi) for ~16-bit mantissa accuracy.
#define ASTR 18          // uint32 stride per A row (16 k-pairs + pad)
#define BSTR 132         // uint32 stride per B kpair row (128 n + pad)
__device__ __forceinline__ void gemm_tile(const float* __restrict__ A, const float* __restrict__ Bx,
                                          float* __restrict__ Cp, int m0, int n0, bool accum) {
    __shared__ uint32_t Aph[128 * ASTR];
    __shared__ uint32_t Apl[128 * ASTR];
    __shared__ uint32_t Bph[16 * BSTR];
    __shared__ uint32_t Bpl[16 * BSTR];
    int t = threadIdx.x;
    int lane = t & 31, wid = t >> 5;
    int wm = (wid >> 2) * 64;       // warp m offset: 0 or 64
    int wn = (wid & 3) * 32;        // warp n offset: 0,32,64,96
    int g = lane >> 2, tig = lane & 3;

    float acc[4][4][4];
#pragma unroll
    for (int mt = 0; mt < 4; mt++)
#pragma unroll
        for (int nt = 0; nt < 4; nt++)
#pragma unroll
            for (int j = 0; j < 4; j++) acc[mt][nt][j] = 0.f;

    for (int ch = 0; ch < 8; ch++) {
        // ---- A chunk: rows m0..m0+127, cols f = ch*32..+31 (16 floats/thread) ----
        {
            int row = t >> 1;
            int cof = (t & 1) * 16;
            const float* ap = A + (size_t)(m0 + row) * FF + ch * 32 + cof;
            uint32_t* dh = Aph + row * ASTR + (cof >> 1);
            uint32_t* dl = Apl + row * ASTR + (cof >> 1);
#pragma unroll
            for (int j = 0; j < 4; j++) {
                float4 v = *(const float4*)(ap + j * 4);
                dh[j * 2 + 0] = bfpack(v.x, v.y);
                dh[j * 2 + 1] = bfpack(v.z, v.w);
                dl[j * 2 + 0] = bfpack(bfres(v.x), bfres(v.y));
                dl[j * 2 + 1] = bfpack(bfres(v.z), bfres(v.w));
            }
        }
        // ---- B chunk: k = ch*32..+31 packed into 16 kpairs x 128 n (16 floats/thread) ----
        {
            int kp = t >> 4;            // 0..15
            int wq = t & 15;            // 0..15 -> 8 n each
            const float* b0p = Bx + (size_t)(ch * 32 + kp * 2) * WW + n0 + wq * 8;
            const float* b1p = b0p + WW;
            float4 x0a = *(const float4*)(b0p);
            float4 x0b = *(const float4*)(b0p + 4);
            float4 x1a = *(const float4*)(b1p);
            float4 x1b = *(const float4*)(b1p + 4);
            float r0[8] = {x0a.x, x0a.y, x0a.z, x0a.w, x0b.x, x0b.y, x0b.z, x0b.w};
            float r1[8] = {x1a.x, x1a.y, x1a.z, x1a.w, x1b.x, x1b.y, x1b.z, x1b.w};
            uint32_t* dh = Bph + kp * BSTR + wq * 8;
            uint32_t* dl = Bpl + kp * BSTR + wq * 8;
#pragma unroll
            for (int j = 0; j < 8; j++) {
                dh[j] = bfpack(r0[j], r1[j]);
                dl[j] = bfpack(bfres(r0[j]), bfres(r1[j]));
            }
        }
        __syncthreads();

#pragma unroll
        for (int ks = 0; ks < 2; ks++) {
            int kk2 = ks * 8;
            uint32_t bh[4][2], bl[4][2];
#pragma unroll
            for (int nt = 0; nt < 4; nt++) {
                int n = wn + nt * 8 + g;
                bh[nt][0] = Bph[(tig + kk2) * BSTR + n];
                bh[nt][1] = Bph[(tig + 4 + kk2) * BSTR + n];
                bl[nt][0] = Bpl[(tig + kk2) * BSTR + n];
                bl[nt][1] = Bpl[(tig + 4 + kk2) * BSTR + n];
            }
#pragma unroll
            for (int mt = 0; mt < 4; mt++) {
                int r0 = wm + mt * 16 + g;
                uint32_t ah0 = Aph[r0 * ASTR + tig + kk2];
                uint32_t ah1 = Aph[(r0 + 8) * ASTR + tig + kk2];
                uint32_t ah2 = Aph[r0 * ASTR + tig + 4 + kk2];
                uint32_t ah3 = Aph[(r0 + 8) * ASTR + tig + 4 + kk2];
                uint32_t al0 = Apl[r0 * ASTR + tig + kk2];
                uint32_t al1 = Apl[(r0 + 8) * ASTR + tig + kk2];
                uint32_t al2 = Apl[r0 * ASTR + tig + 4 + kk2];
                uint32_t al3 = Apl[(r0 + 8) * ASTR + tig + 4 + kk2];
#pragma unroll
                for (int nt = 0; nt < 4; nt++) {
                    mma_bf16(acc[mt][nt], ah0, ah1, ah2, ah3, bh[nt][0], bh[nt][1]);
                    mma_bf16(acc[mt][nt], ah0, ah1, ah2, ah3, bl[nt][0], bl[nt][1]);
                    mma_bf16(acc[mt][nt], al0, al1, al2, al3, bh[nt][0], bh[nt][1]);
                }
            }
        }
        __syncthreads();
    }

    // ---- epilogue ----
#pragma unroll
    for (int mt = 0; mt < 4; mt++) {
#pragma unroll
        for (int nt = 0; nt < 4; nt++) {
            int row = m0 + wm + mt * 16 + g;
            int col = n0 + wn + nt * 8 + tig * 2;
            float* p0 = Cp + (size_t)row * WW + col;
            float* p1 = Cp + (size_t)(row + 8) * WW + col;
            if (accum) {
                float2 c0 = *(float2*)p0;
                float2 c1 = *(float2*)p1;
                c0.x += acc[mt][nt][0]; c0.y += acc[mt][nt][1];
                c1.x += acc[mt][nt][2]; c1.y += acc[mt][nt][3];
                *(float2*)p0 = c0;
                *(float2*)p1 = c1;
            } else {
                *(float2*)p0 = make_float2(acc[mt][nt][0], acc[mt][nt][1]);
                *(float2*)p1 = make_float2(acc[mt][nt][2], acc[mt][nt][3]);
            }
        }
    }
}

// QKV fused GEMM: grid (4, 2, 3*BC)
__global__ __launch_bounds__(256) void gemm_qkv(const float* __restrict__ qsrc, const float* __restrict__ msrc,
                                                const float* __restrict__ Wq, const float* __restrict__ Wk,
                                                const float* __restrict__ Wv,
                                                float* __restrict__ oq, float* __restrict__ ok_,
                                                float* __restrict__ ov) {
    int z = blockIdx.z;
    int which = z >> 4;
    int bc = z & 15;
    int c = bc & (CC - 1);
    const float* X = (which == 0) ? qsrc : msrc;
    const float* Wm = (which == 0) ? Wq : (which == 1) ? Wk : Wv;
    float* Out = (which == 0) ? oq : (which == 1) ? ok_ : ov;
    gemm_tile(Wm + (size_t)c * FF * FF, X + (size_t)bc * FF * WW,
              Out + (size_t)bc * FF * WW, blockIdx.y * 128, blockIdx.x * 128, false);
}

// single GEMM (O projection, accumulates): grid (4, 2, BC)
__global__ __launch_bounds__(256) void gemm_one(const float* __restrict__ X, const float* __restrict__ Wm,
                                                float* __restrict__ Out) {
    int bc = blockIdx.z;
    int c = bc & (CC - 1);
    gemm_tile(Wm + (size_t)c * FF * FF, X + (size_t)bc * FF * WW,
              Out + (size_t)bc * FF * WW, blockIdx.y * 128, blockIdx.x * 128, true);
}

// ---------------- simple copy ----------------
__global__ void copy_kernel(float* __restrict__ dst, const float* __restrict__ src, size_t n) {
    size_t i = (size_t)blockIdx.x * blockDim.x + threadIdx.x;
    size_t stride = (size_t)gridDim.x * blockDim.x;
    for (; i < n; i += stride) dst[i] = src[i];
}

// ---------------- LayerNorm over features, f-partitioned reduce ----------------
// grid (8, BC), block (64, 8)
__global__ void ln_kernel(const float* __restrict__ src, const float* __restrict__ g,
                          const float* __restrict__ bet, float* __restrict__ dst) {
    int bc = blockIdx.y;
    int c = bc & (CC - 1);
    int tx = threadIdx.x;
    int fy = threadIdx.y;
    int w = blockIdx.x * 64 + tx;
    const float* p = src + (size_t)bc * FF * WW + w;
    float s = 0.f, s2 = 0.f;
#pragma unroll 8
    for (int f = fy * 32; f < fy * 32 + 32; f++) {
        float v = p[(size_t)f * WW];
        s += v; s2 += v * v;
    }
    __shared__ float red[2][8][64];
    red[0][fy][tx] = s;
    red[1][fy][tx] = s2;
    __syncthreads();
    float S = 0.f, S2 = 0.f;
#pragma unroll
    for (int j = 0; j < 8; j++) { S += red[0][j][tx]; S2 += red[1][j][tx]; }
    float m = S * (1.0f / FF);
    float rs = rsqrtf(S2 * (1.0f / FF) - m * m + 1e-5f);
    const float* gc = g + c * FF;
    const float* bb = bet + c * FF;
    float* q = dst + (size_t)bc * FF * WW + w;
#pragma unroll 8
    for (int f = fy * 32; f < fy * 32 + 32; f++) {
        q[(size_t)f * WW] = (p[(size_t)f * WW] - m) * rs * gc[f] + bb[f];
    }
}

// ---------------- fused QKV 1x3 channel-mix conv + RoPE ----------------
// grid (4, FF/2, 3*BB), block 128
__global__ __launch_bounds__(128) void convrope3_kernel(
    const float* __restrict__ tq, const float* __restrict__ tk, const float* __restrict__ tv,
    const float* __restrict__ Kq, const float* __restrict__ Kk, const float* __restrict__ Kv,
    const float* __restrict__ bq, const float* __restrict__ bk, const float* __restrict__ bv,
    float* __restrict__ oq, float* __restrict__ ok_, float* __restrict__ ov) {
    int which = blockIdx.z >> 1;
    int b = blockIdx.z & 1;
    const float* src = (which == 0) ? tq : (which == 1) ? tk : tv;
    const float* Kw  = (which == 0) ? Kq : (which == 1) ? Kk : Kv;
    const float* bias = (which == 0) ? bq : (which == 1) ? bk : bv;
    float* dst = (which == 0) ? oq : (which == 1) ? ok_ : ov;

    __shared__ float4 sK4[64];
    __shared__ float sB2[CC];
    int t = threadIdx.x;
    if (t < 64) sK4[t] = make_float4(Kw[t * 3], Kw[t * 3 + 1], Kw[t * 3 + 2], 0.f);
    if (t < CC) sB2[t] = bias[t];
    __syncthreads();

    int w = blockIdx.x * 128 + t;
    int f0 = blockIdx.y * 2;
    float y0[8], y1[8];
#pragma unroll
    for (int co = 0; co < 8; co++) { y0[co] = sB2[co]; y1[co] = sB2[co]; }
#pragma unroll
    for (int ci = 0; ci < 8; ci++) {
        const float* xp = src + ((size_t)(b * CC + ci) * FF + f0) * WW + w;
        float l0 = (w > 0) ? xp[-1] : 0.f;
        float c0 = xp[0];
        float r0 = (w < WW - 1) ? xp[1] : 0.f;
        float l1 = (w > 0) ? xp[WW - 1] : 0.f;
        float c1 = xp[WW];
        float r1 = (w < WW - 1) ? xp[WW + 1] : 0.f;
#pragma unroll
        for (int co = 0; co < 8; co++) {
            float4 kk = sK4[co * 8 + ci];
            y0[co] += kk.x * l0 + kk.y * c0 + kk.z * r0;
            y1[co] += kk.x * l1 + kk.y * c1 + kk.z * r1;
        }
    }
    int d = f0 & (HD - 1);
    float theta = expf(-(float)d * (9.210340371976184f / (float)HD));
    float sn, cs;
    sincosf((float)w * theta, &sn, &cs);
    bool dorope = (which < 2);
#pragma unroll
    for (int co = 0; co < 8; co++) {
        float* op = dst + ((size_t)(b * CC + co) * FF + f0) * WW + w;
        if (dorope) {
            op[0]  = y0[co] * cs - y1[co] * sn;
            op[WW] = y1[co] * cs + y0[co] * sn;
        } else {
            op[0] = y0[co];
            op[WW] = y1[co];
        }
    }
}

// ---------------- attention: one CTA per (b,c,h), K/V in smem, f32x2 online softmax ----------------
#define ATTN_SMEM (2 * WW * 36 * 4)
__global__ __launch_bounds__(512) void attn_kernel(const float* __restrict__ Q,
                                                   const float* __restrict__ Kb,
                                                   const float* __restrict__ Vb,
                                                   float* __restrict__ Ob) {
    extern __shared__ float smB[];
    float* sk = smB;
    float* sv = smB + WW * 36;
    int bch = blockIdx.x;
    int h = bch & (HH - 1);
    int bc = bch >> 3;
    size_t base = ((size_t)bc * FF + h * HD) * WW;
    const float* gq = Q + base;
    const float* gk = Kb + base;
    const float* gv = Vb + base;
    int n = threadIdx.x;
#pragma unroll
    for (int d = 0; d < HD; d++) {
        sk[n * 36 + d] = gk[(size_t)d * WW + n];
        sv[n * 36 + d] = gv[(size_t)d * WW + n];
    }
    unsigned long long q2[16];
#pragma unroll
    for (int u = 0; u < 16; u++) {
        float lo = gq[(size_t)(2 * u) * WW + n] * 0.0625f;
        float hi = gq[(size_t)(2 * u + 1) * WW + n] * 0.0625f;
        q2[u] = pk2(lo, hi);
    }
    __syncthreads();

    float mrun = -INFINITY, lrun = 0.f;
    unsigned long long a2[16];
#pragma unroll
    for (int u = 0; u < 16; u++) a2[u] = 0ull;

    for (int m = 0; m < WW; m++) {
        const ulonglong2* kp = (const ulonglong2*)(sk + m * 36);
        unsigned long long s0 = 0ull, s1 = 0ull, s2 = 0ull, s3 = 0ull;
#pragma unroll
        for (int i = 0; i < 8; i += 2) {
            ulonglong2 ka = kp[i];
            ulonglong2 kb2 = kp[i + 1];
            fma2(s0, q2[2 * i + 0], ka.x);
            fma2(s1, q2[2 * i + 1], ka.y);
            fma2(s2, q2[2 * i + 2], kb2.x);
            fma2(s3, q2[2 * i + 3], kb2.y);
        }
        float2 r0 = up2(s0), r1 = up2(s1), r2 = up2(s2), r3 = up2(s3);
        float s = ((r0.x + r0.y) + (r1.x + r1.y)) + ((r2.x + r2.y) + (r3.x + r3.y));
        const ulonglong2* vp = (const ulonglong2*)(sv + m * 36);
        if (s > mrun) {
            float corr = __expf(mrun - s);
            mrun = s;
            lrun = lrun * corr + 1.f;
            unsigned long long c2 = pk2(corr, corr);
#pragma unroll
            for (int i = 0; i < 8; i++) {
                ulonglong2 vv = vp[i];
                fma2o(a2[2 * i + 0], c2, vv.x);
                fma2o(a2[2 * i + 1], c2, vv.y);
            }
        } else {
            float p = __expf(s - mrun);
            lrun += p;
            unsigned long long p2 = pk2(p, p);
#pragma unroll
            for (int i = 0; i < 8; i++) {
                ulonglong2 vv = vp[i];
                fma2(a2[2 * i + 0], p2, vv.x);
                fma2(a2[2 * i + 1], p2, vv.y);
            }
        }
    }
    float inv = 1.f / lrun;
    float* op = Ob + base;
#pragma unroll
    for (int u = 0; u < 16; u++) {
        float2 r = up2(a2[u]);
        op[(size_t)(2 * u) * WW + n]     = r.x * inv;
        op[(size_t)(2 * u + 1) * WW + n] = r.y * inv;
    }
}

// ---------------- fused depthwise: out = sqrelu(conv11(z)) + conv7(z) ----------------
__global__ void dwfused_kernel(const float* __restrict__ z, const float* __restrict__ w11,
                               const float* __restrict__ b11, const float* __restrict__ w7,
                               const float* __restrict__ b7, float* __restrict__ out) {
    int w = blockIdx.x * 128 + threadIdx.x;
    int f = blockIdx.y;
    int bc = blockIdx.z;
    int c = bc & 7;
    const float* zp = z + (size_t)bc * FF * WW + w;
    float a = b11[c], b2 = b7[c];
#pragma unroll
    for (int k = 0; k < 11; k++) {
        int fv = f + k - 5;
        if (fv >= 0 && fv < FF) {
            float v = zp[(size_t)fv * WW];
            a += w11[c * 11 + k] * v;
            if (k >= 2 && k <= 8) b2 += w7[c * 7 + (k - 2)] * v;
        }
    }
    float r = fmaxf(a, 0.f);
    out[((size_t)bc * FF + f) * WW + w] = r * r + b2;
}

// ---------------- depthwise 7-tap conv accumulated into h ----------------
__global__ void dwc2_acc_kernel(const float* __restrict__ z, const float* __restrict__ w7,
                                const float* __restrict__ b7, float* __restrict__ h) {
    int w = blockIdx.x * 128 + threadIdx.x;
    int f = blockIdx.y;
    int bc = blockIdx.z;
    int c = bc & 7;
    const float* zp = z + (size_t)bc * FF * WW + w;
    float s = b7[c];
#pragma unroll
    for (int k = 0; k < 7; k++) {
        int fv = f + k - 3;
        if (fv >= 0 && fv < FF) s += w7[c * 7 + k] * zp[(size_t)fv * WW];
    }
    h[((size_t)bc * FF + f) * WW + w] += s;
}

// ---------------- FFN ----------------
__global__ void ffn1_kernel(const float* __restrict__ z, const float* __restrict__ w3,
                            float* __restrict__ u) {
    int tx = threadIdx.x;
    int fy = threadIdx.y;
    int w = blockIdx.x * 128 + tx;
    int bc = blockIdx.y;
    int c = bc & 7;
    const float* zp = z + (size_t)bc * FF * WW + w;
    const float* wp = w3 + (size_t)c * EE * FF;
    float s0 = 0.f, s1 = 0.f, s2 = 0.f, s3 = 0.f;
#pragma unroll 4
    for (int f = fy * 128; f < fy * 128 + 128; f++) {
        float zv = zp[(size_t)f * WW];
        s0 += wp[f] * zv;
        s1 += wp[FF + f] * zv;
        s2 += wp[2 * FF + f] * zv;
        s3 += wp[3 * FF + f] * zv;
    }
    __shared__ float red[4][2][128];
    red[0][fy][tx] = s0; red[1][fy][tx] = s1;
    red[2][fy][tx] = s2; red[3][fy][tx] = s3;
    __syncthreads();
    if (fy == 0) {
        s0 = red[0][0][tx] + red[0][1][tx];
        s1 = red[1][0][tx] + red[1][1][tx];
        s2 = red[2][0][tx] + red[2][1][tx];
        s3 = red[3][0][tx] + red[3][1][tx];
        float* up = u + (size_t)bc * EE * WW + w;
        float r;
        r = fmaxf(s0, 0.f); up[0]      = r * r;
        r = fmaxf(s1, 0.f); up[WW]     = r * r;
        r = fmaxf(s2, 0.f); up[2 * WW] = r * r;
        r = fmaxf(s3, 0.f); up[3 * WW] = r * r;
    }
}

__global__ void ffn2_out_kernel(const float* __restrict__ u, const float* __restrict__ w4,
                                const float* __restrict__ h, float* __restrict__ out) {
    int w = blockIdx.x * 128 + threadIdx.x;
    int f = blockIdx.y;
    int bc = blockIdx.z;
    int c = bc & 7;
    int b = bc >> 3;
    const float* up = u + (size_t)bc * EE * WW + w;
    const float* wp = w4 + ((size_t)c * FF + f) * EE;
    float s = wp[0] * up[0] + wp[1] * up[WW] + wp[2] * up[2 * WW] + wp[3] * up[3 * WW];
    out[(((size_t)b * 2 * CC + CC + c) * FF + f) * WW + w] =
        h[((size_t)bc * FF + f) * WW + w] + s;
}

__global__ void xcopy_kernel(const float* __restrict__ x, float* __restrict__ out) {
    size_t i = (size_t)blockIdx.x * blockDim.x + threadIdx.x;
    if (i >= NTOT) return;
    size_t chunk = (size_t)CC * FF * WW;
    size_t b = i / chunk;
    size_t inner = i % chunk;
    out[b * 2 * chunk + inner] = x[i];
}

// ================================================================================
extern "C" void kernel_launch(void* const* d_in, const int* in_sizes, int n_in,
                              void* d_out, int out_size) {
    const float* x    = (const float*)d_in[0];
    const float* skip = (const float*)d_in[1];
    const float* Wq   = (const float*)d_in[2];
    const float* Kq   = (const float*)d_in[3];
    const float* bq   = (const float*)d_in[4];
    const float* Wk   = (const float*)d_in[5];
    const float* Kk   = (const float*)d_in[6];
    const float* bk   = (const float*)d_in[7];
    const float* Wv   = (const float*)d_in[8];
    const float* Kv   = (const float*)d_in[9];
    const float* bv   = (const float*)d_in[10];
    const float* Wo   = (const float*)d_in[11];
    const float* ng   = (const float*)d_in[12];
    const float* nb   = (const float*)d_in[13];
    const float* c1aw = (const float*)d_in[14];
    const float* c1ab = (const float*)d_in[15];
    const float* c1bw = (const float*)d_in[16];
    const float* c1bb = (const float*)d_in[17];
    const float* c2w  = (const float*)d_in[18];
    const float* c2b  = (const float*)d_in[19];
    const float* w3   = (const float*)d_in[20];
    const float* w4   = (const float*)d_in[21];
    float* out = (float*)d_out;

    float *ph, *pz, *pq, *pk, *pv, *ptq, *ptk, *ptv, *pu;
    cudaGetSymbolAddress((void**)&ph, g_h);
    cudaGetSymbolAddress((void**)&pz, g_z);
    cudaGetSymbolAddress((void**)&pq, g_q);
    cudaGetSymbolAddress((void**)&pk, g_k);
    cudaGetSymbolAddress((void**)&pv, g_v);
    cudaGetSymbolAddress((void**)&ptq, g_t);
    cudaGetSymbolAddress((void**)&ptk, g_t2);
    cudaGetSymbolAddress((void**)&ptv, g_t3);
    cudaGetSymbolAddress((void**)&pu, g_u);

    cudaFuncSetAttribute(attn_kernel, cudaFuncAttributeMaxDynamicSharedMemorySize, ATTN_SMEM);

    const dim3 gemm_grid(4, 2, BC);
    const dim3 gemm3_grid(4, 2, 3 * BC);
    const dim3 conv3_grid(4, FF / 2, 3 * BB);
    const dim3 ln_grid(8, BC);
    const dim3 ln_block(64, 8);
    const dim3 elw_grid(4, FF, BC);

    const size_t WFF = (size_t)CC * FF * FF;
    const size_t KFF = (size_t)CC * CC * 3;

    auto attn_block = [&](int i, const float* qsrc, const float* msrc) {
        gemm_qkv<<<gemm3_grid, 256>>>(qsrc, msrc, Wq + (size_t)i * WFF, Wk + (size_t)i * WFF,
                                      Wv + (size_t)i * WFF, ptq, ptk, ptv);
        convrope3_kernel<<<conv3_grid, 128>>>(ptq, ptk, ptv,
                                              Kq + (size_t)i * KFF, Kk + (size_t)i * KFF, Kv + (size_t)i * KFF,
                                              bq + i * CC, bk + i * CC, bv + i * CC,
                                              pq, pk, pv);
        attn_kernel<<<BC * HH, 512, ATTN_SMEM>>>(pq, pk, pv, ptq);
        gemm_one<<<gemm_grid, 256>>>(ptq, Wo + (size_t)i * WFF, ph);
    };

    // h = x
    copy_kernel<<<2048, 512>>>(ph, x, NTOT);

    // z = LN0(h); h += attn0(z,z); h += attn1(z, skip)
    ln_kernel<<<ln_grid, ln_block>>>(ph, ng + 0 * CC * FF, nb + 0 * CC * FF, pz);
    attn_block(0, pz, pz);
    attn_block(1, pz, skip);

    // conv block
    ln_kernel<<<ln_grid, ln_block>>>(ph, ng + 1 * CC * FF, nb + 1 * CC * FF, pz);
    dwfused_kernel<<<elw_grid, 128>>>(pz, c1aw, c1ab, c1bw, c1bb, pq);
    ln_kernel<<<ln_grid, ln_block>>>(pq, ng + 2 * CC * FF, nb + 2 * CC * FF, pz);
    dwc2_acc_kernel<<<elw_grid, 128>>>(pz, c2w, c2b, ph);

    // attn2 (self) and attn3 (skip)
    ln_kernel<<<ln_grid, ln_block>>>(ph, ng + 3 * CC * FF, nb + 3 * CC * FF, pz);
    attn_block(2, pz, pz);
    ln_kernel<<<ln_grid, ln_block>>>(ph, ng + 4 * CC * FF, nb + 4 * CC * FF, pz);
    attn_block(3, pz, skip);

    // FFN (+ fused concat)
    ln_kernel<<<ln_grid, ln_block>>>(ph, ng + 5 * CC * FF, nb + 5 * CC * FF, pz);
    ffn1_kernel<<<dim3(4, BC), dim3(128, 2)>>>(pz, w3, pu);
    ffn2_out_kernel<<<elw_grid, 128>>>(pu, w4, ph, out);
    xcopy_kernel<<<(unsigned)((NTOT + 255) / 256), 256>>>(x, out);
    (void)in_sizes; (void)n_in; (void)out_size;
}

// round 7
// speedup vs baseline: 2.1582x; 1.5678x over previous
#include <cuda_runtime.h>
#include <cuda_bf16.h>
#include <math.h>
#include <stdint.h>

#define BB 2
#define CC 8
#define FF 256
#define WW 512
#define HH 8
#define HD 32
#define EE 4
#define BC (BB*CC)
#define NTOT ((size_t)BB*CC*FF*WW)

// ---------------- scratch (static device globals; no allocation) ----------------
__device__ float g_h[BB*CC*FF*WW];
__device__ float g_z[BB*CC*FF*WW];
__device__ float g_q[BB*CC*FF*WW];
__device__ float g_k[BB*CC*FF*WW];
__device__ float g_v[BB*CC*FF*WW];
__device__ float g_t[BB*CC*FF*WW];
__device__ float g_t2[BB*CC*FF*WW];
__device__ float g_t3[BB*CC*FF*WW];
__device__ float g_u[BB*CC*EE*WW];

// ---------------- bf16 pack helpers ----------------
__device__ __forceinline__ uint32_t bfpack(float a, float b) {
    uint32_t lo = (uint32_t)__bfloat16_as_ushort(__float2bfloat16(a));
    uint32_t hi = (uint32_t)__bfloat16_as_ushort(__float2bfloat16(b));
    return lo | (hi << 16);
}
__device__ __forceinline__ float bfres(float x) {   // x - bf16(x)
    return x - __bfloat162float(__float2bfloat16(x));
}

// ---------------- warp mma.sync bf16 (sm_80+, valid on plain sm_100) ----------------
__device__ __forceinline__ void mma_bf16(float* d, uint32_t a0, uint32_t a1, uint32_t a2, uint32_t a3,
                                         uint32_t b0, uint32_t b1) {
    asm volatile(
        "mma.sync.aligned.m16n8k16.row.col.f32.bf16.bf16.f32 "
        "{%0,%1,%2,%3}, {%4,%5,%6,%7}, {%8,%9}, {%0,%1,%2,%3};"
        : "+f"(d[0]), "+f"(d[1]), "+f"(d[2]), "+f"(d[3])
        : "r"(a0), "r"(a1), "r"(a2), "r"(a3), "r"(b0), "r"(b1));
}

// ---------------- tensor-core GEMM tile: Out[128g x 128w] = W[128g x 256f] * X[f][w] ----------------
#define ASTR 18
#define BSTR 132
__device__ __forceinline__ void gemm_tile(const float* __restrict__ A, const float* __restrict__ Bx,
                                          float* __restrict__ Cp, int m0, int n0, bool accum) {
    __shared__ uint32_t Aph[128 * ASTR];
    __shared__ uint32_t Apl[128 * ASTR];
    __shared__ uint32_t Bph[16 * BSTR];
    __shared__ uint32_t Bpl[16 * BSTR];
    int t = threadIdx.x;
    int lane = t & 31, wid = t >> 5;
    int wm = (wid >> 2) * 64;
    int wn = (wid & 3) * 32;
    int g = lane >> 2, tig = lane & 3;

    float acc[4][4][4];
#pragma unroll
    for (int mt = 0; mt < 4; mt++)
#pragma unroll
        for (int nt = 0; nt < 4; nt++)
#pragma unroll
            for (int j = 0; j < 4; j++) acc[mt][nt][j] = 0.f;

    for (int ch = 0; ch < 8; ch++) {
        {
            int row = t >> 1;
            int cof = (t & 1) * 16;
            const float* ap = A + (size_t)(m0 + row) * FF + ch * 32 + cof;
            uint32_t* dh = Aph + row * ASTR + (cof >> 1);
            uint32_t* dl = Apl + row * ASTR + (cof >> 1);
#pragma unroll
            for (int j = 0; j < 4; j++) {
                float4 v = *(const float4*)(ap + j * 4);
                dh[j * 2 + 0] = bfpack(v.x, v.y);
                dh[j * 2 + 1] = bfpack(v.z, v.w);
                dl[j * 2 + 0] = bfpack(bfres(v.x), bfres(v.y));
                dl[j * 2 + 1] = bfpack(bfres(v.z), bfres(v.w));
            }
        }
        {
            int kp = t >> 4;
            int wq = t & 15;
            const float* b0p = Bx + (size_t)(ch * 32 + kp * 2) * WW + n0 + wq * 8;
            const float* b1p = b0p + WW;
            float4 x0a = *(const float4*)(b0p);
            float4 x0b = *(const float4*)(b0p + 4);
            float4 x1a = *(const float4*)(b1p);
            float4 x1b = *(const float4*)(b1p + 4);
            float r0[8] = {x0a.x, x0a.y, x0a.z, x0a.w, x0b.x, x0b.y, x0b.z, x0b.w};
            float r1[8] = {x1a.x, x1a.y, x1a.z, x1a.w, x1b.x, x1b.y, x1b.z, x1b.w};
            uint32_t* dh = Bph + kp * BSTR + wq * 8;
            uint32_t* dl = Bpl + kp * BSTR + wq * 8;
#pragma unroll
            for (int j = 0; j < 8; j++) {
                dh[j] = bfpack(r0[j], r1[j]);
                dl[j] = bfpack(bfres(r0[j]), bfres(r1[j]));
            }
        }
        __syncthreads();

#pragma unroll
        for (int ks = 0; ks < 2; ks++) {
            int kk2 = ks * 8;
            uint32_t bh[4][2], bl[4][2];
#pragma unroll
            for (int nt = 0; nt < 4; nt++) {
                int n = wn + nt * 8 + g;
                bh[nt][0] = Bph[(tig + kk2) * BSTR + n];
                bh[nt][1] = Bph[(tig + 4 + kk2) * BSTR + n];
                bl[nt][0] = Bpl[(tig + kk2) * BSTR + n];
                bl[nt][1] = Bpl[(tig + 4 + kk2) * BSTR + n];
            }
#pragma unroll
            for (int mt = 0; mt < 4; mt++) {
                int r0 = wm + mt * 16 + g;
                uint32_t ah0 = Aph[r0 * ASTR + tig + kk2];
                uint32_t ah1 = Aph[(r0 + 8) * ASTR + tig + kk2];
                uint32_t ah2 = Aph[r0 * ASTR + tig + 4 + kk2];
                uint32_t ah3 = Aph[(r0 + 8) * ASTR + tig + 4 + kk2];
                uint32_t al0 = Apl[r0 * ASTR + tig + kk2];
                uint32_t al1 = Apl[(r0 + 8) * ASTR + tig + kk2];
                uint32_t al2 = Apl[r0 * ASTR + tig + 4 + kk2];
                uint32_t al3 = Apl[(r0 + 8) * ASTR + tig + 4 + kk2];
#pragma unroll
                for (int nt = 0; nt < 4; nt++) {
                    mma_bf16(acc[mt][nt], ah0, ah1, ah2, ah3, bh[nt][0], bh[nt][1]);
                    mma_bf16(acc[mt][nt], ah0, ah1, ah2, ah3, bl[nt][0], bl[nt][1]);
                    mma_bf16(acc[mt][nt], al0, al1, al2, al3, bh[nt][0], bh[nt][1]);
                }
            }
        }
        __syncthreads();
    }

#pragma unroll
    for (int mt = 0; mt < 4; mt++) {
#pragma unroll
        for (int nt = 0; nt < 4; nt++) {
            int row = m0 + wm + mt * 16 + g;
            int col = n0 + wn + nt * 8 + tig * 2;
            float* p0 = Cp + (size_t)row * WW + col;
            float* p1 = Cp + (size_t)(row + 8) * WW + col;
            if (accum) {
                float2 c0 = *(float2*)p0;
                float2 c1 = *(float2*)p1;
                c0.x += acc[mt][nt][0]; c0.y += acc[mt][nt][1];
                c1.x += acc[mt][nt][2]; c1.y += acc[mt][nt][3];
                *(float2*)p0 = c0;
                *(float2*)p1 = c1;
            } else {
                *(float2*)p0 = make_float2(acc[mt][nt][0], acc[mt][nt][1]);
                *(float2*)p1 = make_float2(acc[mt][nt][2], acc[mt][nt][3]);
            }
        }
    }
}

__global__ __launch_bounds__(256) void gemm_qkv(const float* __restrict__ qsrc, const float* __restrict__ msrc,
                                                const float* __restrict__ Wq, const float* __restrict__ Wk,
                                                const float* __restrict__ Wv,
                                                float* __restrict__ oq, float* __restrict__ ok_,
                                                float* __restrict__ ov) {
    int z = blockIdx.z;
    int which = z >> 4;
    int bc = z & 15;
    int c = bc & (CC - 1);
    const float* X = (which == 0) ? qsrc : msrc;
    const float* Wm = (which == 0) ? Wq : (which == 1) ? Wk : Wv;
    float* Out = (which == 0) ? oq : (which == 1) ? ok_ : ov;
    gemm_tile(Wm + (size_t)c * FF * FF, X + (size_t)bc * FF * WW,
              Out + (size_t)bc * FF * WW, blockIdx.y * 128, blockIdx.x * 128, false);
}

__global__ __launch_bounds__(256) void gemm_one(const float* __restrict__ X, const float* __restrict__ Wm,
                                                float* __restrict__ Out) {
    int bc = blockIdx.z;
    int c = bc & (CC - 1);
    gemm_tile(Wm + (size_t)c * FF * FF, X + (size_t)bc * FF * WW,
              Out + (size_t)bc * FF * WW, blockIdx.y * 128, blockIdx.x * 128, true);
}

// ---------------- flash-attention via mma.sync ----------------
// grid (4 qtiles, 128 heads), 256 threads. Q tile 128x32 hi/lo, K tiles hi/lo, V hi only.
#define AT_QSTR 17
#define AT_KSTR 136
#define AT_VSTR 40
__global__ __launch_bounds__(256, 2) void attn_mma_kernel(const float* __restrict__ Q,
                                                          const float* __restrict__ Kb,
                                                          const float* __restrict__ Vb,
                                                          float* __restrict__ Ob) {
    __shared__ uint32_t Qh[128 * AT_QSTR];
    __shared__ uint32_t Ql[128 * AT_QSTR];
    __shared__ uint32_t Kh[16 * AT_KSTR];
    __shared__ uint32_t Kl[16 * AT_KSTR];
    __shared__ uint32_t Vh[64 * AT_VSTR];
    int t = threadIdx.x;
    int lane = t & 31, wid = t >> 5;
    int g = lane >> 2, tig = lane & 3;
    int qt = blockIdx.x;
    int bch = blockIdx.y;
    int h = bch & (HH - 1);
    int bc = bch >> 3;
    size_t base = ((size_t)bc * FF + h * HD) * WW;
    const float* gq = Q + base + qt * 128;
    const float* gk = Kb + base;
    const float* gv = Vb + base;

    // ---- Q tile load + hi/lo pack (scale 1/16 folded before split) ----
    {
        int q = t & 127;
        int dp0 = (t >> 7) * 8;
#pragma unroll
        for (int j = 0; j < 8; j++) {
            int dp = dp0 + j;
            float v0 = gq[(size_t)(2 * dp) * WW + q] * 0.0625f;
            float v1 = gq[(size_t)(2 * dp + 1) * WW + q] * 0.0625f;
            Qh[q * AT_QSTR + dp] = bfpack(v0, v1);
            Ql[q * AT_QSTR + dp] = bfpack(bfres(v0), bfres(v1));
        }
    }
    __syncthreads();

    // warp's Q fragments (rows wid*16 .. +16), kept in regs
    uint32_t qah[2][4], qal[2][4];
    int qr = wid * 16;
#pragma unroll
    for (int s = 0; s < 2; s++) {
        qah[s][0] = Qh[(qr + g) * AT_QSTR + s * 8 + tig];
        qah[s][1] = Qh[(qr + g + 8) * AT_QSTR + s * 8 + tig];
        qah[s][2] = Qh[(qr + g) * AT_QSTR + s * 8 + tig + 4];
        qah[s][3] = Qh[(qr + g + 8) * AT_QSTR + s * 8 + tig + 4];
        qal[s][0] = Ql[(qr + g) * AT_QSTR + s * 8 + tig];
        qal[s][1] = Ql[(qr + g + 8) * AT_QSTR + s * 8 + tig];
        qal[s][2] = Ql[(qr + g) * AT_QSTR + s * 8 + tig + 4];
        qal[s][3] = Ql[(qr + g + 8) * AT_QSTR + s * 8 + tig + 4];
    }

    float M0 = -1e30f, M1 = -1e30f, L0 = 0.f, L1 = 0.f;
    float oac[4][4];
#pragma unroll
    for (int i = 0; i < 4; i++)
#pragma unroll
        for (int j = 0; j < 4; j++) oac[i][j] = 0.f;

    for (int kt = 0; kt < 4; kt++) {
        __syncthreads();
        // ---- K tile: Kp[dp][key] hi/lo ----
        {
            int dp = t >> 4;
            int kq = (t & 15) * 8;
            const float* r0 = gk + (size_t)(2 * dp) * WW + kt * 128 + kq;
            const float* r1 = r0 + WW;
            float4 a0 = *(const float4*)(r0);
            float4 a1 = *(const float4*)(r0 + 4);
            float4 b0 = *(const float4*)(r1);
            float4 b1 = *(const float4*)(r1 + 4);
            float ra[8] = {a0.x, a0.y, a0.z, a0.w, a1.x, a1.y, a1.z, a1.w};
            float rb[8] = {b0.x, b0.y, b0.z, b0.w, b1.x, b1.y, b1.z, b1.w};
            uint32_t* dh = Kh + dp * AT_KSTR + kq;
            uint32_t* dl = Kl + dp * AT_KSTR + kq;
#pragma unroll
            for (int j = 0; j < 8; j++) {
                dh[j] = bfpack(ra[j], rb[j]);
                dl[j] = bfpack(bfres(ra[j]), bfres(rb[j]));
            }
        }
        // ---- V tile: Vp[kp][d] hi only ----
        {
            int d = t & 31;
            int kp0 = (t >> 5) * 8;
            const float* r = gv + (size_t)d * WW + kt * 128 + kp0 * 2;
            float4 x0 = *(const float4*)(r);
            float4 x1 = *(const float4*)(r + 4);
            float4 x2 = *(const float4*)(r + 8);
            float4 x3 = *(const float4*)(r + 12);
            Vh[(kp0 + 0) * AT_VSTR + d] = bfpack(x0.x, x0.y);
            Vh[(kp0 + 1) * AT_VSTR + d] = bfpack(x0.z, x0.w);
            Vh[(kp0 + 2) * AT_VSTR + d] = bfpack(x1.x, x1.y);
            Vh[(kp0 + 3) * AT_VSTR + d] = bfpack(x1.z, x1.w);
            Vh[(kp0 + 4) * AT_VSTR + d] = bfpack(x2.x, x2.y);
            Vh[(kp0 + 5) * AT_VSTR + d] = bfpack(x2.z, x2.w);
            Vh[(kp0 + 6) * AT_VSTR + d] = bfpack(x3.x, x3.y);
            Vh[(kp0 + 7) * AT_VSTR + d] = bfpack(x3.z, x3.w);
        }
        __syncthreads();

        // ---- S = Q K^T (hi*hi + hi*lo + lo*hi) ----
        float sa[16][4];
#pragma unroll
        for (int nt = 0; nt < 16; nt++) {
            sa[nt][0] = 0.f; sa[nt][1] = 0.f; sa[nt][2] = 0.f; sa[nt][3] = 0.f;
        }
#pragma unroll
        for (int nt = 0; nt < 16; nt++) {
            int n = nt * 8 + g;
            uint32_t kh0 = Kh[(tig) * AT_KSTR + n];
            uint32_t kh1 = Kh[(tig + 4) * AT_KSTR + n];
            uint32_t kh2 = Kh[(tig + 8) * AT_KSTR + n];
            uint32_t kh3 = Kh[(tig + 12) * AT_KSTR + n];
            uint32_t kl0 = Kl[(tig) * AT_KSTR + n];
            uint32_t kl1 = Kl[(tig + 4) * AT_KSTR + n];
            uint32_t kl2 = Kl[(tig + 8) * AT_KSTR + n];
            uint32_t kl3 = Kl[(tig + 12) * AT_KSTR + n];
            mma_bf16(sa[nt], qah[0][0], qah[0][1], qah[0][2], qah[0][3], kh0, kh1);
            mma_bf16(sa[nt], qah[1][0], qah[1][1], qah[1][2], qah[1][3], kh2, kh3);
            mma_bf16(sa[nt], qah[0][0], qah[0][1], qah[0][2], qah[0][3], kl0, kl1);
            mma_bf16(sa[nt], qah[1][0], qah[1][1], qah[1][2], qah[1][3], kl2, kl3);
            mma_bf16(sa[nt], qal[0][0], qal[0][1], qal[0][2], qal[0][3], kh0, kh1);
            mma_bf16(sa[nt], qal[1][0], qal[1][1], qal[1][2], qal[1][3], kh2, kh3);
        }

        // ---- online softmax (rows g and g+8) ----
        float mx0 = -1e30f, mx1 = -1e30f;
#pragma unroll
        for (int nt = 0; nt < 16; nt++) {
            mx0 = fmaxf(mx0, fmaxf(sa[nt][0], sa[nt][1]));
            mx1 = fmaxf(mx1, fmaxf(sa[nt][2], sa[nt][3]));
        }
        mx0 = fmaxf(mx0, __shfl_xor_sync(0xFFFFFFFFu, mx0, 1));
        mx0 = fmaxf(mx0, __shfl_xor_sync(0xFFFFFFFFu, mx0, 2));
        mx1 = fmaxf(mx1, __shfl_xor_sync(0xFFFFFFFFu, mx1, 1));
        mx1 = fmaxf(mx1, __shfl_xor_sync(0xFFFFFFFFu, mx1, 2));
        float Mn0 = fmaxf(M0, mx0), Mn1 = fmaxf(M1, mx1);
        float c0 = __expf(M0 - Mn0), c1 = __expf(M1 - Mn1);
        float ps0 = 0.f, ps1 = 0.f;
#pragma unroll
        for (int nt = 0; nt < 16; nt++) {
            sa[nt][0] = __expf(sa[nt][0] - Mn0);
            sa[nt][1] = __expf(sa[nt][1] - Mn0);
            sa[nt][2] = __expf(sa[nt][2] - Mn1);
            sa[nt][3] = __expf(sa[nt][3] - Mn1);
            ps0 += sa[nt][0] + sa[nt][1];
            ps1 += sa[nt][2] + sa[nt][3];
        }
        ps0 += __shfl_xor_sync(0xFFFFFFFFu, ps0, 1);
        ps0 += __shfl_xor_sync(0xFFFFFFFFu, ps0, 2);
        ps1 += __shfl_xor_sync(0xFFFFFFFFu, ps1, 1);
        ps1 += __shfl_xor_sync(0xFFFFFFFFu, ps1, 2);
        L0 = L0 * c0 + ps0;
        L1 = L1 * c1 + ps1;
        M0 = Mn0; M1 = Mn1;
#pragma unroll
        for (int nt4 = 0; nt4 < 4; nt4++) {
            oac[nt4][0] *= c0; oac[nt4][1] *= c0;
            oac[nt4][2] *= c1; oac[nt4][3] *= c1;
        }

        // ---- O += P V (P packed from S fragments; single bf16) ----
#pragma unroll
        for (int s8 = 0; s8 < 8; s8++) {
            uint32_t pa0 = bfpack(sa[2 * s8][0], sa[2 * s8][1]);
            uint32_t pa1 = bfpack(sa[2 * s8][2], sa[2 * s8][3]);
            uint32_t pa2 = bfpack(sa[2 * s8 + 1][0], sa[2 * s8 + 1][1]);
            uint32_t pa3 = bfpack(sa[2 * s8 + 1][2], sa[2 * s8 + 1][3]);
#pragma unroll
            for (int nt4 = 0; nt4 < 4; nt4++) {
                int d = nt4 * 8 + g;
                uint32_t vb0 = Vh[(s8 * 8 + tig) * AT_VSTR + d];
                uint32_t vb1 = Vh[(s8 * 8 + tig + 4) * AT_VSTR + d];
                mma_bf16(oac[nt4], pa0, pa1, pa2, pa3, vb0, vb1);
            }
        }
    }

    // ---- normalize + store: rows=q, cols=d; out layout [d][w=q] ----
    float il0 = 1.f / L0, il1 = 1.f / L1;
    int q0 = qt * 128 + qr + g;
#pragma unroll
    for (int nt4 = 0; nt4 < 4; nt4++) {
        int d = nt4 * 8 + 2 * tig;
        float* o0 = Ob + base + (size_t)d * WW;
        float* o1 = Ob + base + (size_t)(d + 1) * WW;
        o0[q0] = oac[nt4][0] * il0;
        o1[q0] = oac[nt4][1] * il0;
        o0[q0 + 8] = oac[nt4][2] * il1;
        o1[q0 + 8] = oac[nt4][3] * il1;
    }
}

// ---------------- simple copy ----------------
__global__ void copy_kernel(float* __restrict__ dst, const float* __restrict__ src, size_t n) {
    size_t i = (size_t)blockIdx.x * blockDim.x + threadIdx.x;
    size_t stride = (size_t)gridDim.x * blockDim.x;
    for (; i < n; i += stride) dst[i] = src[i];
}

// ---------------- LayerNorm over features ----------------
__global__ void ln_kernel(const float* __restrict__ src, const float* __restrict__ g,
                          const float* __restrict__ bet, float* __restrict__ dst) {
    int bc = blockIdx.y;
    int c = bc & (CC - 1);
    int tx = threadIdx.x;
    int fy = threadIdx.y;
    int w = blockIdx.x * 64 + tx;
    const float* p = src + (size_t)bc * FF * WW + w;
    float s = 0.f, s2 = 0.f;
#pragma unroll 8
    for (int f = fy * 32; f < fy * 32 + 32; f++) {
        float v = p[(size_t)f * WW];
        s += v; s2 += v * v;
    }
    __shared__ float red[2][8][64];
    red[0][fy][tx] = s;
    red[1][fy][tx] = s2;
    __syncthreads();
    float S = 0.f, S2 = 0.f;
#pragma unroll
    for (int j = 0; j < 8; j++) { S += red[0][j][tx]; S2 += red[1][j][tx]; }
    float m = S * (1.0f / FF);
    float rs = rsqrtf(S2 * (1.0f / FF) - m * m + 1e-5f);
    const float* gc = g + c * FF;
    const float* bb = bet + c * FF;
    float* q = dst + (size_t)bc * FF * WW + w;
#pragma unroll 8
    for (int f = fy * 32; f < fy * 32 + 32; f++) {
        q[(size_t)f * WW] = (p[(size_t)f * WW] - m) * rs * gc[f] + bb[f];
    }
}

// ---------------- fused QKV 1x3 channel-mix conv + RoPE ----------------
__global__ __launch_bounds__(128) void convrope3_kernel(
    const float* __restrict__ tq, const float* __restrict__ tk, const float* __restrict__ tv,
    const float* __restrict__ Kq, const float* __restrict__ Kk, const float* __restrict__ Kv,
    const float* __restrict__ bq, const float* __restrict__ bk, const float* __restrict__ bv,
    float* __restrict__ oq, float* __restrict__ ok_, float* __restrict__ ov) {
    int which = blockIdx.z >> 1;
    int b = blockIdx.z & 1;
    const float* src = (which == 0) ? tq : (which == 1) ? tk : tv;
    const float* Kw  = (which == 0) ? Kq : (which == 1) ? Kk : Kv;
    const float* bias = (which == 0) ? bq : (which == 1) ? bk : bv;
    float* dst = (which == 0) ? oq : (which == 1) ? ok_ : ov;

    __shared__ float4 sK4[64];
    __shared__ float sB2[CC];
    int t = threadIdx.x;
    if (t < 64) sK4[t] = make_float4(Kw[t * 3], Kw[t * 3 + 1], Kw[t * 3 + 2], 0.f);
    if (t < CC) sB2[t] = bias[t];
    __syncthreads();

    int w = blockIdx.x * 128 + t;
    int f0 = blockIdx.y * 2;
    float y0[8], y1[8];
#pragma unroll
    for (int co = 0; co < 8; co++) { y0[co] = sB2[co]; y1[co] = sB2[co]; }
#pragma unroll
    for (int ci = 0; ci < 8; ci++) {
        const float* xp = src + ((size_t)(b * CC + ci) * FF + f0) * WW + w;
        float l0 = (w > 0) ? xp[-1] : 0.f;
        float c0 = xp[0];
        float r0 = (w < WW - 1) ? xp[1] : 0.f;
        float l1 = (w > 0) ? xp[WW - 1] : 0.f;
        float c1 = xp[WW];
        float r1 = (w < WW - 1) ? xp[WW + 1] : 0.f;
#pragma unroll
        for (int co = 0; co < 8; co++) {
            float4 kk = sK4[co * 8 + ci];
            y0[co] += kk.x * l0 + kk.y * c0 + kk.z * r0;
            y1[co] += kk.x * l1 + kk.y * c1 + kk.z * r1;
        }
    }
    int d = f0 & (HD - 1);
    float theta = expf(-(float)d * (9.210340371976184f / (float)HD));
    float sn, cs;
    sincosf((float)w * theta, &sn, &cs);
    bool dorope = (which < 2);
#pragma unroll
    for (int co = 0; co < 8; co++) {
        float* op = dst + ((size_t)(b * CC + co) * FF + f0) * WW + w;
        if (dorope) {
            op[0]  = y0[co] * cs - y1[co] * sn;
            op[WW] = y1[co] * cs + y0[co] * sn;
        } else {
            op[0] = y0[co];
            op[WW] = y1[co];
        }
    }
}

// ---------------- fused depthwise: out = sqrelu(conv11(z)) + conv7(z) ----------------
__global__ void dwfused_kernel(const float* __restrict__ z, const float* __restrict__ w11,
                               const float* __restrict__ b11, const float* __restrict__ w7,
                               const float* __restrict__ b7, float* __restrict__ out) {
    int w = blockIdx.x * 128 + threadIdx.x;
    int f = blockIdx.y;
    int bc = blockIdx.z;
    int c = bc & 7;
    const float* zp = z + (size_t)bc * FF * WW + w;
    float a = b11[c], b2 = b7[c];
#pragma unroll
    for (int k = 0; k < 11; k++) {
        int fv = f + k - 5;
        if (fv >= 0 && fv < FF) {
            float v = zp[(size_t)fv * WW];
            a += w11[c * 11 + k] * v;
            if (k >= 2 && k <= 8) b2 += w7[c * 7 + (k - 2)] * v;
        }
    }
    float r = fmaxf(a, 0.f);
    out[((size_t)bc * FF + f) * WW + w] = r * r + b2;
}

// ---------------- depthwise 7-tap conv accumulated into h ----------------
__global__ void dwc2_acc_kernel(const float* __restrict__ z, const float* __restrict__ w7,
                                const float* __restrict__ b7, float* __restrict__ h) {
    int w = blockIdx.x * 128 + threadIdx.x;
    int f = blockIdx.y;
    int bc = blockIdx.z;
    int c = bc & 7;
    const float* zp = z + (size_t)bc * FF * WW + w;
    float s = b7[c];
#pragma unroll
    for (int k = 0; k < 7; k++) {
        int fv = f + k - 3;
        if (fv >= 0 && fv < FF) s += w7[c * 7 + k] * zp[(size_t)fv * WW];
    }
    h[((size_t)bc * FF + f) * WW + w] += s;
}

// ---------------- FFN ----------------
__global__ void ffn1_kernel(const float* __restrict__ z, const float* __restrict__ w3,
                            float* __restrict__ u) {
    int tx = threadIdx.x;
    int fy = threadIdx.y;
    int w = blockIdx.x * 128 + tx;
    int bc = blockIdx.y;
    int c = bc & 7;
    const float* zp = z + (size_t)bc * FF * WW + w;
    const float* wp = w3 + (size_t)c * EE * FF;
    float s0 = 0.f, s1 = 0.f, s2 = 0.f, s3 = 0.f;
#pragma unroll 4
    for (int f = fy * 128; f < fy * 128 + 128; f++) {
        float zv = zp[(size_t)f * WW];
        s0 += wp[f] * zv;
        s1 += wp[FF + f] * zv;
        s2 += wp[2 * FF + f] * zv;
        s3 += wp[3 * FF + f] * zv;
    }
    __shared__ float red[4][2][128];
    red[0][fy][tx] = s0; red[1][fy][tx] = s1;
    red[2][fy][tx] = s2; red[3][fy][tx] = s3;
    __syncthreads();
    if (fy == 0) {
        s0 = red[0][0][tx] + red[0][1][tx];
        s1 = red[1][0][tx] + red[1][1][tx];
        s2 = red[2][0][tx] + red[2][1][tx];
        s3 = red[3][0][tx] + red[3][1][tx];
        float* up = u + (size_t)bc * EE * WW + w;
        float r;
        r = fmaxf(s0, 0.f); up[0]      = r * r;
        r = fmaxf(s1, 0.f); up[WW]     = r * r;
        r = fmaxf(s2, 0.f); up[2 * WW] = r * r;
        r = fmaxf(s3, 0.f); up[3 * WW] = r * r;
    }
}

__global__ void ffn2_out_kernel(const float* __restrict__ u, const float* __restrict__ w4,
                                const float* __restrict__ h, float* __restrict__ out) {
    int w = blockIdx.x * 128 + threadIdx.x;
    int f = blockIdx.y;
    int bc = blockIdx.z;
    int c = bc & 7;
    int b = bc >> 3;
    const float* up = u + (size_t)bc * EE * WW + w;
    const float* wp = w4 + ((size_t)c * FF + f) * EE;
    float s = wp[0] * up[0] + wp[1] * up[WW] + wp[2] * up[2 * WW] + wp[3] * up[3 * WW];
    out[(((size_t)b * 2 * CC + CC + c) * FF + f) * WW + w] =
        h[((size_t)bc * FF + f) * WW + w] + s;
}

__global__ void xcopy_kernel(const float* __restrict__ x, float* __restrict__ out) {
    size_t i = (size_t)blockIdx.x * blockDim.x + threadIdx.x;
    if (i >= NTOT) return;
    size_t chunk = (size_t)CC * FF * WW;
    size_t b = i / chunk;
    size_t inner = i % chunk;
    out[b * 2 * chunk + inner] = x[i];
}

// ================================================================================
extern "C" void kernel_launch(void* const* d_in, const int* in_sizes, int n_in,
                              void* d_out, int out_size) {
    const float* x    = (const float*)d_in[0];
    const float* skip = (const float*)d_in[1];
    const float* Wq   = (const float*)d_in[2];
    const float* Kq   = (const float*)d_in[3];
    const float* bq   = (const float*)d_in[4];
    const float* Wk   = (const float*)d_in[5];
    const float* Kk   = (const float*)d_in[6];
    const float* bk   = (const float*)d_in[7];
    const float* Wv   = (const float*)d_in[8];
    const float* Kv   = (const float*)d_in[9];
    const float* bv   = (const float*)d_in[10];
    const float* Wo   = (const float*)d_in[11];
    const float* ng   = (const float*)d_in[12];
    const float* nb   = (const float*)d_in[13];
    const float* c1aw = (const float*)d_in[14];
    const float* c1ab = (const float*)d_in[15];
    const float* c1bw = (const float*)d_in[16];
    const float* c1bb = (const float*)d_in[17];
    const float* c2w  = (const float*)d_in[18];
    const float* c2b  = (const float*)d_in[19];
    const float* w3   = (const float*)d_in[20];
    const float* w4   = (const float*)d_in[21];
    float* out = (float*)d_out;

    float *ph, *pz, *pq, *pk, *pv, *ptq, *ptk, *ptv, *pu;
    cudaGetSymbolAddress((void**)&ph, g_h);
    cudaGetSymbolAddress((void**)&pz, g_z);
    cudaGetSymbolAddress((void**)&pq, g_q);
    cudaGetSymbolAddress((void**)&pk, g_k);
    cudaGetSymbolAddress((void**)&pv, g_v);
    cudaGetSymbolAddress((void**)&ptq, g_t);
    cudaGetSymbolAddress((void**)&ptk, g_t2);
    cudaGetSymbolAddress((void**)&ptv, g_t3);
    cudaGetSymbolAddress((void**)&pu, g_u);

    const dim3 gemm_grid(4, 2, BC);
    const dim3 gemm3_grid(4, 2, 3 * BC);
    const dim3 conv3_grid(4, FF / 2, 3 * BB);
    const dim3 ln_grid(8, BC);
    const dim3 ln_block(64, 8);
    const dim3 elw_grid(4, FF, BC);
    const dim3 attn_grid(4, BC * HH);

    const size_t WFF = (size_t)CC * FF * FF;
    const size_t KFF = (size_t)CC * CC * 3;

    auto attn_block = [&](int i, const float* qsrc, const float* msrc) {
        gemm_qkv<<<gemm3_grid, 256>>>(qsrc, msrc, Wq + (size_t)i * WFF, Wk + (size_t)i * WFF,
                                      Wv + (size_t)i * WFF, ptq, ptk, ptv);
        convrope3_kernel<<<conv3_grid, 128>>>(ptq, ptk, ptv,
                                              Kq + (size_t)i * KFF, Kk + (size_t)i * KFF, Kv + (size_t)i * KFF,
                                              bq + i * CC, bk + i * CC, bv + i * CC,
                                              pq, pk, pv);
        attn_mma_kernel<<<attn_grid, 256>>>(pq, pk, pv, ptq);
        gemm_one<<<gemm_grid, 256>>>(ptq, Wo + (size_t)i * WFF, ph);
    };

    // h = x
    copy_kernel<<<2048, 512>>>(ph, x, NTOT);

    // z = LN0(h); h += attn0(z,z); h += attn1(z, skip)
    ln_kernel<<<ln_grid, ln_block>>>(ph, ng + 0 * CC * FF, nb + 0 * CC * FF, pz);
    attn_block(0, pz, pz);
    attn_block(1, pz, skip);

    // conv block
    ln_kernel<<<ln_grid, ln_block>>>(ph, ng + 1 * CC * FF, nb + 1 * CC * FF, pz);
    dwfused_kernel<<<elw_grid, 128>>>(pz, c1aw, c1ab, c1bw, c1bb, pq);
    ln_kernel<<<ln_grid, ln_block>>>(pq, ng + 2 * CC * FF, nb + 2 * CC * FF, pz);
    dwc2_acc_kernel<<<elw_grid, 128>>>(pz, c2w, c2b, ph);

    // attn2 (self) and attn3 (skip)
    ln_kernel<<<ln_grid, ln_block>>>(ph, ng + 3 * CC * FF, nb + 3 * CC * FF, pz);
    attn_block(2, pz, pz);
    ln_kernel<<<ln_grid, ln_block>>>(ph, ng + 4 * CC * FF, nb + 4 * CC * FF, pz);
    attn_block(3, pz, skip);

    // FFN (+ fused concat)
    ln_kernel<<<ln_grid, ln_block>>>(ph, ng + 5 * CC * FF, nb + 5 * CC * FF, pz);
    ffn1_kernel<<<dim3(4, BC), dim3(128, 2)>>>(pz, w3, pu);
    ffn2_out_kernel<<<elw_grid, 128>>>(pu, w4, ph, out);
    xcopy_kernel<<<(unsigned)((NTOT + 255) / 256), 256>>>(x, out);
    (void)in_sizes; (void)n_in; (void)out_size;
}

// round 8
// speedup vs baseline: 2.2604x; 1.0474x over previous
#include <cuda_runtime.h>
#include <cuda_bf16.h>
#include <math.h>
#include <stdint.h>

#define BB 2
#define CC 8
#define FF 256
#define WW 512
#define HH 8
#define HD 32
#define EE 4
#define BC (BB*CC)
#define NTOT ((size_t)BB*CC*FF*WW)
#define CHUNK ((size_t)CC*FF*WW)       // 2^20
#define WMAT_U32 (CC*FF*(FF/2))        // 262144 uint32 per weight matrix

// ---------------- scratch (static device globals; no allocation) ----------------
__device__ float g_h[BB*CC*FF*WW];
__device__ float g_z[BB*CC*FF*WW];
__device__ float g_q[BB*CC*FF*WW];
__device__ float g_k[BB*CC*FF*WW];
__device__ float g_v[BB*CC*FF*WW];
__device__ float g_t[BB*CC*FF*WW];
__device__ float g_t2[BB*CC*FF*WW];
__device__ float g_t3[BB*CC*FF*WW];
__device__ float g_u[BB*CC*EE*WW];
__device__ uint32_t g_wh[16 * WMAT_U32];   // bf16-hi of all 16 weight mats, k-pair packed
__device__ uint32_t g_wl[16 * WMAT_U32];   // bf16-lo residuals

// ---------------- packed f32x2 helpers ----------------
__device__ __forceinline__ unsigned long long pk2(float lo, float hi) {
    unsigned long long r;
    asm("mov.b64 %0, {%1, %2};" : "=l"(r) : "f"(lo), "f"(hi));
    return r;
}
__device__ __forceinline__ void fma2(unsigned long long& d, unsigned long long a, unsigned long long b) {
    asm("fma.rn.f32x2 %0, %1, %2, %0;" : "+l"(d) : "l"(a), "l"(b));
}
__device__ __forceinline__ float2 up2(unsigned long long v) {
    float2 r;
    asm("mov.b64 {%0, %1}, %2;" : "=f"(r.x), "=f"(r.y) : "l"(v));
    return r;
}

// ---------------- bf16 pack helpers ----------------
__device__ __forceinline__ uint32_t bfpack(float a, float b) {
    uint32_t lo = (uint32_t)__bfloat16_as_ushort(__float2bfloat16(a));
    uint32_t hi = (uint32_t)__bfloat16_as_ushort(__float2bfloat16(b));
    return lo | (hi << 16);
}
__device__ __forceinline__ float bfres(float x) {   // x - bf16(x)
    return x - __bfloat162float(__float2bfloat16(x));
}

// ---------------- warp mma.sync bf16 (sm_80+, valid on plain sm_100) ----------------
__device__ __forceinline__ void mma_bf16(float* d, uint32_t a0, uint32_t a1, uint32_t a2, uint32_t a3,
                                         uint32_t b0, uint32_t b1) {
    asm volatile(
        "mma.sync.aligned.m16n8k16.row.col.f32.bf16.bf16.f32 "
        "{%0,%1,%2,%3}, {%4,%5,%6,%7}, {%8,%9}, {%0,%1,%2,%3};"
        : "+f"(d[0]), "+f"(d[1]), "+f"(d[2]), "+f"(d[3])
        : "r"(a0), "r"(a1), "r"(a2), "r"(a3), "r"(b0), "r"(b1));
}

// ---------------- weight pre-conversion: fp32 -> k-pair packed bf16 hi/lo ----------------
// mat index = layer*4 + {0=q,1=k,2=v,3=o}
__global__ void wprep_kernel(const float* __restrict__ Wq, const float* __restrict__ Wk,
                             const float* __restrict__ Wv, const float* __restrict__ Wo) {
    size_t total = 16ull * WMAT_U32;
    for (size_t i = (size_t)blockIdx.x * blockDim.x + threadIdx.x; i < total;
         i += (size_t)gridDim.x * blockDim.x) {
        int mat = (int)(i / WMAT_U32);
        size_t inner = i % WMAT_U32;
        int layer = mat >> 2, kind = mat & 3;
        const float* src = (kind == 0) ? Wq : (kind == 1) ? Wk : (kind == 2) ? Wv : Wo;
        float2 v = *(const float2*)(src + (size_t)layer * CC * FF * FF + inner * 2);
        g_wh[i] = bfpack(v.x, v.y);
        g_wl[i] = bfpack(bfres(v.x), bfres(v.y));
    }
}

// ---------------- tensor-core GEMM tile: Out[128g x 128w] = W[128g x 256f] * X[f][w] ----------------
// A pre-converted (hi/lo packed); B (activations) converted on the fly.
#define ASTR 20
#define BSTR 132
__device__ __forceinline__ void gemm_tile(const uint32_t* __restrict__ Ahg, const uint32_t* __restrict__ Alg,
                                          const float* __restrict__ Bx,
                                          float* __restrict__ Cp, int m0, int n0, bool accum) {
    __shared__ uint32_t Aph[128 * ASTR];
    __shared__ uint32_t Apl[128 * ASTR];
    __shared__ uint32_t Bph[16 * BSTR];
    __shared__ uint32_t Bpl[16 * BSTR];
    int t = threadIdx.x;
    int lane = t & 31, wid = t >> 5;
    int wm = (wid >> 2) * 64;
    int wn = (wid & 3) * 32;
    int g = lane >> 2, tig = lane & 3;

    float acc[4][4][4];
#pragma unroll
    for (int mt = 0; mt < 4; mt++)
#pragma unroll
        for (int nt = 0; nt < 4; nt++)
#pragma unroll
            for (int j = 0; j < 4; j++) acc[mt][nt][j] = 0.f;

    for (int ch = 0; ch < 8; ch++) {
        // ---- A chunk: direct copy of pre-packed hi/lo (8 uint32/thread each) ----
        {
            int row = t >> 1;
            int half = (t & 1) * 8;
            const uint32_t* sh = Ahg + (size_t)(m0 + row) * (FF / 2) + ch * 16 + half;
            const uint32_t* sl = Alg + (size_t)(m0 + row) * (FF / 2) + ch * 16 + half;
            uint4 h0 = *(const uint4*)sh;
            uint4 h1 = *(const uint4*)(sh + 4);
            uint4 l0 = *(const uint4*)sl;
            uint4 l1 = *(const uint4*)(sl + 4);
            uint32_t* dh = Aph + row * ASTR + half;
            uint32_t* dl = Apl + row * ASTR + half;
            *(uint4*)dh = h0; *(uint4*)(dh + 4) = h1;
            *(uint4*)dl = l0; *(uint4*)(dl + 4) = l1;
        }
        // ---- B chunk: convert on the fly ----
        {
            int kp = t >> 4;
            int wq = t & 15;
            const float* b0p = Bx + (size_t)(ch * 32 + kp * 2) * WW + n0 + wq * 8;
            const float* b1p = b0p + WW;
            float4 x0a = *(const float4*)(b0p);
            float4 x0b = *(const float4*)(b0p + 4);
            float4 x1a = *(const float4*)(b1p);
            float4 x1b = *(const float4*)(b1p + 4);
            float r0[8] = {x0a.x, x0a.y, x0a.z, x0a.w, x0b.x, x0b.y, x0b.z, x0b.w};
            float r1[8] = {x1a.x, x1a.y, x1a.z, x1a.w, x1b.x, x1b.y, x1b.z, x1b.w};
            uint32_t* dh = Bph + kp * BSTR + wq * 8;
            uint32_t* dl = Bpl + kp * BSTR + wq * 8;
#pragma unroll
            for (int j = 0; j < 8; j++) {
                dh[j] = bfpack(r0[j], r1[j]);
                dl[j] = bfpack(bfres(r0[j]), bfres(r1[j]));
            }
        }
        __syncthreads();

#pragma unroll
        for (int ks = 0; ks < 2; ks++) {
            int kk2 = ks * 8;
            uint32_t bh[4][2], bl[4][2];
#pragma unroll
            for (int nt = 0; nt < 4; nt++) {
                int n = wn + nt * 8 + g;
                bh[nt][0] = Bph[(tig + kk2) * BSTR + n];
                bh[nt][1] = Bph[(tig + 4 + kk2) * BSTR + n];
                bl[nt][0] = Bpl[(tig + kk2) * BSTR + n];
                bl[nt][1] = Bpl[(tig + 4 + kk2) * BSTR + n];
            }
#pragma unroll
            for (int mt = 0; mt < 4; mt++) {
                int r0 = wm + mt * 16 + g;
                uint32_t ah0 = Aph[r0 * ASTR + tig + kk2];
                uint32_t ah1 = Aph[(r0 + 8) * ASTR + tig + kk2];
                uint32_t ah2 = Aph[r0 * ASTR + tig + 4 + kk2];
                uint32_t ah3 = Aph[(r0 + 8) * ASTR + tig + 4 + kk2];
                uint32_t al0 = Apl[r0 * ASTR + tig + kk2];
                uint32_t al1 = Apl[(r0 + 8) * ASTR + tig + kk2];
                uint32_t al2 = Apl[r0 * ASTR + tig + 4 + kk2];
                uint32_t al3 = Apl[(r0 + 8) * ASTR + tig + 4 + kk2];
#pragma unroll
                for (int nt = 0; nt < 4; nt++) {
                    mma_bf16(acc[mt][nt], ah0, ah1, ah2, ah3, bh[nt][0], bh[nt][1]);
                    mma_bf16(acc[mt][nt], ah0, ah1, ah2, ah3, bl[nt][0], bl[nt][1]);
                    mma_bf16(acc[mt][nt], al0, al1, al2, al3, bh[nt][0], bh[nt][1]);
                }
            }
        }
        __syncthreads();
    }

#pragma unroll
    for (int mt = 0; mt < 4; mt++) {
#pragma unroll
        for (int nt = 0; nt < 4; nt++) {
            int row = m0 + wm + mt * 16 + g;
            int col = n0 + wn + nt * 8 + tig * 2;
            float* p0 = Cp + (size_t)row * WW + col;
            float* p1 = Cp + (size_t)(row + 8) * WW + col;
            if (accum) {
                float2 c0 = *(float2*)p0;
                float2 c1 = *(float2*)p1;
                c0.x += acc[mt][nt][0]; c0.y += acc[mt][nt][1];
                c1.x += acc[mt][nt][2]; c1.y += acc[mt][nt][3];
                *(float2*)p0 = c0;
                *(float2*)p1 = c1;
            } else {
                *(float2*)p0 = make_float2(acc[mt][nt][0], acc[mt][nt][1]);
                *(float2*)p1 = make_float2(acc[mt][nt][2], acc[mt][nt][3]);
            }
        }
    }
}

__global__ __launch_bounds__(256) void gemm_qkv(int layer,
                                                const float* __restrict__ qsrc, const float* __restrict__ msrc,
                                                float* __restrict__ oq, float* __restrict__ ok_,
                                                float* __restrict__ ov) {
    int z = blockIdx.z;
    int which = z >> 4;
    int bc = z & 15;
    int c = bc & (CC - 1);
    const float* X = (which == 0) ? qsrc : msrc;
    float* Out = (which == 0) ? oq : (which == 1) ? ok_ : ov;
    size_t moff = (size_t)(layer * 4 + which) * WMAT_U32 + (size_t)c * FF * (FF / 2);
    gemm_tile(g_wh + moff, g_wl + moff, X + (size_t)bc * FF * WW,
              Out + (size_t)bc * FF * WW, blockIdx.y * 128, blockIdx.x * 128, false);
}

__global__ __launch_bounds__(256) void gemm_one(int layer, const float* __restrict__ X,
                                                float* __restrict__ Out) {
    int bc = blockIdx.z;
    int c = bc & (CC - 1);
    size_t moff = (size_t)(layer * 4 + 3) * WMAT_U32 + (size_t)c * FF * (FF / 2);
    gemm_tile(g_wh + moff, g_wl + moff, X + (size_t)bc * FF * WW,
              Out + (size_t)bc * FF * WW, blockIdx.y * 128, blockIdx.x * 128, true);
}

// ---------------- flash-attention via mma.sync ----------------
#define AT_QSTR 17
#define AT_KSTR 136
#define AT_VSTR 40
__global__ __launch_bounds__(256, 2) void attn_mma_kernel(const float* __restrict__ Q,
                                                          const float* __restrict__ Kb,
                                                          const float* __restrict__ Vb,
                                                          float* __restrict__ Ob) {
    __shared__ uint32_t Qh[128 * AT_QSTR];
    __shared__ uint32_t Ql[128 * AT_QSTR];
    __shared__ uint32_t Kh[16 * AT_KSTR];
    __shared__ uint32_t Kl[16 * AT_KSTR];
    __shared__ uint32_t Vh[64 * AT_VSTR];
    int t = threadIdx.x;
    int lane = t & 31, wid = t >> 5;
    int g = lane >> 2, tig = lane & 3;
    int qt = blockIdx.x;
    int bch = blockIdx.y;
    int h = bch & (HH - 1);
    int bc = bch >> 3;
    size_t base = ((size_t)bc * FF + h * HD) * WW;
    const float* gq = Q + base + qt * 128;
    const float* gk = Kb + base;
    const float* gv = Vb + base;

    {
        int q = t & 127;
        int dp0 = (t >> 7) * 8;
#pragma unroll
        for (int j = 0; j < 8; j++) {
            int dp = dp0 + j;
            float v0 = gq[(size_t)(2 * dp) * WW + q] * 0.0625f;
            float v1 = gq[(size_t)(2 * dp + 1) * WW + q] * 0.0625f;
            Qh[q * AT_QSTR + dp] = bfpack(v0, v1);
            Ql[q * AT_QSTR + dp] = bfpack(bfres(v0), bfres(v1));
        }
    }
    __syncthreads();

    uint32_t qah[2][4], qal[2][4];
    int qr = wid * 16;
#pragma unroll
    for (int s = 0; s < 2; s++) {
        qah[s][0] = Qh[(qr + g) * AT_QSTR + s * 8 + tig];
        qah[s][1] = Qh[(qr + g + 8) * AT_QSTR + s * 8 + tig];
        qah[s][2] = Qh[(qr + g) * AT_QSTR + s * 8 + tig + 4];
        qah[s][3] = Qh[(qr + g + 8) * AT_QSTR + s * 8 + tig + 4];
        qal[s][0] = Ql[(qr + g) * AT_QSTR + s * 8 + tig];
        qal[s][1] = Ql[(qr + g + 8) * AT_QSTR + s * 8 + tig];
        qal[s][2] = Ql[(qr + g) * AT_QSTR + s * 8 + tig + 4];
        qal[s][3] = Ql[(qr + g + 8) * AT_QSTR + s * 8 + tig + 4];
    }

    float M0 = -1e30f, M1 = -1e30f, L0 = 0.f, L1 = 0.f;
    float oac[4][4];
#pragma unroll
    for (int i = 0; i < 4; i++)
#pragma unroll
        for (int j = 0; j < 4; j++) oac[i][j] = 0.f;

    for (int kt = 0; kt < 4; kt++) {
        __syncthreads();
        {
            int dp = t >> 4;
            int kq = (t & 15) * 8;
            const float* r0 = gk + (size_t)(2 * dp) * WW + kt * 128 + kq;
            const float* r1 = r0 + WW;
            float4 a0 = *(const float4*)(r0);
            float4 a1 = *(const float4*)(r0 + 4);
            float4 b0 = *(const float4*)(r1);
            float4 b1 = *(const float4*)(r1 + 4);
            float ra[8] = {a0.x, a0.y, a0.z, a0.w, a1.x, a1.y, a1.z, a1.w};
            float rb[8] = {b0.x, b0.y, b0.z, b0.w, b1.x, b1.y, b1.z, b1.w};
            uint32_t* dh = Kh + dp * AT_KSTR + kq;
            uint32_t* dl = Kl + dp * AT_KSTR + kq;
#pragma unroll
            for (int j = 0; j < 8; j++) {
                dh[j] = bfpack(ra[j], rb[j]);
                dl[j] = bfpack(bfres(ra[j]), bfres(rb[j]));
            }
        }
        {
            int d = t & 31;
            int kp0 = (t >> 5) * 8;
            const float* r = gv + (size_t)d * WW + kt * 128 + kp0 * 2;
            float4 x0 = *(const float4*)(r);
            float4 x1 = *(const float4*)(r + 4);
            float4 x2 = *(const float4*)(r + 8);
            float4 x3 = *(const float4*)(r + 12);
            Vh[(kp0 + 0) * AT_VSTR + d] = bfpack(x0.x, x0.y);
            Vh[(kp0 + 1) * AT_VSTR + d] = bfpack(x0.z, x0.w);
            Vh[(kp0 + 2) * AT_VSTR + d] = bfpack(x1.x, x1.y);
            Vh[(kp0 + 3) * AT_VSTR + d] = bfpack(x1.z, x1.w);
            Vh[(kp0 + 4) * AT_VSTR + d] = bfpack(x2.x, x2.y);
            Vh[(kp0 + 5) * AT_VSTR + d] = bfpack(x2.z, x2.w);
            Vh[(kp0 + 6) * AT_VSTR + d] = bfpack(x3.x, x3.y);
            Vh[(kp0 + 7) * AT_VSTR + d] = bfpack(x3.z, x3.w);
        }
        __syncthreads();

        float sa[16][4];
#pragma unroll
        for (int nt = 0; nt < 16; nt++) {
            sa[nt][0] = 0.f; sa[nt][1] = 0.f; sa[nt][2] = 0.f; sa[nt][3] = 0.f;
        }
#pragma unroll
        for (int nt = 0; nt < 16; nt++) {
            int n = nt * 8 + g;
            uint32_t kh0 = Kh[(tig) * AT_KSTR + n];
            uint32_t kh1 = Kh[(tig + 4) * AT_KSTR + n];
            uint32_t kh2 = Kh[(tig + 8) * AT_KSTR + n];
            uint32_t kh3 = Kh[(tig + 12) * AT_KSTR + n];
            uint32_t kl0 = Kl[(tig) * AT_KSTR + n];
            uint32_t kl1 = Kl[(tig + 4) * AT_KSTR + n];
            uint32_t kl2 = Kl[(tig + 8) * AT_KSTR + n];
            uint32_t kl3 = Kl[(tig + 12) * AT_KSTR + n];
            mma_bf16(sa[nt], qah[0][0], qah[0][1], qah[0][2], qah[0][3], kh0, kh1);
            mma_bf16(sa[nt], qah[1][0], qah[1][1], qah[1][2], qah[1][3], kh2, kh3);
            mma_bf16(sa[nt], qah[0][0], qah[0][1], qah[0][2], qah[0][3], kl0, kl1);
            mma_bf16(sa[nt], qah[1][0], qah[1][1], qah[1][2], qah[1][3], kl2, kl3);
            mma_bf16(sa[nt], qal[0][0], qal[0][1], qal[0][2], qal[0][3], kh0, kh1);
            mma_bf16(sa[nt], qal[1][0], qal[1][1], qal[1][2], qal[1][3], kh2, kh3);
        }

        float mx0 = -1e30f, mx1 = -1e30f;
#pragma unroll
        for (int nt = 0; nt < 16; nt++) {
            mx0 = fmaxf(mx0, fmaxf(sa[nt][0], sa[nt][1]));
            mx1 = fmaxf(mx1, fmaxf(sa[nt][2], sa[nt][3]));
        }
        mx0 = fmaxf(mx0, __shfl_xor_sync(0xFFFFFFFFu, mx0, 1));
        mx0 = fmaxf(mx0, __shfl_xor_sync(0xFFFFFFFFu, mx0, 2));
        mx1 = fmaxf(mx1, __shfl_xor_sync(0xFFFFFFFFu, mx1, 1));
        mx1 = fmaxf(mx1, __shfl_xor_sync(0xFFFFFFFFu, mx1, 2));
        float Mn0 = fmaxf(M0, mx0), Mn1 = fmaxf(M1, mx1);
        float c0 = __expf(M0 - Mn0), c1 = __expf(M1 - Mn1);
        float ps0 = 0.f, ps1 = 0.f;
#pragma unroll
        for (int nt = 0; nt < 16; nt++) {
            sa[nt][0] = __expf(sa[nt][0] - Mn0);
            sa[nt][1] = __expf(sa[nt][1] - Mn0);
            sa[nt][2] = __expf(sa[nt][2] - Mn1);
            sa[nt][3] = __expf(sa[nt][3] - Mn1);
            ps0 += sa[nt][0] + sa[nt][1];
            ps1 += sa[nt][2] + sa[nt][3];
        }
        ps0 += __shfl_xor_sync(0xFFFFFFFFu, ps0, 1);
        ps0 += __shfl_xor_sync(0xFFFFFFFFu, ps0, 2);
        ps1 += __shfl_xor_sync(0xFFFFFFFFu, ps1, 1);
        ps1 += __shfl_xor_sync(0xFFFFFFFFu, ps1, 2);
        L0 = L0 * c0 + ps0;
        L1 = L1 * c1 + ps1;
        M0 = Mn0; M1 = Mn1;
#pragma unroll
        for (int nt4 = 0; nt4 < 4; nt4++) {
            oac[nt4][0] *= c0; oac[nt4][1] *= c0;
            oac[nt4][2] *= c1; oac[nt4][3] *= c1;
        }

#pragma unroll
        for (int s8 = 0; s8 < 8; s8++) {
            uint32_t pa0 = bfpack(sa[2 * s8][0], sa[2 * s8][1]);
            uint32_t pa1 = bfpack(sa[2 * s8][2], sa[2 * s8][3]);
            uint32_t pa2 = bfpack(sa[2 * s8 + 1][0], sa[2 * s8 + 1][1]);
            uint32_t pa3 = bfpack(sa[2 * s8 + 1][2], sa[2 * s8 + 1][3]);
#pragma unroll
            for (int nt4 = 0; nt4 < 4; nt4++) {
                int d = nt4 * 8 + g;
                uint32_t vb0 = Vh[(s8 * 8 + tig) * AT_VSTR + d];
                uint32_t vb1 = Vh[(s8 * 8 + tig + 4) * AT_VSTR + d];
                mma_bf16(oac[nt4], pa0, pa1, pa2, pa3, vb0, vb1);
            }
        }
    }

    float il0 = 1.f / L0, il1 = 1.f / L1;
    int q0 = qt * 128 + qr + g;
#pragma unroll
    for (int nt4 = 0; nt4 < 4; nt4++) {
        int d = nt4 * 8 + 2 * tig;
        float* o0 = Ob + base + (size_t)d * WW;
        float* o1 = Ob + base + (size_t)(d + 1) * WW;
        o0[q0] = oac[nt4][0] * il0;
        o1[q0] = oac[nt4][1] * il0;
        o0[q0 + 8] = oac[nt4][2] * il1;
        o1[q0 + 8] = oac[nt4][3] * il1;
    }
}

// ---------------- combined: h = x AND out-x-half = x ----------------
__global__ void copy2_kernel(float* __restrict__ dst, const float* __restrict__ src,
                             float* __restrict__ out) {
    size_t i = (size_t)blockIdx.x * blockDim.x + threadIdx.x;
    size_t stride = (size_t)gridDim.x * blockDim.x;
    for (; i < NTOT; i += stride) {
        float v = src[i];
        dst[i] = v;
        size_t b = i >> 20;
        size_t inner = i & (CHUNK - 1);
        out[b * 2 * CHUNK + inner] = v;
    }
}

// ---------------- LayerNorm over features ----------------
__global__ void ln_kernel(const float* __restrict__ src, const float* __restrict__ g,
                          const float* __restrict__ bet, float* __restrict__ dst) {
    int bc = blockIdx.y;
    int c = bc & (CC - 1);
    int tx = threadIdx.x;
    int fy = threadIdx.y;
    int w = blockIdx.x * 64 + tx;
    const float* p = src + (size_t)bc * FF * WW + w;
    float s = 0.f, s2 = 0.f;
#pragma unroll 8
    for (int f = fy * 32; f < fy * 32 + 32; f++) {
        float v = p[(size_t)f * WW];
        s += v; s2 += v * v;
    }
    __shared__ float red[2][8][64];
    red[0][fy][tx] = s;
    red[1][fy][tx] = s2;
    __syncthreads();
    float S = 0.f, S2 = 0.f;
#pragma unroll
    for (int j = 0; j < 8; j++) { S += red[0][j][tx]; S2 += red[1][j][tx]; }
    float m = S * (1.0f / FF);
    float rs = rsqrtf(S2 * (1.0f / FF) - m * m + 1e-5f);
    const float* gc = g + c * FF;
    const float* bb = bet + c * FF;
    float* q = dst + (size_t)bc * FF * WW + w;
#pragma unroll 8
    for (int f = fy * 32; f < fy * 32 + 32; f++) {
        q[(size_t)f * WW] = (p[(size_t)f * WW] - m) * rs * gc[f] + bb[f];
    }
}

// ---------------- fused QKV 1x3 channel-mix conv + RoPE (f32x2 math) ----------------
__global__ __launch_bounds__(128) void convrope3_kernel(
    const float* __restrict__ tq, const float* __restrict__ tk, const float* __restrict__ tv,
    const float* __restrict__ Kq, const float* __restrict__ Kk, const float* __restrict__ Kv,
    const float* __restrict__ bq, const float* __restrict__ bk, const float* __restrict__ bv,
    float* __restrict__ oq, float* __restrict__ ok_, float* __restrict__ ov) {
    int which = blockIdx.z >> 1;
    int b = blockIdx.z & 1;
    const float* src = (which == 0) ? tq : (which == 1) ? tk : tv;
    const float* Kw  = (which == 0) ? Kq : (which == 1) ? Kk : Kv;
    const float* bias = (which == 0) ? bq : (which == 1) ? bk : bv;
    float* dst = (which == 0) ? oq : (which == 1) ? ok_ : ov;

    __shared__ unsigned long long sK2[64][4];   // (k,k) duplicated, stride 4 for 16B align
    __shared__ float sB2[CC];
    int t = threadIdx.x;
    if (t < 64) {
        float k0 = Kw[t * 3], k1 = Kw[t * 3 + 1], k2 = Kw[t * 3 + 2];
        sK2[t][0] = pk2(k0, k0);
        sK2[t][1] = pk2(k1, k1);
        sK2[t][2] = pk2(k2, k2);
    }
    if (t < CC) sB2[t] = bias[t];
    __syncthreads();

    int w = blockIdx.x * 128 + t;
    int f0 = blockIdx.y * 2;
    unsigned long long y01[8];
#pragma unroll
    for (int co = 0; co < 8; co++) y01[co] = pk2(sB2[co], sB2[co]);
#pragma unroll
    for (int ci = 0; ci < 8; ci++) {
        const float* xp = src + ((size_t)(b * CC + ci) * FF + f0) * WW + w;
        float l0 = (w > 0) ? xp[-1] : 0.f;
        float c0 = xp[0];
        float r0 = (w < WW - 1) ? xp[1] : 0.f;
        float l1 = (w > 0) ? xp[WW - 1] : 0.f;
        float c1 = xp[WW];
        float r1 = (w < WW - 1) ? xp[WW + 1] : 0.f;
        unsigned long long l01 = pk2(l0, l1);
        unsigned long long c01 = pk2(c0, c1);
        unsigned long long r01 = pk2(r0, r1);
#pragma unroll
        for (int co = 0; co < 8; co++) {
            const ulonglong2 kk01 = *(const ulonglong2*)&sK2[co * 8 + ci][0];
            unsigned long long kk2v = sK2[co * 8 + ci][2];
            fma2(y01[co], kk01.x, l01);
            fma2(y01[co], kk01.y, c01);
            fma2(y01[co], kk2v, r01);
        }
    }
    int d = f0 & (HD - 1);
    float theta = expf(-(float)d * (9.210340371976184f / (float)HD));
    float sn, cs;
    sincosf((float)w * theta, &sn, &cs);
    bool dorope = (which < 2);
#pragma unroll
    for (int co = 0; co < 8; co++) {
        float2 y = up2(y01[co]);
        float* op = dst + ((size_t)(b * CC + co) * FF + f0) * WW + w;
        if (dorope) {
            op[0]  = y.x * cs - y.y * sn;
            op[WW] = y.y * cs + y.x * sn;
        } else {
            op[0] = y.x;
            op[WW] = y.y;
        }
    }
}

// ---------------- fused depthwise: out = sqrelu(conv11(z)) + conv7(z) ----------------
__global__ void dwfused_kernel(const float* __restrict__ z, const float* __restrict__ w11,
                               const float* __restrict__ b11, const float* __restrict__ w7,
                               const float* __restrict__ b7, float* __restrict__ out) {
    int w = blockIdx.x * 128 + threadIdx.x;
    int f = blockIdx.y;
    int bc = blockIdx.z;
    int c = bc & 7;
    const float* zp = z + (size_t)bc * FF * WW + w;
    float a = b11[c], b2 = b7[c];
#pragma unroll
    for (int k = 0; k < 11; k++) {
        int fv = f + k - 5;
        if (fv >= 0 && fv < FF) {
            float v = zp[(size_t)fv * WW];
            a += w11[c * 11 + k] * v;
            if (k >= 2 && k <= 8) b2 += w7[c * 7 + (k - 2)] * v;
        }
    }
    float r = fmaxf(a, 0.f);
    out[((size_t)bc * FF + f) * WW + w] = r * r + b2;
}

// ---------------- depthwise 7-tap conv accumulated into h ----------------
__global__ void dwc2_acc_kernel(const float* __restrict__ z, const float* __restrict__ w7,
                                const float* __restrict__ b7, float* __restrict__ h) {
    int w = blockIdx.x * 128 + threadIdx.x;
    int f = blockIdx.y;
    int bc = blockIdx.z;
    int c = bc & 7;
    const float* zp = z + (size_t)bc * FF * WW + w;
    float s = b7[c];
#pragma unroll
    for (int k = 0; k < 7; k++) {
        int fv = f + k - 3;
        if (fv >= 0 && fv < FF) s += w7[c * 7 + k] * zp[(size_t)fv * WW];
    }
    h[((size_t)bc * FF + f) * WW + w] += s;
}

// ---------------- FFN ----------------
__global__ void ffn1_kernel(const float* __restrict__ z, const float* __restrict__ w3,
                            float* __restrict__ u) {
    int tx = threadIdx.x;
    int fy = threadIdx.y;
    int w = blockIdx.x * 128 + tx;
    int bc = blockIdx.y;
    int c = bc & 7;
    const float* zp = z + (size_t)bc * FF * WW + w;
    const float* wp = w3 + (size_t)c * EE * FF;
    float s0 = 0.f, s1 = 0.f, s2 = 0.f, s3 = 0.f;
#pragma unroll 4
    for (int f = fy * 128; f < fy * 128 + 128; f++) {
        float zv = zp[(size_t)f * WW];
        s0 += wp[f] * zv;
        s1 += wp[FF + f] * zv;
        s2 += wp[2 * FF + f] * zv;
        s3 += wp[3 * FF + f] * zv;
    }
    __shared__ float red[4][2][128];
    red[0][fy][tx] = s0; red[1][fy][tx] = s1;
    red[2][fy][tx] = s2; red[3][fy][tx] = s3;
    __syncthreads();
    if (fy == 0) {
        s0 = red[0][0][tx] + red[0][1][tx];
        s1 = red[1][0][tx] + red[1][1][tx];
        s2 = red[2][0][tx] + red[2][1][tx];
        s3 = red[3][0][tx] + red[3][1][tx];
        float* up = u + (size_t)bc * EE * WW + w;
        float r;
        r = fmaxf(s0, 0.f); up[0]      = r * r;
        r = fmaxf(s1, 0.f); up[WW]     = r * r;
        r = fmaxf(s2, 0.f); up[2 * WW] = r * r;
        r = fmaxf(s3, 0.f); up[3 * WW] = r * r;
    }
}

__global__ void ffn2_out_kernel(const float* __restrict__ u, const float* __restrict__ w4,
                                const float* __restrict__ h, float* __restrict__ out) {
    int w = blockIdx.x * 128 + threadIdx.x;
    int f = blockIdx.y;
    int bc = blockIdx.z;
    int c = bc & 7;
    int b = bc >> 3;
    const float* up = u + (size_t)bc * EE * WW + w;
    const float* wp = w4 + ((size_t)c * FF + f) * EE;
    float s = wp[0] * up[0] + wp[1] * up[WW] + wp[2] * up[2 * WW] + wp[3] * up[3 * WW];
    out[(((size_t)b * 2 * CC + CC + c) * FF + f) * WW + w] =
        h[((size_t)bc * FF + f) * WW + w] + s;
}

// ================================================================================
extern "C" void kernel_launch(void* const* d_in, const int* in_sizes, int n_in,
                              void* d_out, int out_size) {
    const float* x    = (const float*)d_in[0];
    const float* skip = (const float*)d_in[1];
    const float* Wq   = (const float*)d_in[2];
    const float* Kq   = (const float*)d_in[3];
    const float* bq   = (const float*)d_in[4];
    const float* Wk   = (const float*)d_in[5];
    const float* Kk   = (const float*)d_in[6];
    const float* bk   = (const float*)d_in[7];
    const float* Wv   = (const float*)d_in[8];
    const float* Kv   = (const float*)d_in[9];
    const float* bv   = (const float*)d_in[10];
    const float* Wo   = (const float*)d_in[11];
    const float* ng   = (const float*)d_in[12];
    const float* nb   = (const float*)d_in[13];
    const float* c1aw = (const float*)d_in[14];
    const float* c1ab = (const float*)d_in[15];
    const float* c1bw = (const float*)d_in[16];
    const float* c1bb = (const float*)d_in[17];
    const float* c2w  = (const float*)d_in[18];
    const float* c2b  = (const float*)d_in[19];
    const float* w3   = (const float*)d_in[20];
    const float* w4   = (const float*)d_in[21];
    float* out = (float*)d_out;

    float *ph, *pz, *pq, *pk, *pv, *ptq, *ptk, *ptv, *pu;
    cudaGetSymbolAddress((void**)&ph, g_h);
    cudaGetSymbolAddress((void**)&pz, g_z);
    cudaGetSymbolAddress((void**)&pq, g_q);
    cudaGetSymbolAddress((void**)&pk, g_k);
    cudaGetSymbolAddress((void**)&pv, g_v);
    cudaGetSymbolAddress((void**)&ptq, g_t);
    cudaGetSymbolAddress((void**)&ptk, g_t2);
    cudaGetSymbolAddress((void**)&ptv, g_t3);
    cudaGetSymbolAddress((void**)&pu, g_u);

    const dim3 gemm_grid(4, 2, BC);
    const dim3 gemm3_grid(4, 2, 3 * BC);
    const dim3 conv3_grid(4, FF / 2, 3 * BB);
    const dim3 ln_grid(8, BC);
    const dim3 ln_block(64, 8);
    const dim3 elw_grid(4, FF, BC);
    const dim3 attn_grid(4, BC * HH);

    const size_t KFF = (size_t)CC * CC * 3;

    auto attn_block = [&](int i, const float* qsrc, const float* msrc) {
        gemm_qkv<<<gemm3_grid, 256>>>(i, qsrc, msrc, ptq, ptk, ptv);
        convrope3_kernel<<<conv3_grid, 128>>>(ptq, ptk, ptv,
                                              Kq + (size_t)i * KFF, Kk + (size_t)i * KFF, Kv + (size_t)i * KFF,
                                              bq + i * CC, bk + i * CC, bv + i * CC,
                                              pq, pk, pv);
        attn_mma_kernel<<<attn_grid, 256>>>(pq, pk, pv, ptq);
        gemm_one<<<gemm_grid, 256>>>(i, ptq, ph);
    };

    // weight pre-conversion (runs each replay; ~3 us)
    wprep_kernel<<<4096, 512>>>(Wq, Wk, Wv, Wo);

    // h = x; out-x-half = x
    copy2_kernel<<<2048, 512>>>(ph, x, out);

    // z = LN0(h); h += attn0(z,z); h += attn1(z, skip)
    ln_kernel<<<ln_grid, ln_block>>>(ph, ng + 0 * CC * FF, nb + 0 * CC * FF, pz);
    attn_block(0, pz, pz);
    attn_block(1, pz, skip);

    // conv block
    ln_kernel<<<ln_grid, ln_block>>>(ph, ng + 1 * CC * FF, nb + 1 * CC * FF, pz);
    dwfused_kernel<<<elw_grid, 128>>>(pz, c1aw, c1ab, c1bw, c1bb, pq);
    ln_kernel<<<ln_grid, ln_block>>>(pq, ng + 2 * CC * FF, nb + 2 * CC * FF, pz);
    dwc2_acc_kernel<<<elw_grid, 128>>>(pz, c2w, c2b, ph);

    // attn2 (self) and attn3 (skip)
    ln_kernel<<<ln_grid, ln_block>>>(ph, ng + 3 * CC * FF, nb + 3 * CC * FF, pz);
    attn_block(2, pz, pz);
    ln_kernel<<<ln_grid, ln_block>>>(ph, ng + 4 * CC * FF, nb + 4 * CC * FF, pz);
    attn_block(3, pz, skip);

    // FFN (+ fused concat)
    ln_kernel<<<ln_grid, ln_block>>>(ph, ng + 5 * CC * FF, nb + 5 * CC * FF, pz);
    ffn1_kernel<<<dim3(4, BC), dim3(128, 2)>>>(pz, w3, pu);
    ffn2_out_kernel<<<elw_grid, 128>>>(pu, w4, ph, out);
    (void)in_sizes; (void)n_in; (void)out_size;
}

// round 9
// speedup vs baseline: 2.4130x; 1.0675x over previous
#include <cuda_runtime.h>
#include <cuda_bf16.h>
#include <math.h>
#include <stdint.h>

#define BB 2
#define CC 8
#define FF 256
#define WW 512
#define HH 8
#define HD 32
#define EE 4
#define BC (BB*CC)
#define NTOT ((size_t)BB*CC*FF*WW)
#define CHUNK ((size_t)CC*FF*WW)       // 2^20
#define WMAT_U32 (CC*FF*(FF/2))        // 262144 uint32 per weight matrix

// ---------------- scratch (static device globals; no allocation) ----------------
__device__ float g_h[BB*CC*FF*WW];
__device__ float g_z[BB*CC*FF*WW];
__device__ float g_q[BB*CC*FF*WW];
__device__ float g_k[BB*CC*FF*WW];
__device__ float g_v[BB*CC*FF*WW];
__device__ float g_t[BB*CC*FF*WW];
__device__ float g_t2[BB*CC*FF*WW];
__device__ float g_t3[BB*CC*FF*WW];
__device__ float g_u[BB*CC*EE*WW];
__device__ uint32_t g_wh[16 * WMAT_U32];   // bf16-hi of all 16 weight mats, k-pair packed
__device__ uint32_t g_wl[16 * WMAT_U32];   // bf16-lo residuals

// ---------------- packed f32x2 helpers ----------------
__device__ __forceinline__ unsigned long long pk2(float lo, float hi) {
    unsigned long long r;
    asm("mov.b64 %0, {%1, %2};" : "=l"(r) : "f"(lo), "f"(hi));
    return r;
}
__device__ __forceinline__ void fma2(unsigned long long& d, unsigned long long a, unsigned long long b) {
    asm("fma.rn.f32x2 %0, %1, %2, %0;" : "+l"(d) : "l"(a), "l"(b));
}
__device__ __forceinline__ float2 up2(unsigned long long v) {
    float2 r;
    asm("mov.b64 {%0, %1}, %2;" : "=f"(r.x), "=f"(r.y) : "l"(v));
    return r;
}

// ---------------- bf16 pack helpers ----------------
__device__ __forceinline__ uint32_t bfpack(float a, float b) {
    uint32_t lo = (uint32_t)__bfloat16_as_ushort(__float2bfloat16(a));
    uint32_t hi = (uint32_t)__bfloat16_as_ushort(__float2bfloat16(b));
    return lo | (hi << 16);
}
__device__ __forceinline__ float bfres(float x) {   // x - bf16(x)
    return x - __bfloat162float(__float2bfloat16(x));
}

// ---------------- warp mma.sync bf16 (sm_80+, valid on plain sm_100) ----------------
__device__ __forceinline__ void mma_bf16(float* d, uint32_t a0, uint32_t a1, uint32_t a2, uint32_t a3,
                                         uint32_t b0, uint32_t b1) {
    asm volatile(
        "mma.sync.aligned.m16n8k16.row.col.f32.bf16.bf16.f32 "
        "{%0,%1,%2,%3}, {%4,%5,%6,%7}, {%8,%9}, {%0,%1,%2,%3};"
        : "+f"(d[0]), "+f"(d[1]), "+f"(d[2]), "+f"(d[3])
        : "r"(a0), "r"(a1), "r"(a2), "r"(a3), "r"(b0), "r"(b1));
}

// ---------------- weight pre-conversion: fp32 -> k-pair packed bf16 hi/lo ----------------
__global__ void wprep_kernel(const float* __restrict__ Wq, const float* __restrict__ Wk,
                             const float* __restrict__ Wv, const float* __restrict__ Wo) {
    size_t total = 16ull * WMAT_U32;
    for (size_t i = (size_t)blockIdx.x * blockDim.x + threadIdx.x; i < total;
         i += (size_t)gridDim.x * blockDim.x) {
        int mat = (int)(i / WMAT_U32);
        size_t inner = i % WMAT_U32;
        int layer = mat >> 2, kind = mat & 3;
        const float* src = (kind == 0) ? Wq : (kind == 1) ? Wk : (kind == 2) ? Wv : Wo;
        float2 v = *(const float2*)(src + (size_t)layer * CC * FF * FF + inner * 2);
        g_wh[i] = bfpack(v.x, v.y);
        g_wl[i] = bfpack(bfres(v.x), bfres(v.y));
    }
}

// ---------------- tensor-core GEMM tile: 512 threads, 16 warps, 32x32 warp tile ----------------
#define ASTR 20
#define BSTR 132
__device__ __forceinline__ void gemm_tile(const uint32_t* __restrict__ Ahg, const uint32_t* __restrict__ Alg,
                                          const float* __restrict__ Bx,
                                          float* __restrict__ Cp, int m0, int n0, bool accum) {
    __shared__ uint32_t Aph[128 * ASTR];
    __shared__ uint32_t Apl[128 * ASTR];
    __shared__ uint32_t Bph[16 * BSTR];
    __shared__ uint32_t Bpl[16 * BSTR];
    int t = threadIdx.x;
    int lane = t & 31, wid = t >> 5;
    int wm = (wid >> 2) * 32;       // 4 m-groups of 32 rows
    int wn = (wid & 3) * 32;        // 4 n-groups of 32 cols
    int g = lane >> 2, tig = lane & 3;

    float acc[2][4][4];
#pragma unroll
    for (int mt = 0; mt < 2; mt++)
#pragma unroll
        for (int nt = 0; nt < 4; nt++)
#pragma unroll
            for (int j = 0; j < 4; j++) acc[mt][nt][j] = 0.f;

    for (int ch = 0; ch < 8; ch++) {
        // ---- A chunk: copy pre-packed hi/lo (one uint4 each per thread) ----
        {
            int row = t >> 2;
            int part = (t & 3) * 4;
            const uint32_t* sh = Ahg + (size_t)(m0 + row) * (FF / 2) + ch * 16 + part;
            const uint32_t* sl = Alg + (size_t)(m0 + row) * (FF / 2) + ch * 16 + part;
            uint4 hv = *(const uint4*)sh;
            uint4 lv = *(const uint4*)sl;
            *(uint4*)(Aph + row * ASTR + part) = hv;
            *(uint4*)(Apl + row * ASTR + part) = lv;
        }
        // ---- B chunk: convert on the fly (4 n-cols x 2 k each) ----
        {
            int kp = t >> 5;           // 0..15
            int nq = (t & 31) * 4;     // 0..124
            const float* b0p = Bx + (size_t)(ch * 32 + kp * 2) * WW + n0 + nq;
            const float* b1p = b0p + WW;
            float4 x0 = *(const float4*)(b0p);
            float4 x1 = *(const float4*)(b1p);
            uint32_t* dh = Bph + kp * BSTR + nq;
            uint32_t* dl = Bpl + kp * BSTR + nq;
            dh[0] = bfpack(x0.x, x1.x);
            dh[1] = bfpack(x0.y, x1.y);
            dh[2] = bfpack(x0.z, x1.z);
            dh[3] = bfpack(x0.w, x1.w);
            dl[0] = bfpack(bfres(x0.x), bfres(x1.x));
            dl[1] = bfpack(bfres(x0.y), bfres(x1.y));
            dl[2] = bfpack(bfres(x0.z), bfres(x1.z));
            dl[3] = bfpack(bfres(x0.w), bfres(x1.w));
        }
        __syncthreads();

#pragma unroll
        for (int ks = 0; ks < 2; ks++) {
            int kk2 = ks * 8;
            uint32_t bh[4][2], bl[4][2];
#pragma unroll
            for (int nt = 0; nt < 4; nt++) {
                int n = wn + nt * 8 + g;
                bh[nt][0] = Bph[(tig + kk2) * BSTR + n];
                bh[nt][1] = Bph[(tig + 4 + kk2) * BSTR + n];
                bl[nt][0] = Bpl[(tig + kk2) * BSTR + n];
                bl[nt][1] = Bpl[(tig + 4 + kk2) * BSTR + n];
            }
#pragma unroll
            for (int mt = 0; mt < 2; mt++) {
                int r0 = wm + mt * 16 + g;
                uint32_t ah0 = Aph[r0 * ASTR + tig + kk2];
                uint32_t ah1 = Aph[(r0 + 8) * ASTR + tig + kk2];
                uint32_t ah2 = Aph[r0 * ASTR + tig + 4 + kk2];
                uint32_t ah3 = Aph[(r0 + 8) * ASTR + tig + 4 + kk2];
                uint32_t al0 = Apl[r0 * ASTR + tig + kk2];
                uint32_t al1 = Apl[(r0 + 8) * ASTR + tig + kk2];
                uint32_t al2 = Apl[r0 * ASTR + tig + 4 + kk2];
                uint32_t al3 = Apl[(r0 + 8) * ASTR + tig + 4 + kk2];
#pragma unroll
                for (int nt = 0; nt < 4; nt++) {
                    mma_bf16(acc[mt][nt], ah0, ah1, ah2, ah3, bh[nt][0], bh[nt][1]);
                    mma_bf16(acc[mt][nt], ah0, ah1, ah2, ah3, bl[nt][0], bl[nt][1]);
                    mma_bf16(acc[mt][nt], al0, al1, al2, al3, bh[nt][0], bh[nt][1]);
                }
            }
        }
        __syncthreads();
    }

#pragma unroll
    for (int mt = 0; mt < 2; mt++) {
#pragma unroll
        for (int nt = 0; nt < 4; nt++) {
            int row = m0 + wm + mt * 16 + g;
            int col = n0 + wn + nt * 8 + tig * 2;
            float* p0 = Cp + (size_t)row * WW + col;
            float* p1 = Cp + (size_t)(row + 8) * WW + col;
            if (accum) {
                float2 c0 = *(float2*)p0;
                float2 c1 = *(float2*)p1;
                c0.x += acc[mt][nt][0]; c0.y += acc[mt][nt][1];
                c1.x += acc[mt][nt][2]; c1.y += acc[mt][nt][3];
                *(float2*)p0 = c0;
                *(float2*)p1 = c1;
            } else {
                *(float2*)p0 = make_float2(acc[mt][nt][0], acc[mt][nt][1]);
                *(float2*)p1 = make_float2(acc[mt][nt][2], acc[mt][nt][3]);
            }
        }
    }
}

__global__ __launch_bounds__(512) void gemm_qkv(int layer,
                                                const float* __restrict__ qsrc, const float* __restrict__ msrc,
                                                float* __restrict__ oq, float* __restrict__ ok_,
                                                float* __restrict__ ov) {
    int z = blockIdx.z;
    int which = z >> 4;
    int bc = z & 15;
    int c = bc & (CC - 1);
    const float* X = (which == 0) ? qsrc : msrc;
    float* Out = (which == 0) ? oq : (which == 1) ? ok_ : ov;
    size_t moff = (size_t)(layer * 4 + which) * WMAT_U32 + (size_t)c * FF * (FF / 2);
    gemm_tile(g_wh + moff, g_wl + moff, X + (size_t)bc * FF * WW,
              Out + (size_t)bc * FF * WW, blockIdx.y * 128, blockIdx.x * 128, false);
}

__global__ __launch_bounds__(512) void gemm_one(int layer, const float* __restrict__ X,
                                                float* __restrict__ Out) {
    int bc = blockIdx.z;
    int c = bc & (CC - 1);
    size_t moff = (size_t)(layer * 4 + 3) * WMAT_U32 + (size_t)c * FF * (FF / 2);
    gemm_tile(g_wh + moff, g_wl + moff, X + (size_t)bc * FF * WW,
              Out + (size_t)bc * FF * WW, blockIdx.y * 128, blockIdx.x * 128, true);
}

// ---------------- flash-attention via mma.sync ----------------
#define AT_QSTR 17
#define AT_KSTR 136
#define AT_VSTR 40
__global__ __launch_bounds__(256, 2) void attn_mma_kernel(const float* __restrict__ Q,
                                                          const float* __restrict__ Kb,
                                                          const float* __restrict__ Vb,
                                                          float* __restrict__ Ob) {
    __shared__ uint32_t Qh[128 * AT_QSTR];
    __shared__ uint32_t Ql[128 * AT_QSTR];
    __shared__ uint32_t Kh[16 * AT_KSTR];
    __shared__ uint32_t Kl[16 * AT_KSTR];
    __shared__ uint32_t Vh[64 * AT_VSTR];
    int t = threadIdx.x;
    int lane = t & 31, wid = t >> 5;
    int g = lane >> 2, tig = lane & 3;
    int qt = blockIdx.x;
    int bch = blockIdx.y;
    int h = bch & (HH - 1);
    int bc = bch >> 3;
    size_t base = ((size_t)bc * FF + h * HD) * WW;
    const float* gq = Q + base + qt * 128;
    const float* gk = Kb + base;
    const float* gv = Vb + base;

    {
        int q = t & 127;
        int dp0 = (t >> 7) * 8;
#pragma unroll
        for (int j = 0; j < 8; j++) {
            int dp = dp0 + j;
            float v0 = gq[(size_t)(2 * dp) * WW + q] * 0.0625f;
            float v1 = gq[(size_t)(2 * dp + 1) * WW + q] * 0.0625f;
            Qh[q * AT_QSTR + dp] = bfpack(v0, v1);
            Ql[q * AT_QSTR + dp] = bfpack(bfres(v0), bfres(v1));
        }
    }
    __syncthreads();

    uint32_t qah[2][4], qal[2][4];
    int qr = wid * 16;
#pragma unroll
    for (int s = 0; s < 2; s++) {
        qah[s][0] = Qh[(qr + g) * AT_QSTR + s * 8 + tig];
        qah[s][1] = Qh[(qr + g + 8) * AT_QSTR + s * 8 + tig];
        qah[s][2] = Qh[(qr + g) * AT_QSTR + s * 8 + tig + 4];
        qah[s][3] = Qh[(qr + g + 8) * AT_QSTR + s * 8 + tig + 4];
        qal[s][0] = Ql[(qr + g) * AT_QSTR + s * 8 + tig];
        qal[s][1] = Ql[(qr + g + 8) * AT_QSTR + s * 8 + tig];
        qal[s][2] = Ql[(qr + g) * AT_QSTR + s * 8 + tig + 4];
        qal[s][3] = Ql[(qr + g + 8) * AT_QSTR + s * 8 + tig + 4];
    }

    float M0 = -1e30f, M1 = -1e30f, L0 = 0.f, L1 = 0.f;
    float oac[4][4];
#pragma unroll
    for (int i = 0; i < 4; i++)
#pragma unroll
        for (int j = 0; j < 4; j++) oac[i][j] = 0.f;

    for (int kt = 0; kt < 4; kt++) {
        __syncthreads();
        {
            int dp = t >> 4;
            int kq = (t & 15) * 8;
            const float* r0 = gk + (size_t)(2 * dp) * WW + kt * 128 + kq;
            const float* r1 = r0 + WW;
            float4 a0 = *(const float4*)(r0);
            float4 a1 = *(const float4*)(r0 + 4);
            float4 b0 = *(const float4*)(r1);
            float4 b1 = *(const float4*)(r1 + 4);
            float ra[8] = {a0.x, a0.y, a0.z, a0.w, a1.x, a1.y, a1.z, a1.w};
            float rb[8] = {b0.x, b0.y, b0.z, b0.w, b1.x, b1.y, b1.z, b1.w};
            uint32_t* dh = Kh + dp * AT_KSTR + kq;
            uint32_t* dl = Kl + dp * AT_KSTR + kq;
#pragma unroll
            for (int j = 0; j < 8; j++) {
                dh[j] = bfpack(ra[j], rb[j]);
                dl[j] = bfpack(bfres(ra[j]), bfres(rb[j]));
            }
        }
        {
            int d = t & 31;
            int kp0 = (t >> 5) * 8;
            const float* r = gv + (size_t)d * WW + kt * 128 + kp0 * 2;
            float4 x0 = *(const float4*)(r);
            float4 x1 = *(const float4*)(r + 4);
            float4 x2 = *(const float4*)(r + 8);
            float4 x3 = *(const float4*)(r + 12);
            Vh[(kp0 + 0) * AT_VSTR + d] = bfpack(x0.x, x0.y);
            Vh[(kp0 + 1) * AT_VSTR + d] = bfpack(x0.z, x0.w);
            Vh[(kp0 + 2) * AT_VSTR + d] = bfpack(x1.x, x1.y);
            Vh[(kp0 + 3) * AT_VSTR + d] = bfpack(x1.z, x1.w);
            Vh[(kp0 + 4) * AT_VSTR + d] = bfpack(x2.x, x2.y);
            Vh[(kp0 + 5) * AT_VSTR + d] = bfpack(x2.z, x2.w);
            Vh[(kp0 + 6) * AT_VSTR + d] = bfpack(x3.x, x3.y);
            Vh[(kp0 + 7) * AT_VSTR + d] = bfpack(x3.z, x3.w);
        }
        __syncthreads();

        float sa[16][4];
#pragma unroll
        for (int nt = 0; nt < 16; nt++) {
            sa[nt][0] = 0.f; sa[nt][1] = 0.f; sa[nt][2] = 0.f; sa[nt][3] = 0.f;
        }
#pragma unroll
        for (int nt = 0; nt < 16; nt++) {
            int n = nt * 8 + g;
            uint32_t kh0 = Kh[(tig) * AT_KSTR + n];
            uint32_t kh1 = Kh[(tig + 4) * AT_KSTR + n];
            uint32_t kh2 = Kh[(tig + 8) * AT_KSTR + n];
            uint32_t kh3 = Kh[(tig + 12) * AT_KSTR + n];
            uint32_t kl0 = Kl[(tig) * AT_KSTR + n];
            uint32_t kl1 = Kl[(tig + 4) * AT_KSTR + n];
            uint32_t kl2 = Kl[(tig + 8) * AT_KSTR + n];
            uint32_t kl3 = Kl[(tig + 12) * AT_KSTR + n];
            mma_bf16(sa[nt], qah[0][0], qah[0][1], qah[0][2], qah[0][3], kh0, kh1);
            mma_bf16(sa[nt], qah[1][0], qah[1][1], qah[1][2], qah[1][3], kh2, kh3);
            mma_bf16(sa[nt], qah[0][0], qah[0][1], qah[0][2], qah[0][3], kl0, kl1);
            mma_bf16(sa[nt], qah[1][0], qah[1][1], qah[1][2], qah[1][3], kl2, kl3);
            mma_bf16(sa[nt], qal[0][0], qal[0][1], qal[0][2], qal[0][3], kh0, kh1);
            mma_bf16(sa[nt], qal[1][0], qal[1][1], qal[1][2], qal[1][3], kh2, kh3);
        }

        float mx0 = -1e30f, mx1 = -1e30f;
#pragma unroll
        for (int nt = 0; nt < 16; nt++) {
            mx0 = fmaxf(mx0, fmaxf(sa[nt][0], sa[nt][1]));
            mx1 = fmaxf(mx1, fmaxf(sa[nt][2], sa[nt][3]));
        }
        mx0 = fmaxf(mx0, __shfl_xor_sync(0xFFFFFFFFu, mx0, 1));
        mx0 = fmaxf(mx0, __shfl_xor_sync(0xFFFFFFFFu, mx0, 2));
        mx1 = fmaxf(mx1, __shfl_xor_sync(0xFFFFFFFFu, mx1, 1));
        mx1 = fmaxf(mx1, __shfl_xor_sync(0xFFFFFFFFu, mx1, 2));
        float Mn0 = fmaxf(M0, mx0), Mn1 = fmaxf(M1, mx1);
        float c0 = __expf(M0 - Mn0), c1 = __expf(M1 - Mn1);
        float ps0 = 0.f, ps1 = 0.f;
#pragma unroll
        for (int nt = 0; nt < 16; nt++) {
            sa[nt][0] = __expf(sa[nt][0] - Mn0);
            sa[nt][1] = __expf(sa[nt][1] - Mn0);
            sa[nt][2] = __expf(sa[nt][2] - Mn1);
            sa[nt][3] = __expf(sa[nt][3] - Mn1);
            ps0 += sa[nt][0] + sa[nt][1];
            ps1 += sa[nt][2] + sa[nt][3];
        }
        ps0 += __shfl_xor_sync(0xFFFFFFFFu, ps0, 1);
        ps0 += __shfl_xor_sync(0xFFFFFFFFu, ps0, 2);
        ps1 += __shfl_xor_sync(0xFFFFFFFFu, ps1, 1);
        ps1 += __shfl_xor_sync(0xFFFFFFFFu, ps1, 2);
        L0 = L0 * c0 + ps0;
        L1 = L1 * c1 + ps1;
        M0 = Mn0; M1 = Mn1;
#pragma unroll
        for (int nt4 = 0; nt4 < 4; nt4++) {
            oac[nt4][0] *= c0; oac[nt4][1] *= c0;
            oac[nt4][2] *= c1; oac[nt4][3] *= c1;
        }

#pragma unroll
        for (int s8 = 0; s8 < 8; s8++) {
            uint32_t pa0 = bfpack(sa[2 * s8][0], sa[2 * s8][1]);
            uint32_t pa1 = bfpack(sa[2 * s8][2], sa[2 * s8][3]);
            uint32_t pa2 = bfpack(sa[2 * s8 + 1][0], sa[2 * s8 + 1][1]);
            uint32_t pa3 = bfpack(sa[2 * s8 + 1][2], sa[2 * s8 + 1][3]);
#pragma unroll
            for (int nt4 = 0; nt4 < 4; nt4++) {
                int d = nt4 * 8 + g;
                uint32_t vb0 = Vh[(s8 * 8 + tig) * AT_VSTR + d];
                uint32_t vb1 = Vh[(s8 * 8 + tig + 4) * AT_VSTR + d];
                mma_bf16(oac[nt4], pa0, pa1, pa2, pa3, vb0, vb1);
            }
        }
    }

    float il0 = 1.f / L0, il1 = 1.f / L1;
    int q0 = qt * 128 + qr + g;
#pragma unroll
    for (int nt4 = 0; nt4 < 4; nt4++) {
        int d = nt4 * 8 + 2 * tig;
        float* o0 = Ob + base + (size_t)d * WW;
        float* o1 = Ob + base + (size_t)(d + 1) * WW;
        o0[q0] = oac[nt4][0] * il0;
        o1[q0] = oac[nt4][1] * il0;
        o0[q0 + 8] = oac[nt4][2] * il1;
        o1[q0 + 8] = oac[nt4][3] * il1;
    }
}

// ---------------- combined: h = x AND out-x-half = x ----------------
__global__ void copy2_kernel(float* __restrict__ dst, const float* __restrict__ src,
                             float* __restrict__ out) {
    size_t i = (size_t)blockIdx.x * blockDim.x + threadIdx.x;
    size_t stride = (size_t)gridDim.x * blockDim.x;
    for (; i < NTOT; i += stride) {
        float v = src[i];
        dst[i] = v;
        size_t b = i >> 20;
        size_t inner = i & (CHUNK - 1);
        out[b * 2 * CHUNK + inner] = v;
    }
}

// ---------------- LayerNorm over features ----------------
__global__ void ln_kernel(const float* __restrict__ src, const float* __restrict__ g,
                          const float* __restrict__ bet, float* __restrict__ dst) {
    int bc = blockIdx.y;
    int c = bc & (CC - 1);
    int tx = threadIdx.x;
    int fy = threadIdx.y;
    int w = blockIdx.x * 64 + tx;
    const float* p = src + (size_t)bc * FF * WW + w;
    float s = 0.f, s2 = 0.f;
#pragma unroll 8
    for (int f = fy * 32; f < fy * 32 + 32; f++) {
        float v = p[(size_t)f * WW];
        s += v; s2 += v * v;
    }
    __shared__ float red[2][8][64];
    red[0][fy][tx] = s;
    red[1][fy][tx] = s2;
    __syncthreads();
    float S = 0.f, S2 = 0.f;
#pragma unroll
    for (int j = 0; j < 8; j++) { S += red[0][j][tx]; S2 += red[1][j][tx]; }
    float m = S * (1.0f / FF);
    float rs = rsqrtf(S2 * (1.0f / FF) - m * m + 1e-5f);
    const float* gc = g + c * FF;
    const float* bb = bet + c * FF;
    float* q = dst + (size_t)bc * FF * WW + w;
#pragma unroll 8
    for (int f = fy * 32; f < fy * 32 + 32; f++) {
        q[(size_t)f * WW] = (p[(size_t)f * WW] - m) * rs * gc[f] + bb[f];
    }
}

// ---------------- fused QKV 1x3 channel-mix conv + RoPE (f32x2 math) ----------------
__global__ __launch_bounds__(128) void convrope3_kernel(
    const float* __restrict__ tq, const float* __restrict__ tk, const float* __restrict__ tv,
    const float* __restrict__ Kq, const float* __restrict__ Kk, const float* __restrict__ Kv,
    const float* __restrict__ bq, const float* __restrict__ bk, const float* __restrict__ bv,
    float* __restrict__ oq, float* __restrict__ ok_, float* __restrict__ ov) {
    int which = blockIdx.z >> 1;
    int b = blockIdx.z & 1;
    const float* src = (which == 0) ? tq : (which == 1) ? tk : tv;
    const float* Kw  = (which == 0) ? Kq : (which == 1) ? Kk : Kv;
    const float* bias = (which == 0) ? bq : (which == 1) ? bk : bv;
    float* dst = (which == 0) ? oq : (which == 1) ? ok_ : ov;

    __shared__ unsigned long long sK2[64][4];
    __shared__ float sB2[CC];
    int t = threadIdx.x;
    if (t < 64) {
        float k0 = Kw[t * 3], k1 = Kw[t * 3 + 1], k2 = Kw[t * 3 + 2];
        sK2[t][0] = pk2(k0, k0);
        sK2[t][1] = pk2(k1, k1);
        sK2[t][2] = pk2(k2, k2);
    }
    if (t < CC) sB2[t] = bias[t];
    __syncthreads();

    int w = blockIdx.x * 128 + t;
    int f0 = blockIdx.y * 2;
    unsigned long long y01[8];
#pragma unroll
    for (int co = 0; co < 8; co++) y01[co] = pk2(sB2[co], sB2[co]);
#pragma unroll
    for (int ci = 0; ci < 8; ci++) {
        const float* xp = src + ((size_t)(b * CC + ci) * FF + f0) * WW + w;
        float l0 = (w > 0) ? xp[-1] : 0.f;
        float c0 = xp[0];
        float r0 = (w < WW - 1) ? xp[1] : 0.f;
        float l1 = (w > 0) ? xp[WW - 1] : 0.f;
        float c1 = xp[WW];
        float r1 = (w < WW - 1) ? xp[WW + 1] : 0.f;
        unsigned long long l01 = pk2(l0, l1);
        unsigned long long c01 = pk2(c0, c1);
        unsigned long long r01 = pk2(r0, r1);
#pragma unroll
        for (int co = 0; co < 8; co++) {
            const ulonglong2 kk01 = *(const ulonglong2*)&sK2[co * 8 + ci][0];
            unsigned long long kk2v = sK2[co * 8 + ci][2];
            fma2(y01[co], kk01.x, l01);
            fma2(y01[co], kk01.y, c01);
            fma2(y01[co], kk2v, r01);
        }
    }
    int d = f0 & (HD - 1);
    float theta = expf(-(float)d * (9.210340371976184f / (float)HD));
    float sn, cs;
    sincosf((float)w * theta, &sn, &cs);
    bool dorope = (which < 2);
#pragma unroll
    for (int co = 0; co < 8; co++) {
        float2 y = up2(y01[co]);
        float* op = dst + ((size_t)(b * CC + co) * FF + f0) * WW + w;
        if (dorope) {
            op[0]  = y.x * cs - y.y * sn;
            op[WW] = y.y * cs + y.x * sn;
        } else {
            op[0] = y.x;
            op[WW] = y.y;
        }
    }
}

// ---------------- fused depthwise: out = sqrelu(conv11(z)) + conv7(z) ----------------
__global__ void dwfused_kernel(const float* __restrict__ z, const float* __restrict__ w11,
                               const float* __restrict__ b11, const float* __restrict__ w7,
                               const float* __restrict__ b7, float* __restrict__ out) {
    int w = blockIdx.x * 128 + threadIdx.x;
    int f = blockIdx.y;
    int bc = blockIdx.z;
    int c = bc & 7;
    const float* zp = z + (size_t)bc * FF * WW + w;
    float a = b11[c], b2 = b7[c];
#pragma unroll
    for (int k = 0; k < 11; k++) {
        int fv = f + k - 5;
        if (fv >= 0 && fv < FF) {
            float v = zp[(size_t)fv * WW];
            a += w11[c * 11 + k] * v;
            if (k >= 2 && k <= 8) b2 += w7[c * 7 + (k - 2)] * v;
        }
    }
    float r = fmaxf(a, 0.f);
    out[((size_t)bc * FF + f) * WW + w] = r * r + b2;
}

// ---------------- depthwise 7-tap conv accumulated into h ----------------
__global__ void dwc2_acc_kernel(const float* __restrict__ z, const float* __restrict__ w7,
                                const float* __restrict__ b7, float* __restrict__ h) {
    int w = blockIdx.x * 128 + threadIdx.x;
    int f = blockIdx.y;
    int bc = blockIdx.z;
    int c = bc & 7;
    const float* zp = z + (size_t)bc * FF * WW + w;
    float s = b7[c];
#pragma unroll
    for (int k = 0; k < 7; k++) {
        int fv = f + k - 3;
        if (fv >= 0 && fv < FF) s += w7[c * 7 + k] * zp[(size_t)fv * WW];
    }
    h[((size_t)bc * FF + f) * WW + w] += s;
}

// ---------------- FFN ----------------
__global__ void ffn1_kernel(const float* __restrict__ z, const float* __restrict__ w3,
                            float* __restrict__ u) {
    int tx = threadIdx.x;
    int fy = threadIdx.y;
    int w = blockIdx.x * 128 + tx;
    int bc = blockIdx.y;
    int c = bc & 7;
    const float* zp = z + (size_t)bc * FF * WW + w;
    const float* wp = w3 + (size_t)c * EE * FF;
    float s0 = 0.f, s1 = 0.f, s2 = 0.f, s3 = 0.f;
#pragma unroll 4
    for (int f = fy * 128; f < fy * 128 + 128; f++) {
        float zv = zp[(size_t)f * WW];
        s0 += wp[f] * zv;
        s1 += wp[FF + f] * zv;
        s2 += wp[2 * FF + f] * zv;
        s3 += wp[3 * FF + f] * zv;
    }
    __shared__ float red[4][2][128];
    red[0][fy][tx] = s0; red[1][fy][tx] = s1;
    red[2][fy][tx] = s2; red[3][fy][tx] = s3;
    __syncthreads();
    if (fy == 0) {
        s0 = red[0][0][tx] + red[0][1][tx];
        s1 = red[1][0][tx] + red[1][1][tx];
        s2 = red[2][0][tx] + red[2][1][tx];
        s3 = red[3][0][tx] + red[3][1][tx];
        float* up = u + (size_t)bc * EE * WW + w;
        float r;
        r = fmaxf(s0, 0.f); up[0]      = r * r;
        r = fmaxf(s1, 0.f); up[WW]     = r * r;
        r = fmaxf(s2, 0.f); up[2 * WW] = r * r;
        r = fmaxf(s3, 0.f); up[3 * WW] = r * r;
    }
}

__global__ void ffn2_out_kernel(const float* __restrict__ u, const float* __restrict__ w4,
                                const float* __restrict__ h, float* __restrict__ out) {
    int w = blockIdx.x * 128 + threadIdx.x;
    int f = blockIdx.y;
    int bc = blockIdx.z;
    int c = bc & 7;
    int b = bc >> 3;
    const float* up = u + (size_t)bc * EE * WW + w;
    const float* wp = w4 + ((size_t)c * FF + f) * EE;
    float s = wp[0] * up[0] + wp[1] * up[WW] + wp[2] * up[2 * WW] + wp[3] * up[3 * WW];
    out[(((size_t)b * 2 * CC + CC + c) * FF + f) * WW + w] =
        h[((size_t)bc * FF + f) * WW + w] + s;
}

// ================================================================================
extern "C" void kernel_launch(void* const* d_in, const int* in_sizes, int n_in,
                              void* d_out, int out_size) {
    const float* x    = (const float*)d_in[0];
    const float* skip = (const float*)d_in[1];
    const float* Wq   = (const float*)d_in[2];
    const float* Kq   = (const float*)d_in[3];
    const float* bq   = (const float*)d_in[4];
    const float* Wk   = (const float*)d_in[5];
    const float* Kk   = (const float*)d_in[6];
    const float* bk   = (const float*)d_in[7];
    const float* Wv   = (const float*)d_in[8];
    const float* Kv   = (const float*)d_in[9];
    const float* bv   = (const float*)d_in[10];
    const float* Wo   = (const float*)d_in[11];
    const float* ng   = (const float*)d_in[12];
    const float* nb   = (const float*)d_in[13];
    const float* c1aw = (const float*)d_in[14];
    const float* c1ab = (const float*)d_in[15];
    const float* c1bw = (const float*)d_in[16];
    const float* c1bb = (const float*)d_in[17];
    const float* c2w  = (const float*)d_in[18];
    const float* c2b  = (const float*)d_in[19];
    const float* w3   = (const float*)d_in[20];
    const float* w4   = (const float*)d_in[21];
    float* out = (float*)d_out;

    float *ph, *pz, *pq, *pk, *pv, *ptq, *ptk, *ptv, *pu;
    cudaGetSymbolAddress((void**)&ph, g_h);
    cudaGetSymbolAddress((void**)&pz, g_z);
    cudaGetSymbolAddress((void**)&pq, g_q);
    cudaGetSymbolAddress((void**)&pk, g_k);
    cudaGetSymbolAddress((void**)&pv, g_v);
    cudaGetSymbolAddress((void**)&ptq, g_t);
    cudaGetSymbolAddress((void**)&ptk, g_t2);
    cudaGetSymbolAddress((void**)&ptv, g_t3);
    cudaGetSymbolAddress((void**)&pu, g_u);

    const dim3 gemm_grid(4, 2, BC);
    const dim3 gemm3_grid(4, 2, 3 * BC);
    const dim3 conv3_grid(4, FF / 2, 3 * BB);
    const dim3 ln_grid(8, BC);
    const dim3 ln_block(64, 8);
    const dim3 elw_grid(4, FF, BC);
    const dim3 attn_grid(4, BC * HH);

    const size_t KFF = (size_t)CC * CC * 3;

    auto attn_block = [&](int i, const float* qsrc, const float* msrc) {
        gemm_qkv<<<gemm3_grid, 512>>>(i, qsrc, msrc, ptq, ptk, ptv);
        convrope3_kernel<<<conv3_grid, 128>>>(ptq, ptk, ptv,
                                              Kq + (size_t)i * KFF, Kk + (size_t)i * KFF, Kv + (size_t)i * KFF,
                                              bq + i * CC, bk + i * CC, bv + i * CC,
                                              pq, pk, pv);
        attn_mma_kernel<<<attn_grid, 256>>>(pq, pk, pv, ptq);
        gemm_one<<<gemm_grid, 512>>>(i, ptq, ph);
    };

    // weight pre-conversion (runs each replay; ~3 us)
    wprep_kernel<<<4096, 512>>>(Wq, Wk, Wv, Wo);

    // h = x; out-x-half = x
    copy2_kernel<<<2048, 512>>>(ph, x, out);

    // z = LN0(h); h += attn0(z,z); h += attn1(z, skip)
    ln_kernel<<<ln_grid, ln_block>>>(ph, ng + 0 * CC * FF, nb + 0 * CC * FF, pz);
    attn_block(0, pz, pz);
    attn_block(1, pz, skip);

    // conv block
    ln_kernel<<<ln_grid, ln_block>>>(ph, ng + 1 * CC * FF, nb + 1 * CC * FF, pz);
    dwfused_kernel<<<elw_grid, 128>>>(pz, c1aw, c1ab, c1bw, c1bb, pq);
    ln_kernel<<<ln_grid, ln_block>>>(pq, ng + 2 * CC * FF, nb + 2 * CC * FF, pz);
    dwc2_acc_kernel<<<elw_grid, 128>>>(pz, c2w, c2b, ph);

    // attn2 (self) and attn3 (skip)
    ln_kernel<<<ln_grid, ln_block>>>(ph, ng + 3 * CC * FF, nb + 3 * CC * FF, pz);
    attn_block(2, pz, pz);
    ln_kernel<<<ln_grid, ln_block>>>(ph, ng + 4 * CC * FF, nb + 4 * CC * FF, pz);
    attn_block(3, pz, skip);

    // FFN (+ fused concat)
    ln_kernel<<<ln_grid, ln_block>>>(ph, ng + 5 * CC * FF, nb + 5 * CC * FF, pz);
    ffn1_kernel<<<dim3(4, BC), dim3(128, 2)>>>(pz, w3, pu);
    ffn2_out_kernel<<<elw_grid, 128>>>(pu, w4, ph, out);
    (void)in_sizes; (void)n_in; (void)out_size;
}

// round 11
// speedup vs baseline: 2.5298x; 1.0484x over previous
#include <cuda_runtime.h>
#include <cuda_bf16.h>
#include <math.h>
#include <stdint.h>

#define BB 2
#define CC 8
#define FF 256
#define WW 512
#define HH 8
#define HD 32
#define EE 4
#define BC (BB*CC)
#define NTOT ((size_t)BB*CC*FF*WW)
#define CHUNK ((size_t)CC*FF*WW)       // 2^20
#define WMAT_U32 (CC*FF*(FF/2))        // 262144 uint32 per weight matrix

// ---------------- scratch (static device globals; no allocation) ----------------
__device__ float g_h[BB*CC*FF*WW];
__device__ float g_z[BB*CC*FF*WW];
__device__ float g_q[BB*CC*FF*WW];
__device__ float g_k[BB*CC*FF*WW];
__device__ float g_v[BB*CC*FF*WW];
__device__ float g_t[BB*CC*FF*WW];
__device__ float g_t2[BB*CC*FF*WW];
__device__ float g_t3[BB*CC*FF*WW];
__device__ float g_u[BB*CC*EE*WW];
__device__ uint32_t g_wh[16 * WMAT_U32];   // bf16-hi of all 16 weight mats, k-pair packed
__device__ uint32_t g_wl[16 * WMAT_U32];   // bf16-lo residuals

// ---------------- packed f32x2 helpers ----------------
__device__ __forceinline__ unsigned long long pk2(float lo, float hi) {
    unsigned long long r;
    asm("mov.b64 %0, {%1, %2};" : "=l"(r) : "f"(lo), "f"(hi));
    return r;
}
__device__ __forceinline__ void fma2(unsigned long long& d, unsigned long long a, unsigned long long b) {
    asm("fma.rn.f32x2 %0, %1, %2, %0;" : "+l"(d) : "l"(a), "l"(b));
}
__device__ __forceinline__ float2 up2(unsigned long long v) {
    float2 r;
    asm("mov.b64 {%0, %1}, %2;" : "=f"(r.x), "=f"(r.y) : "l"(v));
    return r;
}

// ---------------- bf16 pack helpers ----------------
__device__ __forceinline__ uint32_t bfpack(float a, float b) {
    uint32_t lo = (uint32_t)__bfloat16_as_ushort(__float2bfloat16(a));
    uint32_t hi = (uint32_t)__bfloat16_as_ushort(__float2bfloat16(b));
    return lo | (hi << 16);
}
__device__ __forceinline__ float bfres(float x) {   // x - bf16(x)
    return x - __bfloat162float(__float2bfloat16(x));
}

// ---------------- warp mma.sync / ldmatrix ----------------
__device__ __forceinline__ void mma_bf16(float* d, uint32_t a0, uint32_t a1, uint32_t a2, uint32_t a3,
                                         uint32_t b0, uint32_t b1) {
    asm volatile(
        "mma.sync.aligned.m16n8k16.row.col.f32.bf16.bf16.f32 "
        "{%0,%1,%2,%3}, {%4,%5,%6,%7}, {%8,%9}, {%0,%1,%2,%3};"
        : "+f"(d[0]), "+f"(d[1]), "+f"(d[2]), "+f"(d[3])
        : "r"(a0), "r"(a1), "r"(a2), "r"(a3), "r"(b0), "r"(b1));
}
__device__ __forceinline__ void ldsm_x4(uint32_t* r, uint32_t addr) {
    asm volatile("ldmatrix.sync.aligned.m8n8.x4.shared.b16 {%0,%1,%2,%3}, [%4];"
                 : "=r"(r[0]), "=r"(r[1]), "=r"(r[2]), "=r"(r[3]) : "r"(addr));
}
__device__ __forceinline__ uint32_t smem_u32(const void* p) {
    uint32_t a;
    asm("{ .reg .u64 t; cvta.to.shared.u64 t, %1; cvt.u32.u64 %0, t; }" : "=r"(a) : "l"(p));
    return a;
}

// ---------------- weight pre-conversion: fp32 -> k-pair packed bf16 hi/lo ----------------
__global__ void wprep_kernel(const float* __restrict__ Wq, const float* __restrict__ Wk,
                             const float* __restrict__ Wv, const float* __restrict__ Wo) {
    size_t total = 16ull * WMAT_U32;
    for (size_t i = (size_t)blockIdx.x * blockDim.x + threadIdx.x; i < total;
         i += (size_t)gridDim.x * blockDim.x) {
        int mat = (int)(i / WMAT_U32);
        size_t inner = i % WMAT_U32;
        int layer = mat >> 2, kind = mat & 3;
        const float* src = (kind == 0) ? Wq : (kind == 1) ? Wk : (kind == 2) ? Wv : Wo;
        float2 v = *(const float2*)(src + (size_t)layer * CC * FF * FF + inner * 2);
        g_wh[i] = bfpack(v.x, v.y);
        g_wl[i] = bfpack(bfres(v.x), bfres(v.y));
    }
}

// ---------------- tensor-core GEMM tile: 512 threads, prefetch + ldmatrix ----------------
#define ASTR 20
#define BSTR 132
__device__ __forceinline__ void gemm_tile(const uint32_t* __restrict__ Ahg, const uint32_t* __restrict__ Alg,
                                          const float* __restrict__ Bx,
                                          float* __restrict__ Cp, int m0, int n0, bool accum) {
    __shared__ uint32_t Aph[128 * ASTR];
    __shared__ uint32_t Apl[128 * ASTR];
    __shared__ uint32_t Bph[16 * BSTR];
    __shared__ uint32_t Bpl[16 * BSTR];
    int t = threadIdx.x;
    int lane = t & 31, wid = t >> 5;
    int wm = (wid >> 2) * 32;
    int wn = (wid & 3) * 32;
    int g = lane >> 2, tig = lane & 3;

    // ldmatrix lane->element map (A fragments)
    int lrow = ((lane >> 3) & 1) * 8 + (lane & 7);
    int lcol = (lane >> 4) * 4;
    uint32_t aph_u32 = smem_u32(Aph);
    uint32_t apl_u32 = smem_u32(Apl);

    // loader indices
    int arow = t >> 2, apart = (t & 3) * 4;
    const uint32_t* aghp = Ahg + (size_t)(m0 + arow) * (FF / 2) + apart;
    const uint32_t* aglp = Alg + (size_t)(m0 + arow) * (FF / 2) + apart;
    int bkp = t >> 5, bnq = (t & 31) * 4;
    const float* bgp = Bx + (size_t)(bkp * 2) * WW + n0 + bnq;

    float acc[2][4][4];
#pragma unroll
    for (int mt = 0; mt < 2; mt++)
#pragma unroll
        for (int nt = 0; nt < 4; nt++)
#pragma unroll
            for (int j = 0; j < 4; j++) acc[mt][nt][j] = 0.f;

    // prefetch chunk 0
    uint4 pf_ah = *(const uint4*)(aghp);
    uint4 pf_al = *(const uint4*)(aglp);
    float4 pf_b0 = *(const float4*)(bgp);
    float4 pf_b1 = *(const float4*)(bgp + WW);

    for (int ch = 0; ch < 8; ch++) {
        // store prefetched chunk into smem (conversion for B happens here)
        *(uint4*)(Aph + arow * ASTR + apart) = pf_ah;
        *(uint4*)(Apl + arow * ASTR + apart) = pf_al;
        {
            uint32_t* dh = Bph + bkp * BSTR + bnq;
            uint32_t* dl = Bpl + bkp * BSTR + bnq;
            dh[0] = bfpack(pf_b0.x, pf_b1.x);
            dh[1] = bfpack(pf_b0.y, pf_b1.y);
            dh[2] = bfpack(pf_b0.z, pf_b1.z);
            dh[3] = bfpack(pf_b0.w, pf_b1.w);
            dl[0] = bfpack(bfres(pf_b0.x), bfres(pf_b1.x));
            dl[1] = bfpack(bfres(pf_b0.y), bfres(pf_b1.y));
            dl[2] = bfpack(bfres(pf_b0.z), bfres(pf_b1.z));
            dl[3] = bfpack(bfres(pf_b0.w), bfres(pf_b1.w));
        }
        __syncthreads();

        // issue prefetch for next chunk BEFORE compute (latency hides under mmas)
        if (ch < 7) {
            pf_ah = *(const uint4*)(aghp + (ch + 1) * 16);
            pf_al = *(const uint4*)(aglp + (ch + 1) * 16);
            pf_b0 = *(const float4*)(bgp + (size_t)(ch + 1) * 32 * WW);
            pf_b1 = *(const float4*)(bgp + (size_t)(ch + 1) * 32 * WW + WW);
        }

#pragma unroll
        for (int ks = 0; ks < 2; ks++) {
            int kk2 = ks * 8;
            uint32_t bh[4][2], bl[4][2];
#pragma unroll
            for (int nt = 0; nt < 4; nt++) {
                int n = wn + nt * 8 + g;
                bh[nt][0] = Bph[(tig + kk2) * BSTR + n];
                bh[nt][1] = Bph[(tig + 4 + kk2) * BSTR + n];
                bl[nt][0] = Bpl[(tig + kk2) * BSTR + n];
                bl[nt][1] = Bpl[(tig + 4 + kk2) * BSTR + n];
            }
#pragma unroll
            for (int mt = 0; mt < 2; mt++) {
                uint32_t off = (uint32_t)(((wm + mt * 16 + lrow) * ASTR + kk2 + lcol) * 4);
                uint32_t ah[4], al[4];
                ldsm_x4(ah, aph_u32 + off);
                ldsm_x4(al, apl_u32 + off);
#pragma unroll
                for (int nt = 0; nt < 4; nt++) {
                    mma_bf16(acc[mt][nt], ah[0], ah[1], ah[2], ah[3], bh[nt][0], bh[nt][1]);
                    mma_bf16(acc[mt][nt], ah[0], ah[1], ah[2], ah[3], bl[nt][0], bl[nt][1]);
                    mma_bf16(acc[mt][nt], al[0], al[1], al[2], al[3], bh[nt][0], bh[nt][1]);
                }
            }
        }
        __syncthreads();
    }

#pragma unroll
    for (int mt = 0; mt < 2; mt++) {
#pragma unroll
        for (int nt = 0; nt < 4; nt++) {
            int row = m0 + wm + mt * 16 + g;
            int col = n0 + wn + nt * 8 + tig * 2;
            float* p0 = Cp + (size_t)row * WW + col;
            float* p1 = Cp + (size_t)(row + 8) * WW + col;
            if (accum) {
                float2 c0 = *(float2*)p0;
                float2 c1 = *(float2*)p1;
                c0.x += acc[mt][nt][0]; c0.y += acc[mt][nt][1];
                c1.x += acc[mt][nt][2]; c1.y += acc[mt][nt][3];
                *(float2*)p0 = c0;
                *(float2*)p1 = c1;
            } else {
                *(float2*)p0 = make_float2(acc[mt][nt][0], acc[mt][nt][1]);
                *(float2*)p1 = make_float2(acc[mt][nt][2], acc[mt][nt][3]);
            }
        }
    }
}

__global__ __launch_bounds__(512) void gemm_qkv(int layer,
                                                const float* __restrict__ qsrc, const float* __restrict__ msrc,
                                                float* __restrict__ oq, float* __restrict__ ok_,
                                                float* __restrict__ ov) {
    int z = blockIdx.z;
    int which = z >> 4;
    int bc = z & 15;
    int c = bc & (CC - 1);
    const float* X = (which == 0) ? qsrc : msrc;
    float* Out = (which == 0) ? oq : (which == 1) ? ok_ : ov;
    size_t moff = (size_t)(layer * 4 + which) * WMAT_U32 + (size_t)c * FF * (FF / 2);
    gemm_tile(g_wh + moff, g_wl + moff, X + (size_t)bc * FF * WW,
              Out + (size_t)bc * FF * WW, blockIdx.y * 128, blockIdx.x * 128, false);
}

__global__ __launch_bounds__(512) void gemm_one(int layer, const float* __restrict__ X,
                                                float* __restrict__ Out) {
    int bc = blockIdx.z;
    int c = bc & (CC - 1);
    size_t moff = (size_t)(layer * 4 + 3) * WMAT_U32 + (size_t)c * FF * (FF / 2);
    gemm_tile(g_wh + moff, g_wl + moff, X + (size_t)bc * FF * WW,
              Out + (size_t)bc * FF * WW, blockIdx.y * 128, blockIdx.x * 128, true);
}

// ---------------- flash-attention via mma.sync ----------------
#define AT_QSTR 17
#define AT_KSTR 136
#define AT_VSTR 40
__global__ __launch_bounds__(256, 2) void attn_mma_kernel(const float* __restrict__ Q,
                                                          const float* __restrict__ Kb,
                                                          const float* __restrict__ Vb,
                                                          float* __restrict__ Ob) {
    __shared__ uint32_t Qh[128 * AT_QSTR];
    __shared__ uint32_t Ql[128 * AT_QSTR];
    __shared__ uint32_t Kh[16 * AT_KSTR];
    __shared__ uint32_t Kl[16 * AT_KSTR];
    __shared__ uint32_t Vh[64 * AT_VSTR];
    int t = threadIdx.x;
    int lane = t & 31, wid = t >> 5;
    int g = lane >> 2, tig = lane & 3;
    int qt = blockIdx.x;
    int bch = blockIdx.y;
    int h = bch & (HH - 1);
    int bc = bch >> 3;
    size_t base = ((size_t)bc * FF + h * HD) * WW;
    const float* gq = Q + base + qt * 128;
    const float* gk = Kb + base;
    const float* gv = Vb + base;

    {
        int q = t & 127;
        int dp0 = (t >> 7) * 8;
#pragma unroll
        for (int j = 0; j < 8; j++) {
            int dp = dp0 + j;
            float v0 = gq[(size_t)(2 * dp) * WW + q] * 0.0625f;
            float v1 = gq[(size_t)(2 * dp + 1) * WW + q] * 0.0625f;
            Qh[q * AT_QSTR + dp] = bfpack(v0, v1);
            Ql[q * AT_QSTR + dp] = bfpack(bfres(v0), bfres(v1));
        }
    }
    __syncthreads();

    uint32_t qah[2][4], qal[2][4];
    int qr = wid * 16;
#pragma unroll
    for (int s = 0; s < 2; s++) {
        qah[s][0] = Qh[(qr + g) * AT_QSTR + s * 8 + tig];
        qah[s][1] = Qh[(qr + g + 8) * AT_QSTR + s * 8 + tig];
        qah[s][2] = Qh[(qr + g) * AT_QSTR + s * 8 + tig + 4];
        qah[s][3] = Qh[(qr + g + 8) * AT_QSTR + s * 8 + tig + 4];
        qal[s][0] = Ql[(qr + g) * AT_QSTR + s * 8 + tig];
        qal[s][1] = Ql[(qr + g + 8) * AT_QSTR + s * 8 + tig];
        qal[s][2] = Ql[(qr + g) * AT_QSTR + s * 8 + tig + 4];
        qal[s][3] = Ql[(qr + g + 8) * AT_QSTR + s * 8 + tig + 4];
    }

    float M0 = -1e30f, M1 = -1e30f, L0 = 0.f, L1 = 0.f;
    float oac[4][4];
#pragma unroll
    for (int i = 0; i < 4; i++)
#pragma unroll
        for (int j = 0; j < 4; j++) oac[i][j] = 0.f;

    for (int kt = 0; kt < 4; kt++) {
        __syncthreads();
        {
            int dp = t >> 4;
            int kq = (t & 15) * 8;
            const float* r0 = gk + (size_t)(2 * dp) * WW + kt * 128 + kq;
            const float* r1 = r0 + WW;
            float4 a0 = *(const float4*)(r0);
            float4 a1 = *(const float4*)(r0 + 4);
            float4 b0 = *(const float4*)(r1);
            float4 b1 = *(const float4*)(r1 + 4);
            float ra[8] = {a0.x, a0.y, a0.z, a0.w, a1.x, a1.y, a1.z, a1.w};
            float rb[8] = {b0.x, b0.y, b0.z, b0.w, b1.x, b1.y, b1.z, b1.w};
            uint32_t* dh = Kh + dp * AT_KSTR + kq;
            uint32_t* dl = Kl + dp * AT_KSTR + kq;
#pragma unroll
            for (int j = 0; j < 8; j++) {
                dh[j] = bfpack(ra[j], rb[j]);
                dl[j] = bfpack(bfres(ra[j]), bfres(rb[j]));
            }
        }
        {
            int d = t & 31;
            int kp0 = (t >> 5) * 8;
            const float* r = gv + (size_t)d * WW + kt * 128 + kp0 * 2;
            float4 x0 = *(const float4*)(r);
            float4 x1 = *(const float4*)(r + 4);
            float4 x2 = *(const float4*)(r + 8);
            float4 x3 = *(const float4*)(r + 12);
            Vh[(kp0 + 0) * AT_VSTR + d] = bfpack(x0.x, x0.y);
            Vh[(kp0 + 1) * AT_VSTR + d] = bfpack(x0.z, x0.w);
            Vh[(kp0 + 2) * AT_VSTR + d] = bfpack(x1.x, x1.y);
            Vh[(kp0 + 3) * AT_VSTR + d] = bfpack(x1.z, x1.w);
            Vh[(kp0 + 4) * AT_VSTR + d] = bfpack(x2.x, x2.y);
            Vh[(kp0 + 5) * AT_VSTR + d] = bfpack(x2.z, x2.w);
            Vh[(kp0 + 6) * AT_VSTR + d] = bfpack(x3.x, x3.y);
            Vh[(kp0 + 7) * AT_VSTR + d] = bfpack(x3.z, x3.w);
        }
        __syncthreads();

        float sa[16][4];
#pragma unroll
        for (int nt = 0; nt < 16; nt++) {
            sa[nt][0] = 0.f; sa[nt][1] = 0.f; sa[nt][2] = 0.f; sa[nt][3] = 0.f;
        }
#pragma unroll
        for (int nt = 0; nt < 16; nt++) {
            int n = nt * 8 + g;
            uint32_t kh0 = Kh[(tig) * AT_KSTR + n];
            uint32_t kh1 = Kh[(tig + 4) * AT_KSTR + n];
            uint32_t kh2 = Kh[(tig + 8) * AT_KSTR + n];
            uint32_t kh3 = Kh[(tig + 12) * AT_KSTR + n];
            uint32_t kl0 = Kl[(tig) * AT_KSTR + n];
            uint32_t kl1 = Kl[(tig + 4) * AT_KSTR + n];
            uint32_t kl2 = Kl[(tig + 8) * AT_KSTR + n];
            uint32_t kl3 = Kl[(tig + 12) * AT_KSTR + n];
            mma_bf16(sa[nt], qah[0][0], qah[0][1], qah[0][2], qah[0][3], kh0, kh1);
            mma_bf16(sa[nt], qah[1][0], qah[1][1], qah[1][2], qah[1][3], kh2, kh3);
            mma_bf16(sa[nt], qah[0][0], qah[0][1], qah[0][2], qah[0][3], kl0, kl1);
            mma_bf16(sa[nt], qah[1][0], qah[1][1], qah[1][2], qah[1][3], kl2, kl3);
            mma_bf16(sa[nt], qal[0][0], qal[0][1], qal[0][2], qal[0][3], kh0, kh1);
            mma_bf16(sa[nt], qal[1][0], qal[1][1], qal[1][2], qal[1][3], kh2, kh3);
        }

        float mx0 = -1e30f, mx1 = -1e30f;
#pragma unroll
        for (int nt = 0; nt < 16; nt++) {
            mx0 = fmaxf(mx0, fmaxf(sa[nt][0], sa[nt][1]));
            mx1 = fmaxf(mx1, fmaxf(sa[nt][2], sa[nt][3]));
        }
        mx0 = fmaxf(mx0, __shfl_xor_sync(0xFFFFFFFFu, mx0, 1));
        mx0 = fmaxf(mx0, __shfl_xor_sync(0xFFFFFFFFu, mx0, 2));
        mx1 = fmaxf(mx1, __shfl_xor_sync(0xFFFFFFFFu, mx1, 1));
        mx1 = fmaxf(mx1, __shfl_xor_sync(0xFFFFFFFFu, mx1, 2));
        float Mn0 = fmaxf(M0, mx0), Mn1 = fmaxf(M1, mx1);
        float c0 = __expf(M0 - Mn0), c1 = __expf(M1 - Mn1);
        float ps0 = 0.f, ps1 = 0.f;
#pragma unroll
        for (int nt = 0; nt < 16; nt++) {
            sa[nt][0] = __expf(sa[nt][0] - Mn0);
            sa[nt][1] = __expf(sa[nt][1] - Mn0);
            sa[nt][2] = __expf(sa[nt][2] - Mn1);
            sa[nt][3] = __expf(sa[nt][3] - Mn1);
            ps0 += sa[nt][0] + sa[nt][1];
            ps1 += sa[nt][2] + sa[nt][3];
        }
        ps0 += __shfl_xor_sync(0xFFFFFFFFu, ps0, 1);
        ps0 += __shfl_xor_sync(0xFFFFFFFFu, ps0, 2);
        ps1 += __shfl_xor_sync(0xFFFFFFFFu, ps1, 1);
        ps1 += __shfl_xor_sync(0xFFFFFFFFu, ps1, 2);
        L0 = L0 * c0 + ps0;
        L1 = L1 * c1 + ps1;
        M0 = Mn0; M1 = Mn1;
#pragma unroll
        for (int nt4 = 0; nt4 < 4; nt4++) {
            oac[nt4][0] *= c0; oac[nt4][1] *= c0;
            oac[nt4][2] *= c1; oac[nt4][3] *= c1;
        }

#pragma unroll
        for (int s8 = 0; s8 < 8; s8++) {
            uint32_t pa0 = bfpack(sa[2 * s8][0], sa[2 * s8][1]);
            uint32_t pa1 = bfpack(sa[2 * s8][2], sa[2 * s8][3]);
            uint32_t pa2 = bfpack(sa[2 * s8 + 1][0], sa[2 * s8 + 1][1]);
            uint32_t pa3 = bfpack(sa[2 * s8 + 1][2], sa[2 * s8 + 1][3]);
#pragma unroll
            for (int nt4 = 0; nt4 < 4; nt4++) {
                int d = nt4 * 8 + g;
                uint32_t vb0 = Vh[(s8 * 8 + tig) * AT_VSTR + d];
                uint32_t vb1 = Vh[(s8 * 8 + tig + 4) * AT_VSTR + d];
                mma_bf16(oac[nt4], pa0, pa1, pa2, pa3, vb0, vb1);
            }
        }
    }

    float il0 = 1.f / L0, il1 = 1.f / L1;
    int q0 = qt * 128 + qr + g;
#pragma unroll
    for (int nt4 = 0; nt4 < 4; nt4++) {
        int d = nt4 * 8 + 2 * tig;
        float* o0 = Ob + base + (size_t)d * WW;
        float* o1 = Ob + base + (size_t)(d + 1) * WW;
        o0[q0] = oac[nt4][0] * il0;
        o1[q0] = oac[nt4][1] * il0;
        o0[q0 + 8] = oac[nt4][2] * il1;
        o1[q0 + 8] = oac[nt4][3] * il1;
    }
}

// ---------------- combined: h = x AND out-x-half = x ----------------
__global__ void copy2_kernel(float* __restrict__ dst, const float* __restrict__ src,
                             float* __restrict__ out) {
    size_t i = (size_t)blockIdx.x * blockDim.x + threadIdx.x;
    size_t stride = (size_t)gridDim.x * blockDim.x;
    for (; i < NTOT; i += stride) {
        float v = src[i];
        dst[i] = v;
        size_t b = i >> 20;
        size_t inner = i & (CHUNK - 1);
        out[b * 2 * CHUNK + inner] = v;
    }
}

// ---------------- LayerNorm over features ----------------
__global__ void ln_kernel(const float* __restrict__ src, const float* __restrict__ g,
                          const float* __restrict__ bet, float* __restrict__ dst) {
    int bc = blockIdx.y;
    int c = bc & (CC - 1);
    int tx = threadIdx.x;
    int fy = threadIdx.y;
    int w = blockIdx.x * 64 + tx;
    const float* p = src + (size_t)bc * FF * WW + w;
    float s = 0.f, s2 = 0.f;
#pragma unroll 8
    for (int f = fy * 32; f < fy * 32 + 32; f++) {
        float v = p[(size_t)f * WW];
        s += v; s2 += v * v;
    }
    __shared__ float red[2][8][64];
    red[0][fy][tx] = s;
    red[1][fy][tx] = s2;
    __syncthreads();
    float S = 0.f, S2 = 0.f;
#pragma unroll
    for (int j = 0; j < 8; j++) { S += red[0][j][tx]; S2 += red[1][j][tx]; }
    float m = S * (1.0f / FF);
    float rs = rsqrtf(S2 * (1.0f / FF) - m * m + 1e-5f);
    const float* gc = g + c * FF;
    const float* bb = bet + c * FF;
    float* q = dst + (size_t)bc * FF * WW + w;
#pragma unroll 8
    for (int f = fy * 32; f < fy * 32 + 32; f++) {
        q[(size_t)f * WW] = (p[(size_t)f * WW] - m) * rs * gc[f] + bb[f];
    }
}

// ---------------- fused QKV 1x3 channel-mix conv + RoPE (f32x2 math) ----------------
__global__ __launch_bounds__(128) void convrope3_kernel(
    const float* __restrict__ tq, const float* __restrict__ tk, const float* __restrict__ tv,
    const float* __restrict__ Kq, const float* __restrict__ Kk, const float* __restrict__ Kv,
    const float* __restrict__ bq, const float* __restrict__ bk, const float* __restrict__ bv,
    float* __restrict__ oq, float* __restrict__ ok_, float* __restrict__ ov) {
    int which = blockIdx.z >> 1;
    int b = blockIdx.z & 1;
    const float* src = (which == 0) ? tq : (which == 1) ? tk : tv;
    const float* Kw  = (which == 0) ? Kq : (which == 1) ? Kk : Kv;
    const float* bias = (which == 0) ? bq : (which == 1) ? bk : bv;
    float* dst = (which == 0) ? oq : (which == 1) ? ok_ : ov;

    __shared__ unsigned long long sK2[64][4];
    __shared__ float sB2[CC];
    int t = threadIdx.x;
    if (t < 64) {
        float k0 = Kw[t * 3], k1 = Kw[t * 3 + 1], k2 = Kw[t * 3 + 2];
        sK2[t][0] = pk2(k0, k0);
        sK2[t][1] = pk2(k1, k1);
        sK2[t][2] = pk2(k2, k2);
    }
    if (t < CC) sB2[t] = bias[t];
    __syncthreads();

    int w = blockIdx.x * 128 + t;
    int f0 = blockIdx.y * 2;
    unsigned long long y01[8];
#pragma unroll
    for (int co = 0; co < 8; co++) y01[co] = pk2(sB2[co], sB2[co]);
#pragma unroll
    for (int ci = 0; ci < 8; ci++) {
        const float* xp = src + ((size_t)(b * CC + ci) * FF + f0) * WW + w;
        float l0 = (w > 0) ? xp[-1] : 0.f;
        float c0 = xp[0];
        float r0 = (w < WW - 1) ? xp[1] : 0.f;
        float l1 = (w > 0) ? xp[WW - 1] : 0.f;
        float c1 = xp[WW];
        float r1 = (w < WW - 1) ? xp[WW + 1] : 0.f;
        unsigned long long l01 = pk2(l0, l1);
        unsigned long long c01 = pk2(c0, c1);
        unsigned long long r01 = pk2(r0, r1);
#pragma unroll
        for (int co = 0; co < 8; co++) {
            const ulonglong2 kk01 = *(const ulonglong2*)&sK2[co * 8 + ci][0];
            unsigned long long kk2v = sK2[co * 8 + ci][2];
            fma2(y01[co], kk01.x, l01);
            fma2(y01[co], kk01.y, c01);
            fma2(y01[co], kk2v, r01);
        }
    }
    int d = f0 & (HD - 1);
    float theta = expf(-(float)d * (9.210340371976184f / (float)HD));
    float sn, cs;
    sincosf((float)w * theta, &sn, &cs);
    bool dorope = (which < 2);
#pragma unroll
    for (int co = 0; co < 8; co++) {
        float2 y = up2(y01[co]);
        float* op = dst + ((size_t)(b * CC + co) * FF + f0) * WW + w;
        if (dorope) {
            op[0]  = y.x * cs - y.y * sn;
            op[WW] = y.y * cs + y.x * sn;
        } else {
            op[0] = y.x;
            op[WW] = y.y;
        }
    }
}

// ---------------- fused depthwise: out = sqrelu(conv11(z)) + conv7(z) ----------------
__global__ void dwfused_kernel(const float* __restrict__ z, const float* __restrict__ w11,
                               const float* __restrict__ b11, const float* __restrict__ w7,
                               const float* __restrict__ b7, float* __restrict__ out) {
    int w = blockIdx.x * 128 + threadIdx.x;
    int f = blockIdx.y;
    int bc = blockIdx.z;
    int c = bc & 7;
    const float* zp = z + (size_t)bc * FF * WW + w;
    float a = b11[c], b2 = b7[c];
#pragma unroll
    for (int k = 0; k < 11; k++) {
        int fv = f + k - 5;
        if (fv >= 0 && fv < FF) {
            float v = zp[(size_t)fv * WW];
            a += w11[c * 11 + k] * v;
            if (k >= 2 && k <= 8) b2 += w7[c * 7 + (k - 2)] * v;
        }
    }
    float r = fmaxf(a, 0.f);
    out[((size_t)bc * FF + f) * WW + w] = r * r + b2;
}

// ---------------- depthwise 7-tap conv accumulated into h ----------------
__global__ void dwc2_acc_kernel(const float* __restrict__ z, const float* __restrict__ w7,
                                const float* __restrict__ b7, float* __restrict__ h) {
    int w = blockIdx.x * 128 + threadIdx.x;
    int f = blockIdx.y;
    int bc = blockIdx.z;
    int c = bc & 7;
    const float* zp = z + (size_t)bc * FF * WW + w;
    float s = b7[c];
#pragma unroll
    for (int k = 0; k < 7; k++) {
        int fv = f + k - 3;
        if (fv >= 0 && fv < FF) s += w7[c * 7 + k] * zp[(size_t)fv * WW];
    }
    h[((size_t)bc * FF + f) * WW + w] += s;
}

// ---------------- FFN ----------------
__global__ void ffn1_kernel(const float* __restrict__ z, const float* __restrict__ w3,
                            float* __restrict__ u) {
    int tx = threadIdx.x;
    int fy = threadIdx.y;
    int w = blockIdx.x * 128 + tx;
    int bc = blockIdx.y;
    int c = bc & 7;
    const float* zp = z + (size_t)bc * FF * WW + w;
    const float* wp = w3 + (size_t)c * EE * FF;
    float s0 = 0.f, s1 = 0.f, s2 = 0.f, s3 = 0.f;
#pragma unroll 4
    for (int f = fy * 128; f < fy * 128 + 128; f++) {
        float zv = zp[(size_t)f * WW];
        s0 += wp[f] * zv;
        s1 += wp[FF + f] * zv;
        s2 += wp[2 * FF + f] * zv;
        s3 += wp[3 * FF + f] * zv;
    }
    __shared__ float red[4][2][128];
    red[0][fy][tx] = s0; red[1][fy][tx] = s1;
    red[2][fy][tx] = s2; red[3][fy][tx] = s3;
    __syncthreads();
    if (fy == 0) {
        s0 = red[0][0][tx] + red[0][1][tx];
        s1 = red[1][0][tx] + red[1][1][tx];
        s2 = red[2][0][tx] + red[2][1][tx];
        s3 = red[3][0][tx] + red[3][1][tx];
        float* up = u + (size_t)bc * EE * WW + w;
        float r;
        r = fmaxf(s0, 0.f); up[0]      = r * r;
        r = fmaxf(s1, 0.f); up[WW]     = r * r;
        r = fmaxf(s2, 0.f); up[2 * WW] = r * r;
        r = fmaxf(s3, 0.f); up[3 * WW] = r * r;
    }
}

__global__ void ffn2_out_kernel(const float* __restrict__ u, const float* __restrict__ w4,
                                const float* __restrict__ h, float* __restrict__ out) {
    int w = blockIdx.x * 128 + threadIdx.x;
    int f = blockIdx.y;
    int bc = blockIdx.z;
    int c = bc & 7;
    int b = bc >> 3;
    const float* up = u + (size_t)bc * EE * WW + w;
    const float* wp = w4 + ((size_t)c * FF + f) * EE;
    float s = wp[0] * up[0] + wp[1] * up[WW] + wp[2] * up[2 * WW] + wp[3] * up[3 * WW];
    out[(((size_t)b * 2 * CC + CC + c) * FF + f) * WW + w] =
        h[((size_t)bc * FF + f) * WW + w] + s;
}

// ================================================================================
extern "C" void kernel_launch(void* const* d_in, const int* in_sizes, int n_in,
                              void* d_out, int out_size) {
    const float* x    = (const float*)d_in[0];
    const float* skip = (const float*)d_in[1];
    const float* Wq   = (const float*)d_in[2];
    const float* Kq   = (const float*)d_in[3];
    const float* bq   = (const float*)d_in[4];
    const float* Wk   = (const float*)d_in[5];
    const float* Kk   = (const float*)d_in[6];
    const float* bk   = (const float*)d_in[7];
    const float* Wv   = (const float*)d_in[8];
    const float* Kv   = (const float*)d_in[9];
    const float* bv   = (const float*)d_in[10];
    const float* Wo   = (const float*)d_in[11];
    const float* ng   = (const float*)d_in[12];
    const float* nb   = (const float*)d_in[13];
    const float* c1aw = (const float*)d_in[14];
    const float* c1ab = (const float*)d_in[15];
    const float* c1bw = (const float*)d_in[16];
    const float* c1bb = (const float*)d_in[17];
    const float* c2w  = (const float*)d_in[18];
    const float* c2b  = (const float*)d_in[19];
    const float* w3   = (const float*)d_in[20];
    const float* w4   = (const float*)d_in[21];
    float* out = (float*)d_out;

    float *ph, *pz, *pq, *pk, *pv, *ptq, *ptk, *ptv, *pu;
    cudaGetSymbolAddress((void**)&ph, g_h);
    cudaGetSymbolAddress((void**)&pz, g_z);
    cudaGetSymbolAddress((void**)&pq, g_q);
    cudaGetSymbolAddress((void**)&pk, g_k);
    cudaGetSymbolAddress((void**)&pv, g_v);
    cudaGetSymbolAddress((void**)&ptq, g_t);
    cudaGetSymbolAddress((void**)&ptk, g_t2);
    cudaGetSymbolAddress((void**)&ptv, g_t3);
    cudaGetSymbolAddress((void**)&pu, g_u);

    const dim3 gemm_grid(4, 2, BC);
    const dim3 gemm3_grid(4, 2, 3 * BC);
    const dim3 conv3_grid(4, FF / 2, 3 * BB);
    const dim3 ln_grid(8, BC);
    const dim3 ln_block(64, 8);
    const dim3 elw_grid(4, FF, BC);
    const dim3 attn_grid(4, BC * HH);

    const size_t KFF = (size_t)CC * CC * 3;

    auto attn_block = [&](int i, const float* qsrc, const float* msrc) {
        gemm_qkv<<<gemm3_grid, 512>>>(i, qsrc, msrc, ptq, ptk, ptv);
        convrope3_kernel<<<conv3_grid, 128>>>(ptq, ptk, ptv,
                                              Kq + (size_t)i * KFF, Kk + (size_t)i * KFF, Kv + (size_t)i * KFF,
                                              bq + i * CC, bk + i * CC, bv + i * CC,
                                              pq, pk, pv);
        attn_mma_kernel<<<attn_grid, 256>>>(pq, pk, pv, ptq);
        gemm_one<<<gemm_grid, 512>>>(i, ptq, ph);
    };

    // weight pre-conversion (runs each replay; ~3 us)
    wprep_kernel<<<4096, 512>>>(Wq, Wk, Wv, Wo);

    // h = x; out-x-half = x
    copy2_kernel<<<2048, 512>>>(ph, x, out);

    // z = LN0(h); h += attn0(z,z); h += attn1(z, skip)
    ln_kernel<<<ln_grid, ln_block>>>(ph, ng + 0 * CC * FF, nb + 0 * CC * FF, pz);
    attn_block(0, pz, pz);
    attn_block(1, pz, skip);

    // conv block
    ln_kernel<<<ln_grid, ln_block>>>(ph, ng + 1 * CC * FF, nb + 1 * CC * FF, pz);
    dwfused_kernel<<<elw_grid, 128>>>(pz, c1aw, c1ab, c1bw, c1bb, pq);
    ln_kernel<<<ln_grid, ln_block>>>(pq, ng + 2 * CC * FF, nb + 2 * CC * FF, pz);
    dwc2_acc_kernel<<<elw_grid, 128>>>(pz, c2w, c2b, ph);

    // attn2 (self) and attn3 (skip)
    ln_kernel<<<ln_grid, ln_block>>>(ph, ng + 3 * CC * FF, nb + 3 * CC * FF, pz);
    attn_block(2, pz, pz);
    ln_kernel<<<ln_grid, ln_block>>>(ph, ng + 4 * CC * FF, nb + 4 * CC * FF, pz);
    attn_block(3, pz, skip);

    // FFN (+ fused concat)
    ln_kernel<<<ln_grid, ln_block>>>(ph, ng + 5 * CC * FF, nb + 5 * CC * FF, pz);
    ffn1_kernel<<<dim3(4, BC), dim3(128, 2)>>>(pz, w3, pu);
    ffn2_out_kernel<<<elw_grid, 128>>>(pu, w4, ph, out);
    (void)in_sizes; (void)n_in; (void)out_size;
}

// round 12
// speedup vs baseline: 2.5414x; 1.0046x over previous
#include <cuda_runtime.h>
#include <cuda_bf16.h>
#include <math.h>
#include <stdint.h>

#define BB 2
#define CC 8
#define FF 256
#define WW 512
#define HH 8
#define HD 32
#define EE 4
#define BC (BB*CC)
#define NTOT ((size_t)BB*CC*FF*WW)
#define CHUNK ((size_t)CC*FF*WW)       // 2^20
#define WMAT_U32 (CC*FF*(FF/2))        // 262144 uint32 per weight matrix

// ---------------- scratch (static device globals; no allocation) ----------------
__device__ float g_h[BB*CC*FF*WW];
__device__ float g_z[BB*CC*FF*WW];
__device__ float g_q[BB*CC*FF*WW];
__device__ float g_k[BB*CC*FF*WW];
__device__ float g_v[BB*CC*FF*WW];
__device__ float g_t[BB*CC*FF*WW];
__device__ float g_t2[BB*CC*FF*WW];
__device__ float g_t3[BB*CC*FF*WW];
__device__ float g_u[BB*CC*EE*WW];
__device__ uint32_t g_wh[16 * WMAT_U32];   // bf16-hi of all 16 weight mats, k-pair packed
__device__ uint32_t g_wl[16 * WMAT_U32];   // bf16-lo residuals

// ---------------- packed f32x2 helpers ----------------
__device__ __forceinline__ unsigned long long pk2(float lo, float hi) {
    unsigned long long r;
    asm("mov.b64 %0, {%1, %2};" : "=l"(r) : "f"(lo), "f"(hi));
    return r;
}
__device__ __forceinline__ void fma2(unsigned long long& d, unsigned long long a, unsigned long long b) {
    asm("fma.rn.f32x2 %0, %1, %2, %0;" : "+l"(d) : "l"(a), "l"(b));
}
__device__ __forceinline__ float2 up2(unsigned long long v) {
    float2 r;
    asm("mov.b64 {%0, %1}, %2;" : "=f"(r.x), "=f"(r.y) : "l"(v));
    return r;
}

// ---------------- bf16 pack helpers ----------------
__device__ __forceinline__ uint32_t bfpack(float a, float b) {
    uint32_t lo = (uint32_t)__bfloat16_as_ushort(__float2bfloat16(a));
    uint32_t hi = (uint32_t)__bfloat16_as_ushort(__float2bfloat16(b));
    return lo | (hi << 16);
}
__device__ __forceinline__ float bfres(float x) {   // x - bf16(x)
    return x - __bfloat162float(__float2bfloat16(x));
}

// ---------------- warp mma.sync / ldmatrix ----------------
__device__ __forceinline__ void mma_bf16(float* d, uint32_t a0, uint32_t a1, uint32_t a2, uint32_t a3,
                                         uint32_t b0, uint32_t b1) {
    asm volatile(
        "mma.sync.aligned.m16n8k16.row.col.f32.bf16.bf16.f32 "
        "{%0,%1,%2,%3}, {%4,%5,%6,%7}, {%8,%9}, {%0,%1,%2,%3};"
        : "+f"(d[0]), "+f"(d[1]), "+f"(d[2]), "+f"(d[3])
        : "r"(a0), "r"(a1), "r"(a2), "r"(a3), "r"(b0), "r"(b1));
}
__device__ __forceinline__ void ldsm_x4(uint32_t* r, uint32_t addr) {
    asm volatile("ldmatrix.sync.aligned.m8n8.x4.shared.b16 {%0,%1,%2,%3}, [%4];"
                 : "=r"(r[0]), "=r"(r[1]), "=r"(r[2]), "=r"(r[3]) : "r"(addr));
}
__device__ __forceinline__ uint32_t smem_u32(const void* p) {
    uint32_t a;
    asm("{ .reg .u64 t; cvta.to.shared.u64 t, %1; cvt.u32.u64 %0, t; }" : "=r"(a) : "l"(p));
    return a;
}

// ---------------- weight pre-conversion: fp32 -> k-pair packed bf16 hi/lo ----------------
__global__ void wprep_kernel(const float* __restrict__ Wq, const float* __restrict__ Wk,
                             const float* __restrict__ Wv, const float* __restrict__ Wo) {
    size_t total = 16ull * WMAT_U32;
    for (size_t i = (size_t)blockIdx.x * blockDim.x + threadIdx.x; i < total;
         i += (size_t)gridDim.x * blockDim.x) {
        int mat = (int)(i / WMAT_U32);
        size_t inner = i % WMAT_U32;
        int layer = mat >> 2, kind = mat & 3;
        const float* src = (kind == 0) ? Wq : (kind == 1) ? Wk : (kind == 2) ? Wv : Wo;
        float2 v = *(const float2*)(src + (size_t)layer * CC * FF * FF + inner * 2);
        g_wh[i] = bfpack(v.x, v.y);
        g_wl[i] = bfpack(bfres(v.x), bfres(v.y));
    }
}

// ---------------- tensor-core GEMM tile: 512 threads, prefetch + ldmatrix ----------------
#define ASTR 20
#define BSTR 132
__device__ __forceinline__ void gemm_tile(const uint32_t* __restrict__ Ahg, const uint32_t* __restrict__ Alg,
                                          const float* __restrict__ Bx,
                                          float* __restrict__ Cp, int m0, int n0, bool accum) {
    __shared__ uint32_t Aph[128 * ASTR];
    __shared__ uint32_t Apl[128 * ASTR];
    __shared__ uint32_t Bph[16 * BSTR];
    __shared__ uint32_t Bpl[16 * BSTR];
    int t = threadIdx.x;
    int lane = t & 31, wid = t >> 5;
    int wm = (wid >> 2) * 32;
    int wn = (wid & 3) * 32;
    int g = lane >> 2, tig = lane & 3;

    // ldmatrix lane->element map (A fragments)
    int lrow = ((lane >> 3) & 1) * 8 + (lane & 7);
    int lcol = (lane >> 4) * 4;
    uint32_t aph_u32 = smem_u32(Aph);
    uint32_t apl_u32 = smem_u32(Apl);

    // loader indices
    int arow = t >> 2, apart = (t & 3) * 4;
    const uint32_t* aghp = Ahg + (size_t)(m0 + arow) * (FF / 2) + apart;
    const uint32_t* aglp = Alg + (size_t)(m0 + arow) * (FF / 2) + apart;
    int bkp = t >> 5, bnq = (t & 31) * 4;
    const float* bgp = Bx + (size_t)(bkp * 2) * WW + n0 + bnq;

    float acc[2][4][4];
#pragma unroll
    for (int mt = 0; mt < 2; mt++)
#pragma unroll
        for (int nt = 0; nt < 4; nt++)
#pragma unroll
            for (int j = 0; j < 4; j++) acc[mt][nt][j] = 0.f;

    // prefetch chunk 0
    uint4 pf_ah = *(const uint4*)(aghp);
    uint4 pf_al = *(const uint4*)(aglp);
    float4 pf_b0 = *(const float4*)(bgp);
    float4 pf_b1 = *(const float4*)(bgp + WW);

    for (int ch = 0; ch < 8; ch++) {
        // store prefetched chunk into smem (conversion for B happens here)
        *(uint4*)(Aph + arow * ASTR + apart) = pf_ah;
        *(uint4*)(Apl + arow * ASTR + apart) = pf_al;
        {
            uint32_t* dh = Bph + bkp * BSTR + bnq;
            uint32_t* dl = Bpl + bkp * BSTR + bnq;
            dh[0] = bfpack(pf_b0.x, pf_b1.x);
            dh[1] = bfpack(pf_b0.y, pf_b1.y);
            dh[2] = bfpack(pf_b0.z, pf_b1.z);
            dh[3] = bfpack(pf_b0.w, pf_b1.w);
            dl[0] = bfpack(bfres(pf_b0.x), bfres(pf_b1.x));
            dl[1] = bfpack(bfres(pf_b0.y), bfres(pf_b1.y));
            dl[2] = bfpack(bfres(pf_b0.z), bfres(pf_b1.z));
            dl[3] = bfpack(bfres(pf_b0.w), bfres(pf_b1.w));
        }
        __syncthreads();

        // issue prefetch for next chunk BEFORE compute (latency hides under mmas)
        if (ch < 7) {
            pf_ah = *(const uint4*)(aghp + (ch + 1) * 16);
            pf_al = *(const uint4*)(aglp + (ch + 1) * 16);
            pf_b0 = *(const float4*)(bgp + (size_t)(ch + 1) * 32 * WW);
            pf_b1 = *(const float4*)(bgp + (size_t)(ch + 1) * 32 * WW + WW);
        }

#pragma unroll
        for (int ks = 0; ks < 2; ks++) {
            int kk2 = ks * 8;
            uint32_t bh[4][2], bl[4][2];
#pragma unroll
            for (int nt = 0; nt < 4; nt++) {
                int n = wn + nt * 8 + g;
                bh[nt][0] = Bph[(tig + kk2) * BSTR + n];
                bh[nt][1] = Bph[(tig + 4 + kk2) * BSTR + n];
                bl[nt][0] = Bpl[(tig + kk2) * BSTR + n];
                bl[nt][1] = Bpl[(tig + 4 + kk2) * BSTR + n];
            }
#pragma unroll
            for (int mt = 0; mt < 2; mt++) {
                uint32_t off = (uint32_t)(((wm + mt * 16 + lrow) * ASTR + kk2 + lcol) * 4);
                uint32_t ah[4], al[4];
                ldsm_x4(ah, aph_u32 + off);
                ldsm_x4(al, apl_u32 + off);
#pragma unroll
                for (int nt = 0; nt < 4; nt++) {
                    mma_bf16(acc[mt][nt], ah[0], ah[1], ah[2], ah[3], bh[nt][0], bh[nt][1]);
                    mma_bf16(acc[mt][nt], ah[0], ah[1], ah[2], ah[3], bl[nt][0], bl[nt][1]);
                    mma_bf16(acc[mt][nt], al[0], al[1], al[2], al[3], bh[nt][0], bh[nt][1]);
                }
            }
        }
        __syncthreads();
    }

#pragma unroll
    for (int mt = 0; mt < 2; mt++) {
#pragma unroll
        for (int nt = 0; nt < 4; nt++) {
            int row = m0 + wm + mt * 16 + g;
            int col = n0 + wn + nt * 8 + tig * 2;
            float* p0 = Cp + (size_t)row * WW + col;
            float* p1 = Cp + (size_t)(row + 8) * WW + col;
            if (accum) {
                float2 c0 = *(float2*)p0;
                float2 c1 = *(float2*)p1;
                c0.x += acc[mt][nt][0]; c0.y += acc[mt][nt][1];
                c1.x += acc[mt][nt][2]; c1.y += acc[mt][nt][3];
                *(float2*)p0 = c0;
                *(float2*)p1 = c1;
            } else {
                *(float2*)p0 = make_float2(acc[mt][nt][0], acc[mt][nt][1]);
                *(float2*)p1 = make_float2(acc[mt][nt][2], acc[mt][nt][3]);
            }
        }
    }
}

__global__ __launch_bounds__(512) void gemm_qkv(int layer,
                                                const float* __restrict__ qsrc, const float* __restrict__ msrc,
                                                float* __restrict__ oq, float* __restrict__ ok_,
                                                float* __restrict__ ov) {
    int z = blockIdx.z;
    int which = z >> 4;
    int bc = z & 15;
    int c = bc & (CC - 1);
    const float* X = (which == 0) ? qsrc : msrc;
    float* Out = (which == 0) ? oq : (which == 1) ? ok_ : ov;
    size_t moff = (size_t)(layer * 4 + which) * WMAT_U32 + (size_t)c * FF * (FF / 2);
    gemm_tile(g_wh + moff, g_wl + moff, X + (size_t)bc * FF * WW,
              Out + (size_t)bc * FF * WW, blockIdx.y * 128, blockIdx.x * 128, false);
}

__global__ __launch_bounds__(512) void gemm_one(int layer, const float* __restrict__ X,
                                                float* __restrict__ Out) {
    int bc = blockIdx.z;
    int c = bc & (CC - 1);
    size_t moff = (size_t)(layer * 4 + 3) * WMAT_U32 + (size_t)c * FF * (FF / 2);
    gemm_tile(g_wh + moff, g_wl + moff, X + (size_t)bc * FF * WW,
              Out + (size_t)bc * FF * WW, blockIdx.y * 128, blockIdx.x * 128, true);
}

// ---------------- flash-attention via mma.sync ----------------
#define AT_QSTR 17
#define AT_KSTR 136
#define AT_VSTR 40
__global__ __launch_bounds__(256, 2) void attn_mma_kernel(const float* __restrict__ Q,
                                                          const float* __restrict__ Kb,
                                                          const float* __restrict__ Vb,
                                                          float* __restrict__ Ob) {
    __shared__ uint32_t Qh[128 * AT_QSTR];
    __shared__ uint32_t Ql[128 * AT_QSTR];
    __shared__ uint32_t Kh[16 * AT_KSTR];
    __shared__ uint32_t Kl[16 * AT_KSTR];
    __shared__ uint32_t Vh[64 * AT_VSTR];
    int t = threadIdx.x;
    int lane = t & 31, wid = t >> 5;
    int g = lane >> 2, tig = lane & 3;
    int qt = blockIdx.x;
    int bch = blockIdx.y;
    int h = bch & (HH - 1);
    int bc = bch >> 3;
    size_t base = ((size_t)bc * FF + h * HD) * WW;
    const float* gq = Q + base + qt * 128;
    const float* gk = Kb + base;
    const float* gv = Vb + base;

    {
        int q = t & 127;
        int dp0 = (t >> 7) * 8;
#pragma unroll
        for (int j = 0; j < 8; j++) {
            int dp = dp0 + j;
            float v0 = gq[(size_t)(2 * dp) * WW + q] * 0.0625f;
            float v1 = gq[(size_t)(2 * dp + 1) * WW + q] * 0.0625f;
            Qh[q * AT_QSTR + dp] = bfpack(v0, v1);
            Ql[q * AT_QSTR + dp] = bfpack(bfres(v0), bfres(v1));
        }
    }
    __syncthreads();

    uint32_t qah[2][4], qal[2][4];
    int qr = wid * 16;
#pragma unroll
    for (int s = 0; s < 2; s++) {
        qah[s][0] = Qh[(qr + g) * AT_QSTR + s * 8 + tig];
        qah[s][1] = Qh[(qr + g + 8) * AT_QSTR + s * 8 + tig];
        qah[s][2] = Qh[(qr + g) * AT_QSTR + s * 8 + tig + 4];
        qah[s][3] = Qh[(qr + g + 8) * AT_QSTR + s * 8 + tig + 4];
        qal[s][0] = Ql[(qr + g) * AT_QSTR + s * 8 + tig];
        qal[s][1] = Ql[(qr + g + 8) * AT_QSTR + s * 8 + tig];
        qal[s][2] = Ql[(qr + g) * AT_QSTR + s * 8 + tig + 4];
        qal[s][3] = Ql[(qr + g + 8) * AT_QSTR + s * 8 + tig + 4];
    }

    float M0 = -1e30f, M1 = -1e30f, L0 = 0.f, L1 = 0.f;
    float oac[4][4];
#pragma unroll
    for (int i = 0; i < 4; i++)
#pragma unroll
        for (int j = 0; j < 4; j++) oac[i][j] = 0.f;

    for (int kt = 0; kt < 4; kt++) {
        __syncthreads();
        {
            int dp = t >> 4;
            int kq = (t & 15) * 8;
            const float* r0 = gk + (size_t)(2 * dp) * WW + kt * 128 + kq;
            const float* r1 = r0 + WW;
            float4 a0 = *(const float4*)(r0);
            float4 a1 = *(const float4*)(r0 + 4);
            float4 b0 = *(const float4*)(r1);
            float4 b1 = *(const float4*)(r1 + 4);
            float ra[8] = {a0.x, a0.y, a0.z, a0.w, a1.x, a1.y, a1.z, a1.w};
            float rb[8] = {b0.x, b0.y, b0.z, b0.w, b1.x, b1.y, b1.z, b1.w};
            uint32_t* dh = Kh + dp * AT_KSTR + kq;
            uint32_t* dl = Kl + dp * AT_KSTR + kq;
#pragma unroll
            for (int j = 0; j < 8; j++) {
                dh[j] = bfpack(ra[j], rb[j]);
                dl[j] = bfpack(bfres(ra[j]), bfres(rb[j]));
            }
        }
        {
            int d = t & 31;
            int kp0 = (t >> 5) * 8;
            const float* r = gv + (size_t)d * WW + kt * 128 + kp0 * 2;
            float4 x0 = *(const float4*)(r);
            float4 x1 = *(const float4*)(r + 4);
            float4 x2 = *(const float4*)(r + 8);
            float4 x3 = *(const float4*)(r + 12);
            Vh[(kp0 + 0) * AT_VSTR + d] = bfpack(x0.x, x0.y);
            Vh[(kp0 + 1) * AT_VSTR + d] = bfpack(x0.z, x0.w);
            Vh[(kp0 + 2) * AT_VSTR + d] = bfpack(x1.x, x1.y);
            Vh[(kp0 + 3) * AT_VSTR + d] = bfpack(x1.z, x1.w);
            Vh[(kp0 + 4) * AT_VSTR + d] = bfpack(x2.x, x2.y);
            Vh[(kp0 + 5) * AT_VSTR + d] = bfpack(x2.z, x2.w);
            Vh[(kp0 + 6) * AT_VSTR + d] = bfpack(x3.x, x3.y);
            Vh[(kp0 + 7) * AT_VSTR + d] = bfpack(x3.z, x3.w);
        }
        __syncthreads();

        float sa[16][4];
#pragma unroll
        for (int nt = 0; nt < 16; nt++) {
            sa[nt][0] = 0.f; sa[nt][1] = 0.f; sa[nt][2] = 0.f; sa[nt][3] = 0.f;
        }
#pragma unroll
        for (int nt = 0; nt < 16; nt++) {
            int n = nt * 8 + g;
            uint32_t kh0 = Kh[(tig) * AT_KSTR + n];
            uint32_t kh1 = Kh[(tig + 4) * AT_KSTR + n];
            uint32_t kh2 = Kh[(tig + 8) * AT_KSTR + n];
            uint32_t kh3 = Kh[(tig + 12) * AT_KSTR + n];
            uint32_t kl0 = Kl[(tig) * AT_KSTR + n];
            uint32_t kl1 = Kl[(tig + 4) * AT_KSTR + n];
            uint32_t kl2 = Kl[(tig + 8) * AT_KSTR + n];
            uint32_t kl3 = Kl[(tig + 12) * AT_KSTR + n];
            mma_bf16(sa[nt], qah[0][0], qah[0][1], qah[0][2], qah[0][3], kh0, kh1);
            mma_bf16(sa[nt], qah[1][0], qah[1][1], qah[1][2], qah[1][3], kh2, kh3);
            mma_bf16(sa[nt], qah[0][0], qah[0][1], qah[0][2], qah[0][3], kl0, kl1);
            mma_bf16(sa[nt], qah[1][0], qah[1][1], qah[1][2], qah[1][3], kl2, kl3);
            mma_bf16(sa[nt], qal[0][0], qal[0][1], qal[0][2], qal[0][3], kh0, kh1);
            mma_bf16(sa[nt], qal[1][0], qal[1][1], qal[1][2], qal[1][3], kh2, kh3);
        }

        float mx0 = -1e30f, mx1 = -1e30f;
#pragma unroll
        for (int nt = 0; nt < 16; nt++) {
            mx0 = fmaxf(mx0, fmaxf(sa[nt][0], sa[nt][1]));
            mx1 = fmaxf(mx1, fmaxf(sa[nt][2], sa[nt][3]));
        }
        mx0 = fmaxf(mx0, __shfl_xor_sync(0xFFFFFFFFu, mx0, 1));
        mx0 = fmaxf(mx0, __shfl_xor_sync(0xFFFFFFFFu, mx0, 2));
        mx1 = fmaxf(mx1, __shfl_xor_sync(0xFFFFFFFFu, mx1, 1));
        mx1 = fmaxf(mx1, __shfl_xor_sync(0xFFFFFFFFu, mx1, 2));
        float Mn0 = fmaxf(M0, mx0), Mn1 = fmaxf(M1, mx1);
        float c0 = __expf(M0 - Mn0), c1 = __expf(M1 - Mn1);
        float ps0 = 0.f, ps1 = 0.f;
#pragma unroll
        for (int nt = 0; nt < 16; nt++) {
            sa[nt][0] = __expf(sa[nt][0] - Mn0);
            sa[nt][1] = __expf(sa[nt][1] - Mn0);
            sa[nt][2] = __expf(sa[nt][2] - Mn1);
            sa[nt][3] = __expf(sa[nt][3] - Mn1);
            ps0 += sa[nt][0] + sa[nt][1];
            ps1 += sa[nt][2] + sa[nt][3];
        }
        ps0 += __shfl_xor_sync(0xFFFFFFFFu, ps0, 1);
        ps0 += __shfl_xor_sync(0xFFFFFFFFu, ps0, 2);
        ps1 += __shfl_xor_sync(0xFFFFFFFFu, ps1, 1);
        ps1 += __shfl_xor_sync(0xFFFFFFFFu, ps1, 2);
        L0 = L0 * c0 + ps0;
        L1 = L1 * c1 + ps1;
        M0 = Mn0; M1 = Mn1;
#pragma unroll
        for (int nt4 = 0; nt4 < 4; nt4++) {
            oac[nt4][0] *= c0; oac[nt4][1] *= c0;
            oac[nt4][2] *= c1; oac[nt4][3] *= c1;
        }

#pragma unroll
        for (int s8 = 0; s8 < 8; s8++) {
            uint32_t pa0 = bfpack(sa[2 * s8][0], sa[2 * s8][1]);
            uint32_t pa1 = bfpack(sa[2 * s8][2], sa[2 * s8][3]);
            uint32_t pa2 = bfpack(sa[2 * s8 + 1][0], sa[2 * s8 + 1][1]);
            uint32_t pa3 = bfpack(sa[2 * s8 + 1][2], sa[2 * s8 + 1][3]);
#pragma unroll
            for (int nt4 = 0; nt4 < 4; nt4++) {
                int d = nt4 * 8 + g;
                uint32_t vb0 = Vh[(s8 * 8 + tig) * AT_VSTR + d];
                uint32_t vb1 = Vh[(s8 * 8 + tig + 4) * AT_VSTR + d];
                mma_bf16(oac[nt4], pa0, pa1, pa2, pa3, vb0, vb1);
            }
        }
    }

    float il0 = 1.f / L0, il1 = 1.f / L1;
    int q0 = qt * 128 + qr + g;
#pragma unroll
    for (int nt4 = 0; nt4 < 4; nt4++) {
        int d = nt4 * 8 + 2 * tig;
        float* o0 = Ob + base + (size_t)d * WW;
        float* o1 = Ob + base + (size_t)(d + 1) * WW;
        o0[q0] = oac[nt4][0] * il0;
        o1[q0] = oac[nt4][1] * il0;
        o0[q0 + 8] = oac[nt4][2] * il1;
        o1[q0 + 8] = oac[nt4][3] * il1;
    }
}

// ---------------- combined: h = x AND out-x-half = x ----------------
__global__ void copy2_kernel(float* __restrict__ dst, const float* __restrict__ src,
                             float* __restrict__ out) {
    size_t i = (size_t)blockIdx.x * blockDim.x + threadIdx.x;
    size_t stride = (size_t)gridDim.x * blockDim.x;
    for (; i < NTOT; i += stride) {
        float v = src[i];
        dst[i] = v;
        size_t b = i >> 20;
        size_t inner = i & (CHUNK - 1);
        out[b * 2 * CHUNK + inner] = v;
    }
}

// ---------------- LayerNorm over features ----------------
__global__ void ln_kernel(const float* __restrict__ src, const float* __restrict__ g,
                          const float* __restrict__ bet, float* __restrict__ dst) {
    int bc = blockIdx.y;
    int c = bc & (CC - 1);
    int tx = threadIdx.x;
    int fy = threadIdx.y;
    int w = blockIdx.x * 64 + tx;
    const float* p = src + (size_t)bc * FF * WW + w;
    float s = 0.f, s2 = 0.f;
#pragma unroll 8
    for (int f = fy * 32; f < fy * 32 + 32; f++) {
        float v = p[(size_t)f * WW];
        s += v; s2 += v * v;
    }
    __shared__ float red[2][8][64];
    red[0][fy][tx] = s;
    red[1][fy][tx] = s2;
    __syncthreads();
    float S = 0.f, S2 = 0.f;
#pragma unroll
    for (int j = 0; j < 8; j++) { S += red[0][j][tx]; S2 += red[1][j][tx]; }
    float m = S * (1.0f / FF);
    float rs = rsqrtf(S2 * (1.0f / FF) - m * m + 1e-5f);
    const float* gc = g + c * FF;
    const float* bb = bet + c * FF;
    float* q = dst + (size_t)bc * FF * WW + w;
#pragma unroll 8
    for (int f = fy * 32; f < fy * 32 + 32; f++) {
        q[(size_t)f * WW] = (p[(size_t)f * WW] - m) * rs * gc[f] + bb[f];
    }
}

// ---------------- fused QKV 1x3 channel-mix conv + RoPE (f32x2 math) ----------------
__global__ __launch_bounds__(128) void convrope3_kernel(
    const float* __restrict__ tq, const float* __restrict__ tk, const float* __restrict__ tv,
    const float* __restrict__ Kq, const float* __restrict__ Kk, const float* __restrict__ Kv,
    const float* __restrict__ bq, const float* __restrict__ bk, const float* __restrict__ bv,
    float* __restrict__ oq, float* __restrict__ ok_, float* __restrict__ ov) {
    int which = blockIdx.z >> 1;
    int b = blockIdx.z & 1;
    const float* src = (which == 0) ? tq : (which == 1) ? tk : tv;
    const float* Kw  = (which == 0) ? Kq : (which == 1) ? Kk : Kv;
    const float* bias = (which == 0) ? bq : (which == 1) ? bk : bv;
    float* dst = (which == 0) ? oq : (which == 1) ? ok_ : ov;

    __shared__ unsigned long long sK2[64][4];
    __shared__ float sB2[CC];
    int t = threadIdx.x;
    if (t < 64) {
        float k0 = Kw[t * 3], k1 = Kw[t * 3 + 1], k2 = Kw[t * 3 + 2];
        sK2[t][0] = pk2(k0, k0);
        sK2[t][1] = pk2(k1, k1);
        sK2[t][2] = pk2(k2, k2);
    }
    if (t < CC) sB2[t] = bias[t];
    __syncthreads();

    int w = blockIdx.x * 128 + t;
    int f0 = blockIdx.y * 2;
    unsigned long long y01[8];
#pragma unroll
    for (int co = 0; co < 8; co++) y01[co] = pk2(sB2[co], sB2[co]);
#pragma unroll
    for (int ci = 0; ci < 8; ci++) {
        const float* xp = src + ((size_t)(b * CC + ci) * FF + f0) * WW + w;
        float l0 = (w > 0) ? xp[-1] : 0.f;
        float c0 = xp[0];
        float r0 = (w < WW - 1) ? xp[1] : 0.f;
        float l1 = (w > 0) ? xp[WW - 1] : 0.f;
        float c1 = xp[WW];
        float r1 = (w < WW - 1) ? xp[WW + 1] : 0.f;
        unsigned long long l01 = pk2(l0, l1);
        unsigned long long c01 = pk2(c0, c1);
        unsigned long long r01 = pk2(r0, r1);
#pragma unroll
        for (int co = 0; co < 8; co++) {
            const ulonglong2 kk01 = *(const ulonglong2*)&sK2[co * 8 + ci][0];
            unsigned long long kk2v = sK2[co * 8 + ci][2];
            fma2(y01[co], kk01.x, l01);
            fma2(y01[co], kk01.y, c01);
            fma2(y01[co], kk2v, r01);
        }
    }
    int d = f0 & (HD - 1);
    float theta = expf(-(float)d * (9.210340371976184f / (float)HD));
    float sn, cs;
    sincosf((float)w * theta, &sn, &cs);
    bool dorope = (which < 2);
#pragma unroll
    for (int co = 0; co < 8; co++) {
        float2 y = up2(y01[co]);
        float* op = dst + ((size_t)(b * CC + co) * FF + f0) * WW + w;
        if (dorope) {
            op[0]  = y.x * cs - y.y * sn;
            op[WW] = y.y * cs + y.x * sn;
        } else {
            op[0] = y.x;
            op[WW] = y.y;
        }
    }
}

// ---------------- fused depthwise: out = sqrelu(conv11(z)) + conv7(z) ----------------
__global__ void dwfused_kernel(const float* __restrict__ z, const float* __restrict__ w11,
                               const float* __restrict__ b11, const float* __restrict__ w7,
                               const float* __restrict__ b7, float* __restrict__ out) {
    int w = blockIdx.x * 128 + threadIdx.x;
    int f = blockIdx.y;
    int bc = blockIdx.z;
    int c = bc & 7;
    const float* zp = z + (size_t)bc * FF * WW + w;
    float a = b11[c], b2 = b7[c];
#pragma unroll
    for (int k = 0; k < 11; k++) {
        int fv = f + k - 5;
        if (fv >= 0 && fv < FF) {
            float v = zp[(size_t)fv * WW];
            a += w11[c * 11 + k] * v;
            if (k >= 2 && k <= 8) b2 += w7[c * 7 + (k - 2)] * v;
        }
    }
    float r = fmaxf(a, 0.f);
    out[((size_t)bc * FF + f) * WW + w] = r * r + b2;
}

// ---------------- depthwise 7-tap conv accumulated into h ----------------
__global__ void dwc2_acc_kernel(const float* __restrict__ z, const float* __restrict__ w7,
                                const float* __restrict__ b7, float* __restrict__ h) {
    int w = blockIdx.x * 128 + threadIdx.x;
    int f = blockIdx.y;
    int bc = blockIdx.z;
    int c = bc & 7;
    const float* zp = z + (size_t)bc * FF * WW + w;
    float s = b7[c];
#pragma unroll
    for (int k = 0; k < 7; k++) {
        int fv = f + k - 3;
        if (fv >= 0 && fv < FF) s += w7[c * 7 + k] * zp[(size_t)fv * WW];
    }
    h[((size_t)bc * FF + f) * WW + w] += s;
}

// ---------------- FFN ----------------
__global__ void ffn1_kernel(const float* __restrict__ z, const float* __restrict__ w3,
                            float* __restrict__ u) {
    int tx = threadIdx.x;
    int fy = threadIdx.y;
    int w = blockIdx.x * 128 + tx;
    int bc = blockIdx.y;
    int c = bc & 7;
    const float* zp = z + (size_t)bc * FF * WW + w;
    const float* wp = w3 + (size_t)c * EE * FF;
    float s0 = 0.f, s1 = 0.f, s2 = 0.f, s3 = 0.f;
#pragma unroll 4
    for (int f = fy * 128; f < fy * 128 + 128; f++) {
        float zv = zp[(size_t)f * WW];
        s0 += wp[f] * zv;
        s1 += wp[FF + f] * zv;
        s2 += wp[2 * FF + f] * zv;
        s3 += wp[3 * FF + f] * zv;
    }
    __shared__ float red[4][2][128];
    red[0][fy][tx] = s0; red[1][fy][tx] = s1;
    red[2][fy][tx] = s2; red[3][fy][tx] = s3;
    __syncthreads();
    if (fy == 0) {
        s0 = red[0][0][tx] + red[0][1][tx];
        s1 = red[1][0][tx] + red[1][1][tx];
        s2 = red[2][0][tx] + red[2][1][tx];
        s3 = red[3][0][tx] + red[3][1][tx];
        float* up = u + (size_t)bc * EE * WW + w;
        float r;
        r = fmaxf(s0, 0.f); up[0]      = r * r;
        r = fmaxf(s1, 0.f); up[WW]     = r * r;
        r = fmaxf(s2, 0.f); up[2 * WW] = r * r;
        r = fmaxf(s3, 0.f); up[3 * WW] = r * r;
    }
}

__global__ void ffn2_out_kernel(const float* __restrict__ u, const float* __restrict__ w4,
                                const float* __restrict__ h, float* __restrict__ out) {
    int w = blockIdx.x * 128 + threadIdx.x;
    int f = blockIdx.y;
    int bc = blockIdx.z;
    int c = bc & 7;
    int b = bc >> 3;
    const float* up = u + (size_t)bc * EE * WW + w;
    const float* wp = w4 + ((size_t)c * FF + f) * EE;
    float s = wp[0] * up[0] + wp[1] * up[WW] + wp[2] * up[2 * WW] + wp[3] * up[3 * WW];
    out[(((size_t)b * 2 * CC + CC + c) * FF + f) * WW + w] =
        h[((size_t)bc * FF + f) * WW + w] + s;
}

// ================================================================================
extern "C" void kernel_launch(void* const* d_in, const int* in_sizes, int n_in,
                              void* d_out, int out_size) {
    const float* x    = (const float*)d_in[0];
    const float* skip = (const float*)d_in[1];
    const float* Wq   = (const float*)d_in[2];
    const float* Kq   = (const float*)d_in[3];
    const float* bq   = (const float*)d_in[4];
    const float* Wk   = (const float*)d_in[5];
    const float* Kk   = (const float*)d_in[6];
    const float* bk   = (const float*)d_in[7];
    const float* Wv   = (const float*)d_in[8];
    const float* Kv   = (const float*)d_in[9];
    const float* bv   = (const float*)d_in[10];
    const float* Wo   = (const float*)d_in[11];
    const float* ng   = (const float*)d_in[12];
    const float* nb   = (const float*)d_in[13];
    const float* c1aw = (const float*)d_in[14];
    const float* c1ab = (const float*)d_in[15];
    const float* c1bw = (const float*)d_in[16];
    const float* c1bb = (const float*)d_in[17];
    const float* c2w  = (const float*)d_in[18];
    const float* c2b  = (const float*)d_in[19];
    const float* w3   = (const float*)d_in[20];
    const float* w4   = (const float*)d_in[21];
    float* out = (float*)d_out;

    float *ph, *pz, *pq, *pk, *pv, *ptq, *ptk, *ptv, *pu;
    cudaGetSymbolAddress((void**)&ph, g_h);
    cudaGetSymbolAddress((void**)&pz, g_z);
    cudaGetSymbolAddress((void**)&pq, g_q);
    cudaGetSymbolAddress((void**)&pk, g_k);
    cudaGetSymbolAddress((void**)&pv, g_v);
    cudaGetSymbolAddress((void**)&ptq, g_t);
    cudaGetSymbolAddress((void**)&ptk, g_t2);
    cudaGetSymbolAddress((void**)&ptv, g_t3);
    cudaGetSymbolAddress((void**)&pu, g_u);

    const dim3 gemm_grid(4, 2, BC);
    const dim3 gemm3_grid(4, 2, 3 * BC);
    const dim3 conv3_grid(4, FF / 2, 3 * BB);
    const dim3 ln_grid(8, BC);
    const dim3 ln_block(64, 8);
    const dim3 elw_grid(4, FF, BC);
    const dim3 attn_grid(4, BC * HH);

    const size_t KFF = (size_t)CC * CC * 3;

    auto attn_block = [&](int i, const float* qsrc, const float* msrc) {
        gemm_qkv<<<gemm3_grid, 512>>>(i, qsrc, msrc, ptq, ptk, ptv);
        convrope3_kernel<<<conv3_grid, 128>>>(ptq, ptk, ptv,
                                              Kq + (size_t)i * KFF, Kk + (size_t)i * KFF, Kv + (size_t)i * KFF,
                                              bq + i * CC, bk + i * CC, bv + i * CC,
                                              pq, pk, pv);
        attn_mma_kernel<<<attn_grid, 256>>>(pq, pk, pv, ptq);
        gemm_one<<<gemm_grid, 512>>>(i, ptq, ph);
    };

    // weight pre-conversion (runs each replay; ~3 us)
    wprep_kernel<<<4096, 512>>>(Wq, Wk, Wv, Wo);

    // h = x; out-x-half = x
    copy2_kernel<<<2048, 512>>>(ph, x, out);

    // z = LN0(h); h += attn0(z,z); h += attn1(z, skip)
    ln_kernel<<<ln_grid, ln_block>>>(ph, ng + 0 * CC * FF, nb + 0 * CC * FF, pz);
    attn_block(0, pz, pz);
    attn_block(1, pz, skip);

    // conv block
    ln_kernel<<<ln_grid, ln_block>>>(ph, ng + 1 * CC * FF, nb + 1 * CC * FF, pz);
    dwfused_kernel<<<elw_grid, 128>>>(pz, c1aw, c1ab, c1bw, c1bb, pq);
    ln_kernel<<<ln_grid, ln_block>>>(pq, ng + 2 * CC * FF, nb + 2 * CC * FF, pz);
    dwc2_acc_kernel<<<elw_grid, 128>>>(pz, c2w, c2b, ph);

    // attn2 (self) and attn3 (skip)
    ln_kernel<<<ln_grid, ln_block>>>(ph, ng + 3 * CC * FF, nb + 3 * CC * FF, pz);
    attn_block(2, pz, pz);
    ln_kernel<<<ln_grid, ln_block>>>(ph, ng + 4 * CC * FF, nb + 4 * CC * FF, pz);
    attn_block(3, pz, skip);

    // FFN (+ fused concat)
    ln_kernel<<<ln_grid, ln_block>>>(ph, ng + 5 * CC * FF, nb + 5 * CC * FF, pz);
    ffn1_kernel<<<dim3(4, BC), dim3(128, 2)>>>(pz, w3, pu);
    ffn2_out_kernel<<<elw_grid, 128>>>(pu, w4, ph, out);
    (void)in_sizes; (void)n_in; (void)out_size;
}